// round 8
// baseline (speedup 1.0000x reference)
#include <cuda_runtime.h>
#include <cuda_bf16.h>
#include <math.h>
#include <stdint.h>

#define BB 4
#define TT 2048
#define DD 1024
#define HH 8
#define DHH 128
#define TEE 2048
#define MM (BB*TT)          // 8192 rows
#define NCHUNK 16

__device__ __forceinline__ uint32_t smem_to_u32(const void* p) {
    uint32_t a;
    asm("{ .reg .u64 t; cvta.to.shared.u64 t, %1; cvt.u32.u64 %0, t; }" : "=r"(a) : "l"(p));
    return a;
}

#define LDSM4(R, addr) \
    asm volatile("ldmatrix.sync.aligned.m8n8.x4.shared.b16 {%0,%1,%2,%3}, [%4];" \
        : "=r"((R)[0]), "=r"((R)[1]), "=r"((R)[2]), "=r"((R)[3]) : "r"(addr))

#define MMA_BF16(c, a, b0, b1) \
    asm volatile("mma.sync.aligned.m16n8k16.row.col.f32.bf16.bf16.f32 " \
        "{%0,%1,%2,%3}, {%4,%5,%6,%7}, {%8,%9}, {%0,%1,%2,%3};" \
        : "+f"((c)[0]), "+f"((c)[1]), "+f"((c)[2]), "+f"((c)[3]) \
        : "r"((a)[0]), "r"((a)[1]), "r"((a)[2]), "r"((a)[3]), "r"(b0), "r"(b1))

#define CP16(dst, src) \
    asm volatile("cp.async.cg.shared.global [%0], [%1], 16;" :: "r"(dst), "l"(src))
#define CP_COMMIT() asm volatile("cp.async.commit_group;")
#define CP_WAIT1()  asm volatile("cp.async.wait_group 1;")

// ======================= device scratch =======================
__device__ __nv_bfloat16 g_xnhi[MM*DD];
__device__ __nv_bfloat16 g_xnlo[MM*DD];
__device__ __nv_bfloat16 g_acthi[MM*DD];
__device__ __nv_bfloat16 g_actlo[MM*DD];
__device__ __nv_bfloat16 g_wthi[4][DD*DD];
__device__ __nv_bfloat16 g_wtlo[4][DD*DD];
__device__ float g_k [MM*DD];
__device__ float g_v [MM*DD];
__device__ float g_y [MM*DD];
__device__ __nv_bfloat16 g_qhi[MM*DD];
__device__ __nv_bfloat16 g_qlo[MM*DD];
__device__ __nv_bfloat16 g_kThi[MM*DD];
__device__ __nv_bfloat16 g_kTlo[MM*DD];
__device__ __nv_bfloat16 g_vThi[MM*DD];
__device__ __nv_bfloat16 g_vTlo[MM*DD];
__device__ float g_att_part[NCHUNK*BB*HH*DHH*DHH];
__device__ __nv_bfloat16 g_attThi[BB*HH*DHH*DHH];
__device__ __nv_bfloat16 g_attTlo[BB*HH*DHH*DHH];
__device__ float g_emb_act[BB*TEE];
__device__ float g_embout[BB*2*DD];

__device__ __forceinline__ void split_store4(__nv_bfloat16* ph, __nv_bfloat16* pl, float4 v) {
    __nv_bfloat162 h0 = __floats2bfloat162_rn(v.x, v.y);
    __nv_bfloat162 h1 = __floats2bfloat162_rn(v.z, v.w);
    float rx = v.x - __bfloat162float(h0.x);
    float ry = v.y - __bfloat162float(h0.y);
    float rz = v.z - __bfloat162float(h1.x);
    float rw = v.w - __bfloat162float(h1.y);
    __nv_bfloat162 l0 = __floats2bfloat162_rn(rx, ry);
    __nv_bfloat162 l1 = __floats2bfloat162_rn(rz, rw);
    uint2 uh; uh.x = *(uint32_t*)&h0; uh.y = *(uint32_t*)&h1;
    uint2 ul; ul.x = *(uint32_t*)&l0; ul.y = *(uint32_t*)&l1;
    *(uint2*)ph = uh;
    *(uint2*)pl = ul;
}

// ======================= LayerNorm -> bf16 hi/lo =======================
__global__ __launch_bounds__(256) void ln_kernel(const float* __restrict__ x,
                                                 const float* __restrict__ w,
                                                 const float* __restrict__ b,
                                                 __nv_bfloat16* __restrict__ outh,
                                                 __nv_bfloat16* __restrict__ outl)
{
    int row = blockIdx.x;
    int tid = threadIdx.x;
    const float4* xr = (const float4*)(x + (size_t)row*DD);
    float4 v = xr[tid];
    float s  = v.x+v.y+v.z+v.w;
    float ss = v.x*v.x+v.y*v.y+v.z*v.z+v.w*v.w;
    #pragma unroll
    for (int o=16;o>0;o>>=1){ s += __shfl_down_sync(0xffffffffu,s,o); ss += __shfl_down_sync(0xffffffffu,ss,o); }
    __shared__ float sm[8], sm2[8];
    int wid = tid>>5, lane = tid&31;
    if (lane==0){ sm[wid]=s; sm2[wid]=ss; }
    __syncthreads();
    if (tid==0){
        float a=0.f, c=0.f;
        #pragma unroll
        for (int i=0;i<8;i++){ a+=sm[i]; c+=sm2[i]; }
        float mean = a*(1.0f/DD);
        float var  = c*(1.0f/DD) - mean*mean;
        sm[0]=mean; sm2[0]=rsqrtf(var+1e-5f);
    }
    __syncthreads();
    float mean=sm[0], rinv=sm2[0];
    float4 wv=((const float4*)w)[tid];
    float4 bv=((const float4*)b)[tid];
    float4 o;
    o.x=(v.x-mean)*rinv*wv.x+bv.x;
    o.y=(v.y-mean)*rinv*wv.y+bv.y;
    o.z=(v.z-mean)*rinv*wv.z+bv.z;
    o.w=(v.w-mean)*rinv*wv.w+bv.w;
    split_store4(outh + (size_t)row*DD + tid*4, outl + (size_t)row*DD + tid*4, o);
}

// ======================= weight transpose + bf16 split (4 weights) ==========
__global__ __launch_bounds__(1024) void wsplit4_k(const float* __restrict__ W0,
                                                  const float* __restrict__ W1,
                                                  const float* __restrict__ W2,
                                                  const float* __restrict__ W3,
                                                  __nv_bfloat16* __restrict__ Thi,
                                                  __nv_bfloat16* __restrict__ Tlo)
{
    __shared__ float t[32][33];
    int tx = threadIdx.x, ty = threadIdx.y;
    int wsel = blockIdx.z;
    const float* W = (wsel==0)?W0:(wsel==1)?W1:(wsel==2)?W2:W3;
    t[ty][tx] = W[(size_t)(blockIdx.y*32+ty)*DD + blockIdx.x*32+tx];
    __syncthreads();
    int n = blockIdx.x*32 + ty;
    int k = blockIdx.y*32 + tx;
    float v = t[tx][ty];
    __nv_bfloat16 h = __float2bfloat16(v);
    size_t base = (size_t)wsel*DD*DD;
    Thi[base + (size_t)n*DD + k] = h;
    Tlo[base + (size_t)n*DD + k] = __float2bfloat16(v - __bfloat162float(h));
}

// ======================= HMMA GEMM, BM=128 BN=128, 64x32 warp tiles =========
// mode 0: softmax-over-dh epilogue -> Qh/Ql (bf16 hi/lo)
// mode 1: +bias+(1-mask)*-1e6 -> C
// mode 2: (+bias)*mask -> C
// mode 3: +bias+resid -> C
#define LDSE    40                        // smem row stride (elements)
#define T_B     (128*LDSE*2)              // 10240 bytes per tile (128 rows)
#define STAGE_B (4*T_B)                   // 40960 bytes per stage
#define HG_SMEM (3*STAGE_B)               // 122880 bytes

__global__ __launch_bounds__(256, 1) void hgemm_k(
        const __nv_bfloat16* __restrict__ Ahi, const __nv_bfloat16* __restrict__ Alo,
        const __nv_bfloat16* __restrict__ Bhi, const __nv_bfloat16* __restrict__ Blo,
        const float* __restrict__ bias, const float* __restrict__ mask,
        const float* __restrict__ resid, float* __restrict__ C,
        __nv_bfloat16* __restrict__ Qh, __nv_bfloat16* __restrict__ Ql, int mode)
{
    extern __shared__ __nv_bfloat16 smbuf[];
    const int tid  = threadIdx.x;
    const int lane = tid & 31;
    const int w    = tid >> 5;      // 0..7
    const int wm   = w >> 2;        // 0..1 : 64 rows each
    const int wn   = w & 3;         // 0..3 : 32 cols each
    const int m0 = blockIdx.y * 128;
    const int n0 = blockIdx.x * 128;

    const uint32_t smb = smem_to_u32(smbuf);
    // loaders: 4 tiles x 128 rows x 4 16B-chunks = 2048 CP16 / 256 thr = 8 each
    const int lr = tid >> 2;            // 0..63
    const int lc = (tid & 3) * 8;
    const __nv_bfloat16* gA0a = Ahi + (size_t)(m0+lr)*DD + lc;
    const __nv_bfloat16* gA0b = Ahi + (size_t)(m0+64+lr)*DD + lc;
    const __nv_bfloat16* gA1a = Alo + (size_t)(m0+lr)*DD + lc;
    const __nv_bfloat16* gA1b = Alo + (size_t)(m0+64+lr)*DD + lc;
    const __nv_bfloat16* gB0a = Bhi + (size_t)(n0+lr)*DD + lc;
    const __nv_bfloat16* gB0b = Bhi + (size_t)(n0+64+lr)*DD + lc;
    const __nv_bfloat16* gB1a = Blo + (size_t)(n0+lr)*DD + lc;
    const __nv_bfloat16* gB1b = Blo + (size_t)(n0+64+lr)*DD + lc;
    const uint32_t dTa = smb + (lr*LDSE + lc)*2;
    const uint32_t dTb = smb + ((64+lr)*LDSE + lc)*2;

    const int arow  = wm*64 + (lane & 7) + ((lane >> 3) & 1) * 8;   // + mt*16
    const int akoff = ((lane >> 4) & 1) * 8;
    const int brow  = wn*32 + (lane & 7) + ((lane >> 4) & 1) * 8;
    const int bkoff = ((lane >> 3) & 1) * 8;

    float acc[4][4][4];
    #pragma unroll
    for (int i=0;i<4;i++)
        #pragma unroll
        for (int j=0;j<4;j++)
            #pragma unroll
            for (int l=0;l<4;l++) acc[i][j][l]=0.f;

    // prologue: stages 0,1
    #pragma unroll
    for (int s = 0; s < 2; s++) {
        int k0 = s*32;
        uint32_t so = s*STAGE_B;
        CP16(dTa + so + 0*T_B, gA0a + k0);
        CP16(dTb + so + 0*T_B, gA0b + k0);
        CP16(dTa + so + 1*T_B, gA1a + k0);
        CP16(dTb + so + 1*T_B, gA1b + k0);
        CP16(dTa + so + 2*T_B, gB0a + k0);
        CP16(dTb + so + 2*T_B, gB0b + k0);
        CP16(dTa + so + 3*T_B, gB1a + k0);
        CP16(dTb + so + 3*T_B, gB1b + k0);
        CP_COMMIT();
    }

    int st_r = 0, st_w = 2;
    for (int kc = 0; kc < 32; kc++) {
        CP_WAIT1();
        __syncthreads();
        if (kc + 2 < 32) {
            int k0 = (kc+2)*32;
            uint32_t so = st_w*STAGE_B;
            CP16(dTa + so + 0*T_B, gA0a + k0);
            CP16(dTb + so + 0*T_B, gA0b + k0);
            CP16(dTa + so + 1*T_B, gA1a + k0);
            CP16(dTb + so + 1*T_B, gA1b + k0);
            CP16(dTa + so + 2*T_B, gB0a + k0);
            CP16(dTb + so + 2*T_B, gB0b + k0);
            CP16(dTa + so + 3*T_B, gB1a + k0);
            CP16(dTb + so + 3*T_B, gB1b + k0);
        }
        CP_COMMIT();

        uint32_t base = smb + st_r*STAGE_B;
        #pragma unroll
        for (int ks = 0; ks < 2; ks++) {
            uint32_t ah[4][4], al[4][4];
            #pragma unroll
            for (int mt = 0; mt < 4; mt++) {
                uint32_t ra = base + ((arow + mt*16)*LDSE + ks*16 + akoff) * 2;
                LDSM4(ah[mt], ra);
                LDSM4(al[mt], ra + T_B);
            }
            uint32_t bh[2][4], bl[2][4];
            #pragma unroll
            for (int nb = 0; nb < 2; nb++) {
                uint32_t rb = base + 2*T_B + ((brow + nb*16)*LDSE + ks*16 + bkoff) * 2;
                LDSM4(bh[nb], rb);
                LDSM4(bl[nb], rb + T_B);
            }
            #pragma unroll
            for (int mt = 0; mt < 4; mt++)
                #pragma unroll
                for (int nt = 0; nt < 4; nt++) {
                    int nb = nt >> 1, sub = (nt & 1) * 2;
                    MMA_BF16(acc[mt][nt], ah[mt], bh[nb][sub], bh[nb][sub+1]);
                }
            #pragma unroll
            for (int mt = 0; mt < 4; mt++)
                #pragma unroll
                for (int nt = 0; nt < 4; nt++) {
                    int nb = nt >> 1, sub = (nt & 1) * 2;
                    MMA_BF16(acc[mt][nt], ah[mt], bl[nb][sub], bl[nb][sub+1]);
                }
            #pragma unroll
            for (int mt = 0; mt < 4; mt++)
                #pragma unroll
                for (int nt = 0; nt < 4; nt++) {
                    int nb = nt >> 1, sub = (nt & 1) * 2;
                    MMA_BF16(acc[mt][nt], al[mt], bh[nb][sub], bh[nb][sub+1]);
                }
        }
        if (++st_r == 3) st_r = 0;
        if (++st_w == 3) st_w = 0;
    }

    const int t4 = lane >> 2;
    const int t2 = (lane & 3) * 2;

    #pragma unroll
    for (int mt = 0; mt < 4; mt++)
        #pragma unroll
        for (int nt = 0; nt < 4; nt++) {
            int col = n0 + wn*32 + nt*8 + t2;
            float2 bi = *(const float2*)(bias + col);
            acc[mt][nt][0] += bi.x; acc[mt][nt][1] += bi.y;
            acc[mt][nt][2] += bi.x; acc[mt][nt][3] += bi.y;
        }

    if (mode == 0) {
        // fused softmax over 128 cols (one head), 128 rows in this block
        __syncthreads();
        float* red  = (float*)smbuf;    // [128][4]
        float* red2 = red + 512;
        float mrow[4][2];
        #pragma unroll
        for (int mt = 0; mt < 4; mt++) {
            float a0 = -1e30f, a1 = -1e30f;
            #pragma unroll
            for (int nt = 0; nt < 4; nt++) {
                a0 = fmaxf(a0, fmaxf(acc[mt][nt][0], acc[mt][nt][1]));
                a1 = fmaxf(a1, fmaxf(acc[mt][nt][2], acc[mt][nt][3]));
            }
            a0 = fmaxf(a0, __shfl_xor_sync(0xffffffffu, a0, 1));
            a0 = fmaxf(a0, __shfl_xor_sync(0xffffffffu, a0, 2));
            a1 = fmaxf(a1, __shfl_xor_sync(0xffffffffu, a1, 1));
            a1 = fmaxf(a1, __shfl_xor_sync(0xffffffffu, a1, 2));
            if ((lane & 3) == 0) {
                int r = wm*64 + mt*16 + t4;
                red[r*4 + wn] = a0;
                red[(r+8)*4 + wn] = a1;
            }
        }
        __syncthreads();
        #pragma unroll
        for (int mt = 0; mt < 4; mt++) {
            int r = wm*64 + mt*16 + t4;
            mrow[mt][0] = fmaxf(fmaxf(red[r*4+0], red[r*4+1]), fmaxf(red[r*4+2], red[r*4+3]));
            mrow[mt][1] = fmaxf(fmaxf(red[(r+8)*4+0], red[(r+8)*4+1]), fmaxf(red[(r+8)*4+2], red[(r+8)*4+3]));
        }
        float srow[4][2];
        #pragma unroll
        for (int mt = 0; mt < 4; mt++) {
            float s0 = 0.f, s1 = 0.f;
            #pragma unroll
            for (int nt = 0; nt < 4; nt++) {
                acc[mt][nt][0] = expf(acc[mt][nt][0] - mrow[mt][0]);
                acc[mt][nt][1] = expf(acc[mt][nt][1] - mrow[mt][0]);
                acc[mt][nt][2] = expf(acc[mt][nt][2] - mrow[mt][1]);
                acc[mt][nt][3] = expf(acc[mt][nt][3] - mrow[mt][1]);
                s0 += acc[mt][nt][0] + acc[mt][nt][1];
                s1 += acc[mt][nt][2] + acc[mt][nt][3];
            }
            s0 += __shfl_xor_sync(0xffffffffu, s0, 1);
            s0 += __shfl_xor_sync(0xffffffffu, s0, 2);
            s1 += __shfl_xor_sync(0xffffffffu, s1, 1);
            s1 += __shfl_xor_sync(0xffffffffu, s1, 2);
            if ((lane & 3) == 0) {
                int r = wm*64 + mt*16 + t4;
                red2[r*4 + wn] = s0;
                red2[(r+8)*4 + wn] = s1;
            }
        }
        __syncthreads();
        #pragma unroll
        for (int mt = 0; mt < 4; mt++) {
            int r = wm*64 + mt*16 + t4;
            srow[mt][0] = 1.0f / (red2[r*4+0] + red2[r*4+1] + red2[r*4+2] + red2[r*4+3]);
            srow[mt][1] = 1.0f / (red2[(r+8)*4+0] + red2[(r+8)*4+1] + red2[(r+8)*4+2] + red2[(r+8)*4+3]);
        }
        #pragma unroll
        for (int mt = 0; mt < 4; mt++) {
            int row0 = m0 + wm*64 + mt*16 + t4;
            int row1 = row0 + 8;
            #pragma unroll
            for (int nt = 0; nt < 4; nt++) {
                int col = n0 + wn*32 + nt*8 + t2;
                float v0 = acc[mt][nt][0] * srow[mt][0];
                float v1 = acc[mt][nt][1] * srow[mt][0];
                float v2 = acc[mt][nt][2] * srow[mt][1];
                float v3 = acc[mt][nt][3] * srow[mt][1];
                __nv_bfloat162 h0 = __floats2bfloat162_rn(v0, v1);
                __nv_bfloat162 h1 = __floats2bfloat162_rn(v2, v3);
                __nv_bfloat162 l0 = __floats2bfloat162_rn(v0 - __bfloat162float(h0.x), v1 - __bfloat162float(h0.y));
                __nv_bfloat162 l1 = __floats2bfloat162_rn(v2 - __bfloat162float(h1.x), v3 - __bfloat162float(h1.y));
                *(uint32_t*)(Qh + (size_t)row0*DD + col) = *(uint32_t*)&h0;
                *(uint32_t*)(Qh + (size_t)row1*DD + col) = *(uint32_t*)&h1;
                *(uint32_t*)(Ql + (size_t)row0*DD + col) = *(uint32_t*)&l0;
                *(uint32_t*)(Ql + (size_t)row1*DD + col) = *(uint32_t*)&l1;
            }
        }
        return;
    }

    #pragma unroll
    for (int mt = 0; mt < 4; mt++) {
        int row0 = m0 + wm*64 + mt*16 + t4;
        int row1 = row0 + 8;
        float m0v = 0.f, m1v = 0.f;
        if (mode == 1 || mode == 2) { m0v = mask[row0]; m1v = mask[row1]; }
        float add0 = (mode==1) ? (1.0f-m0v)*(-1000000.0f) : 0.f;
        float add1 = (mode==1) ? (1.0f-m1v)*(-1000000.0f) : 0.f;
        float mul0 = (mode==2) ? m0v : 1.f;
        float mul1 = (mode==2) ? m1v : 1.f;
        #pragma unroll
        for (int nt = 0; nt < 4; nt++) {
            int col = n0 + wn*32 + nt*8 + t2;
            float a0 = acc[mt][nt][0];
            float a1 = acc[mt][nt][1];
            float a2 = acc[mt][nt][2];
            float a3 = acc[mt][nt][3];
            if (mode == 1) { a0 += add0; a1 += add0; a2 += add1; a3 += add1; }
            else if (mode == 2) { a0 *= mul0; a1 *= mul0; a2 *= mul1; a3 *= mul1; }
            else if (mode == 3) {
                float2 r0 = *(const float2*)(resid + (size_t)row0*DD + col);
                float2 r1 = *(const float2*)(resid + (size_t)row1*DD + col);
                a0 += r0.x; a1 += r0.y; a2 += r1.x; a3 += r1.y;
            }
            *(float2*)(C + (size_t)row0*DD + col) = make_float2(a0, a1);
            *(float2*)(C + (size_t)row1*DD + col) = make_float2(a2, a3);
        }
    }
}

// ======================= softmax over time -> transposed bf16 hi/lo =========
__global__ void ksoftmaxT_k(const float* __restrict__ k,
                            __nv_bfloat16* __restrict__ kTh,
                            __nv_bfloat16* __restrict__ kTl)
{
    int b = blockIdx.x >> 5;
    int g = blockIdx.x & 31;
    int tx = threadIdx.x, ty = threadIdx.y;
    int d = g*32 + tx;
    float m = -INFINITY, s = 0.f;
    for (int t=ty; t<TT; t+=8){
        float val = k[((size_t)b*TT + t)*DD + d];
        float nm = fmaxf(m, val);
        s = s*expf(m-nm) + expf(val-nm);
        m = nm;
    }
    __shared__ float smax[8][32], ssum[8][32];
    smax[ty][tx]=m; ssum[ty][tx]=s;
    __syncthreads();
    if (ty==0){
        float M=smax[0][tx], S=ssum[0][tx];
        #pragma unroll
        for (int i=1;i<8;i++){
            float m2=smax[i][tx], s2=ssum[i][tx];
            float nm=fmaxf(M,m2);
            S = S*expf(M-nm) + s2*expf(m2-nm);
            M = nm;
        }
        smax[0][tx]=M; ssum[0][tx]=1.0f/S;
    }
    __syncthreads();
    float M=smax[0][tx], R=ssum[0][tx];
    __syncthreads();

    __shared__ __nv_bfloat16 sh[32][33], sl[32][33];
    int dg0 = g*32;
    int h = dg0 >> 7;
    int dl0 = dg0 & 127;
    size_t kbase = ((size_t)(b*HH + h))*DHH + dl0;

    for (int t0 = 0; t0 < TT; t0 += 32) {
        #pragma unroll
        for (int i = 0; i < 4; i++) {
            int t = t0 + ty + i*8;
            float val = expf(k[((size_t)b*TT + t)*DD + d] - M) * R;
            __nv_bfloat16 hv = __float2bfloat16(val);
            sh[tx][ty + i*8] = hv;
            sl[tx][ty + i*8] = __float2bfloat16(val - __bfloat162float(hv));
        }
        __syncthreads();
        #pragma unroll
        for (int i = 0; i < 4; i++) {
            int row = ty + i*8;
            kTh[(kbase + row)*TT + t0 + tx] = sh[row][tx];
            kTl[(kbase + row)*TT + t0 + tx] = sl[row][tx];
        }
        __syncthreads();
    }
}

// ======================= v transpose + split =======================
__global__ __launch_bounds__(1024) void vsplitT_k(const float* __restrict__ v,
                                                  __nv_bfloat16* __restrict__ vTh,
                                                  __nv_bfloat16* __restrict__ vTl)
{
    __shared__ float t[32][33];
    int tx = threadIdx.x, ty = threadIdx.y;
    int bh = blockIdx.z;
    int b = bh >> 3, h = bh & 7;
    int t0 = blockIdx.x * 32;
    int l0 = blockIdx.y * 32;
    t[ty][tx] = v[((size_t)(b*TT) + t0 + ty)*DD + h*DHH + l0 + tx];
    __syncthreads();
    float val = t[tx][ty];
    __nv_bfloat16 hv = __float2bfloat16(val);
    size_t idx = ((size_t)bh*DHH + l0 + ty)*TT + t0 + tx;
    vTh[idx] = hv;
    vTl[idx] = __float2bfloat16(val - __bfloat162float(hv));
}

// ======================= attention core HMMA ================================
#define LD2    136
#define ATE    (128*LD2)
#define ATT_SMEM (4*ATE*2)

__global__ __launch_bounds__(512, 1) void att1_k(
        const __nv_bfloat16* __restrict__ vTh, const __nv_bfloat16* __restrict__ vTl,
        const __nv_bfloat16* __restrict__ kTh, const __nv_bfloat16* __restrict__ kTl,
        float* __restrict__ part)
{
    extern __shared__ __nv_bfloat16 smbuf[];
    const int tid  = threadIdx.x;
    const int lane = tid & 31;
    const int w    = tid >> 5;
    const int wm   = w >> 2;
    const int wn   = w & 3;
    const int chunk = blockIdx.x;
    const int bh    = blockIdx.y;
    const int t0 = chunk * 128;

    #pragma unroll
    for (int i = 0; i < 4; i++) {
        int c = tid + i*512;
        int r = c >> 4;
        int c16 = (c & 15) * 8;
        size_t g = ((size_t)bh*DHH + r)*TT + t0 + c16;
        __nv_bfloat16* d = smbuf + r*LD2 + c16;
        *(uint4*)(d + 0*ATE) = *(const uint4*)(vTh + g);
        *(uint4*)(d + 1*ATE) = *(const uint4*)(vTl + g);
        *(uint4*)(d + 2*ATE) = *(const uint4*)(kTh + g);
        *(uint4*)(d + 3*ATE) = *(const uint4*)(kTl + g);
    }
    __syncthreads();

    const uint32_t smb = smem_to_u32(smbuf);
    const int arow  = wm*32 + (lane & 7) + ((lane >> 3) & 1) * 8;
    const int akoff = ((lane >> 4) & 1) * 8;
    const int brow  = wn*32 + (lane & 7) + ((lane >> 4) & 1) * 8;
    const int bkoff = ((lane >> 3) & 1) * 8;

    float acc[2][4][4];
    #pragma unroll
    for (int i=0;i<2;i++)
        #pragma unroll
        for (int j=0;j<4;j++)
            #pragma unroll
            for (int l=0;l<4;l++) acc[i][j][l]=0.f;

    #pragma unroll
    for (int ks = 0; ks < 8; ks++) {
        uint32_t ah[2][4], al[2][4];
        #pragma unroll
        for (int mt = 0; mt < 2; mt++) {
            uint32_t ra = smb + ((arow + mt*16)*LD2 + ks*16 + akoff) * 2;
            LDSM4(ah[mt], ra);
            LDSM4(al[mt], ra + ATE*2);
        }
        uint32_t bhf[2][4], blf[2][4];
        #pragma unroll
        for (int nb = 0; nb < 2; nb++) {
            uint32_t rb = smb + 2*ATE*2 + ((brow + nb*16)*LD2 + ks*16 + bkoff) * 2;
            LDSM4(bhf[nb], rb);
            LDSM4(blf[nb], rb + ATE*2);
        }
        #pragma unroll
        for (int mt = 0; mt < 2; mt++)
            #pragma unroll
            for (int nt = 0; nt < 4; nt++) {
                int nb = nt >> 1, sub = (nt & 1) * 2;
                MMA_BF16(acc[mt][nt], ah[mt], bhf[nb][sub], bhf[nb][sub+1]);
            }
        #pragma unroll
        for (int mt = 0; mt < 2; mt++)
            #pragma unroll
            for (int nt = 0; nt < 4; nt++) {
                int nb = nt >> 1, sub = (nt & 1) * 2;
                MMA_BF16(acc[mt][nt], ah[mt], blf[nb][sub], blf[nb][sub+1]);
            }
        #pragma unroll
        for (int mt = 0; mt < 2; mt++)
            #pragma unroll
            for (int nt = 0; nt < 4; nt++) {
                int nb = nt >> 1, sub = (nt & 1) * 2;
                MMA_BF16(acc[mt][nt], al[mt], bhf[nb][sub], bhf[nb][sub+1]);
            }
    }

    float* dst = part + ((size_t)(chunk*(BB*HH) + bh))*(DHH*DHH);
    const int t4 = lane >> 2;
    const int t2 = (lane & 3) * 2;
    #pragma unroll
    for (int mt = 0; mt < 2; mt++) {
        int row0 = wm*32 + mt*16 + t4;
        int row1 = row0 + 8;
        #pragma unroll
        for (int nt = 0; nt < 4; nt++) {
            int col = wn*32 + nt*8 + t2;
            *(float2*)(dst + row0*DHH + col) = make_float2(acc[mt][nt][0], acc[mt][nt][1]);
            *(float2*)(dst + row1*DHH + col) = make_float2(acc[mt][nt][2], acc[mt][nt][3]);
        }
    }
}

__global__ void att_reduce_k(const float* __restrict__ part,
                             __nv_bfloat16* __restrict__ ath,
                             __nv_bfloat16* __restrict__ atl)
{
    int i = blockIdx.x*256 + threadIdx.x;
    float s = 0.f;
    #pragma unroll
    for (int c=0;c<NCHUNK;c++) s += part[(size_t)c*(BB*HH*DHH*DHH) + i];
    __nv_bfloat16 h = __float2bfloat16(s);
    ath[i] = h;
    atl[i] = __float2bfloat16(s - __bfloat162float(h));
}

__global__ __launch_bounds__(512, 1) void att2_k(
        const __nv_bfloat16* __restrict__ qh, const __nv_bfloat16* __restrict__ ql,
        const __nv_bfloat16* __restrict__ ath, const __nv_bfloat16* __restrict__ atl,
        float* __restrict__ y)
{
    extern __shared__ __nv_bfloat16 smbuf[];
    const int tid  = threadIdx.x;
    const int lane = tid & 31;
    const int w    = tid >> 5;
    const int wm   = w >> 2;
    const int wn   = w & 3;
    const int m0 = blockIdx.x * 128;
    const int h  = blockIdx.y;
    const int bh = (m0 >> 11) * HH + h;

    #pragma unroll
    for (int i = 0; i < 4; i++) {
        int c = tid + i*512;
        int r = c >> 4;
        int c16 = (c & 15) * 8;
        size_t ga = (size_t)(m0 + r)*DD + h*DHH + c16;
        size_t gb = ((size_t)bh*DHH + r)*DHH + c16;
        __nv_bfloat16* d = smbuf + r*LD2 + c16;
        *(uint4*)(d + 0*ATE) = *(const uint4*)(qh + ga);
        *(uint4*)(d + 1*ATE) = *(const uint4*)(ql + ga);
        *(uint4*)(d + 2*ATE) = *(const uint4*)(ath + gb);
        *(uint4*)(d + 3*ATE) = *(const uint4*)(atl + gb);
    }
    __syncthreads();

    const uint32_t smb = smem_to_u32(smbuf);
    const int arow  = wm*32 + (lane & 7) + ((lane >> 3) & 1) * 8;
    const int akoff = ((lane >> 4) & 1) * 8;
    const int brow  = wn*32 + (lane & 7) + ((lane >> 4) & 1) * 8;
    const int bkoff = ((lane >> 3) & 1) * 8;

    float acc[2][4][4];
    #pragma unroll
    for (int i=0;i<2;i++)
        #pragma unroll
        for (int j=0;j<4;j++)
            #pragma unroll
            for (int l=0;l<4;l++) acc[i][j][l]=0.f;

    #pragma unroll
    for (int ks = 0; ks < 8; ks++) {
        uint32_t ah[2][4], al[2][4];
        #pragma unroll
        for (int mt = 0; mt < 2; mt++) {
            uint32_t ra = smb + ((arow + mt*16)*LD2 + ks*16 + akoff) * 2;
            LDSM4(ah[mt], ra);
            LDSM4(al[mt], ra + ATE*2);
        }
        uint32_t bhf[2][4], blf[2][4];
        #pragma unroll
        for (int nb = 0; nb < 2; nb++) {
            uint32_t rb = smb + 2*ATE*2 + ((brow + nb*16)*LD2 + ks*16 + bkoff) * 2;
            LDSM4(bhf[nb], rb);
            LDSM4(blf[nb], rb + ATE*2);
        }
        #pragma unroll
        for (int mt = 0; mt < 2; mt++)
            #pragma unroll
            for (int nt = 0; nt < 4; nt++) {
                int nb = nt >> 1, sub = (nt & 1) * 2;
                MMA_BF16(acc[mt][nt], ah[mt], bhf[nb][sub], bhf[nb][sub+1]);
            }
        #pragma unroll
        for (int mt = 0; mt < 2; mt++)
            #pragma unroll
            for (int nt = 0; nt < 4; nt++) {
                int nb = nt >> 1, sub = (nt & 1) * 2;
                MMA_BF16(acc[mt][nt], ah[mt], blf[nb][sub], blf[nb][sub+1]);
            }
        #pragma unroll
        for (int mt = 0; mt < 2; mt++)
            #pragma unroll
            for (int nt = 0; nt < 4; nt++) {
                int nb = nt >> 1, sub = (nt & 1) * 2;
                MMA_BF16(acc[mt][nt], al[mt], bhf[nb][sub], bhf[nb][sub+1]);
            }
    }

    const int t4 = lane >> 2;
    const int t2 = (lane & 3) * 2;
    #pragma unroll
    for (int mt = 0; mt < 2; mt++) {
        int row0 = m0 + wm*32 + mt*16 + t4;
        int row1 = row0 + 8;
        #pragma unroll
        for (int nt = 0; nt < 4; nt++) {
            int col = h*DHH + wn*32 + nt*8 + t2;
            *(float2*)(y + (size_t)row0*DD + col) = make_float2(acc[mt][nt][0], acc[mt][nt][1]);
            *(float2*)(y + (size_t)row1*DD + col) = make_float2(acc[mt][nt][2], acc[mt][nt][3]);
        }
    }
}

// ======================= emb path =======================
__global__ void silu_emb_k(const float* __restrict__ emb, float* __restrict__ out)
{
    int i = blockIdx.x*256 + threadIdx.x;
    float e = emb[i];
    out[i] = e / (1.0f + expf(-e));
}

__global__ __launch_bounds__(256) void emb_gemm_k(const float* __restrict__ ea,
                                                  const float* __restrict__ W,
                                                  const float* __restrict__ bias,
                                                  float* __restrict__ out)
{
    int n = blockIdx.x*256 + threadIdx.x;
    int b = blockIdx.y;
    const float* e = ea + b*TEE;
    float acc = 0.f;
    #pragma unroll 8
    for (int t=0;t<TEE;t++)
        acc = fmaf(e[t], W[(size_t)t*(2*DD) + n], acc);
    out[b*(2*DD) + n] = acc + bias[n];
}

// ======================= LN2 + FiLM + SiLU -> bf16 hi/lo =======================
__global__ __launch_bounds__(256) void film_k(const float* __restrict__ y,
                                              const float* __restrict__ w2,
                                              const float* __restrict__ b2,
                                              const float* __restrict__ embout,
                                              __nv_bfloat16* __restrict__ acth,
                                              __nv_bfloat16* __restrict__ actl)
{
    int row = blockIdx.x;
    int b = row / TT;
    int tid = threadIdx.x;
    const float4* yr = (const float4*)(y + (size_t)row*DD);
    float4 v = yr[tid];
    float s  = v.x+v.y+v.z+v.w;
    float ss = v.x*v.x+v.y*v.y+v.z*v.z+v.w*v.w;
    #pragma unroll
    for (int o=16;o>0;o>>=1){ s += __shfl_down_sync(0xffffffffu,s,o); ss += __shfl_down_sync(0xffffffffu,ss,o); }
    __shared__ float sm[8], sm2[8];
    int wid = tid>>5, lane = tid&31;
    if (lane==0){ sm[wid]=s; sm2[wid]=ss; }
    __syncthreads();
    if (tid==0){
        float a=0.f, c=0.f;
        #pragma unroll
        for (int i=0;i<8;i++){ a+=sm[i]; c+=sm2[i]; }
        float mean = a*(1.0f/DD);
        float var  = c*(1.0f/DD) - mean*mean;
        sm[0]=mean; sm2[0]=rsqrtf(var+1e-5f);
    }
    __syncthreads();
    float mean=sm[0], rinv=sm2[0];
    float4 wv=((const float4*)w2)[tid];
    float4 bv=((const float4*)b2)[tid];
    float4 sc=((const float4*)(embout + (size_t)b*(2*DD)))[tid];
    float4 sh=((const float4*)(embout + (size_t)b*(2*DD) + DD))[tid];
    float4 o;
    float h;
    h=(v.x-mean)*rinv*wv.x+bv.x; h=h*(1.0f+sc.x)+sh.x; o.x=h/(1.0f+expf(-h));
    h=(v.y-mean)*rinv*wv.y+bv.y; h=h*(1.0f+sc.y)+sh.y; o.y=h/(1.0f+expf(-h));
    h=(v.z-mean)*rinv*wv.z+bv.z; h=h*(1.0f+sc.z)+sh.z; o.z=h/(1.0f+expf(-h));
    h=(v.w-mean)*rinv*wv.w+bv.w; h=h*(1.0f+sc.w)+sh.w; o.w=h/(1.0f+expf(-h));
    split_store4(acth + (size_t)row*DD + tid*4, actl + (size_t)row*DD + tid*4, o);
}

// ======================= launch =======================
extern "C" void kernel_launch(void* const* d_in, const int* in_sizes, int n_in,
                              void* d_out, int out_size)
{
    (void)in_sizes; (void)n_in; (void)out_size;
    const float* x     = (const float*)d_in[0];
    const float* emb   = (const float*)d_in[1];
    const float* mask  = (const float*)d_in[2];
    const float* ln_w  = (const float*)d_in[4];
    const float* ln_b  = (const float*)d_in[5];
    const float* Wq    = (const float*)d_in[6];
    const float* bq    = (const float*)d_in[7];
    const float* Wk    = (const float*)d_in[8];
    const float* bk    = (const float*)d_in[9];
    const float* Wv    = (const float*)d_in[10];
    const float* bv    = (const float*)d_in[11];
    const float* W_emb = (const float*)d_in[12];
    const float* b_emb = (const float*)d_in[13];
    const float* ln2_w = (const float*)d_in[14];
    const float* ln2_b = (const float*)d_in[15];
    const float* W_out = (const float*)d_in[16];
    const float* b_out = (const float*)d_in[17];
    float* out = (float*)d_out;

    __nv_bfloat16 *p_xnh, *p_xnl, *p_acth, *p_actl, *p_wth, *p_wtl;
    __nv_bfloat16 *p_qh, *p_ql, *p_kTh, *p_kTl, *p_vTh, *p_vTl, *p_ath, *p_atl;
    float *p_k, *p_v, *p_y, *p_attp, *p_emba, *p_embout;
    cudaGetSymbolAddress((void**)&p_xnh,    g_xnhi);
    cudaGetSymbolAddress((void**)&p_xnl,    g_xnlo);
    cudaGetSymbolAddress((void**)&p_acth,   g_acthi);
    cudaGetSymbolAddress((void**)&p_actl,   g_actlo);
    cudaGetSymbolAddress((void**)&p_wth,    g_wthi);
    cudaGetSymbolAddress((void**)&p_wtl,    g_wtlo);
    cudaGetSymbolAddress((void**)&p_k,      g_k);
    cudaGetSymbolAddress((void**)&p_v,      g_v);
    cudaGetSymbolAddress((void**)&p_y,      g_y);
    cudaGetSymbolAddress((void**)&p_qh,     g_qhi);
    cudaGetSymbolAddress((void**)&p_ql,     g_qlo);
    cudaGetSymbolAddress((void**)&p_kTh,    g_kThi);
    cudaGetSymbolAddress((void**)&p_kTl,    g_kTlo);
    cudaGetSymbolAddress((void**)&p_vTh,    g_vThi);
    cudaGetSymbolAddress((void**)&p_vTl,    g_vTlo);
    cudaGetSymbolAddress((void**)&p_ath,    g_attThi);
    cudaGetSymbolAddress((void**)&p_atl,    g_attTlo);
    cudaGetSymbolAddress((void**)&p_attp,   g_att_part);
    cudaGetSymbolAddress((void**)&p_emba,   g_emb_act);
    cudaGetSymbolAddress((void**)&p_embout, g_embout);

    cudaFuncSetAttribute(hgemm_k, cudaFuncAttributeMaxDynamicSharedMemorySize, HG_SMEM);
    cudaFuncSetAttribute(att1_k,  cudaFuncAttributeMaxDynamicSharedMemorySize, ATT_SMEM);
    cudaFuncSetAttribute(att2_k,  cudaFuncAttributeMaxDynamicSharedMemorySize, ATT_SMEM);

    wsplit4_k<<<dim3(32,32,4), dim3(32,32)>>>(Wq, Wk, Wv, W_out, p_wth, p_wtl);
    ln_kernel<<<MM, 256>>>(x, ln_w, ln_b, p_xnh, p_xnl);
    silu_emb_k<<<(BB*TEE)/256, 256>>>(emb, p_emba);

    dim3 ggrid(DD/128, MM/128);    // (8, 64) = 512 blocks, 256 threads
    hgemm_k<<<ggrid, 256, HG_SMEM>>>(p_xnh, p_xnl, p_wth + 0*(size_t)DD*DD, p_wtl + 0*(size_t)DD*DD,
                                     bq, nullptr, nullptr, nullptr, p_qh, p_ql, 0);
    hgemm_k<<<ggrid, 256, HG_SMEM>>>(p_xnh, p_xnl, p_wth + 1*(size_t)DD*DD, p_wtl + 1*(size_t)DD*DD,
                                     bk, mask, nullptr, p_k, nullptr, nullptr, 1);
    hgemm_k<<<ggrid, 256, HG_SMEM>>>(p_xnh, p_xnl, p_wth + 2*(size_t)DD*DD, p_wtl + 2*(size_t)DD*DD,
                                     bv, mask, nullptr, p_v, nullptr, nullptr, 2);

    ksoftmaxT_k<<<BB*32, dim3(32,8)>>>(p_k, p_kTh, p_kTl);
    vsplitT_k<<<dim3(TT/32, DHH/32, BB*HH), dim3(32,32)>>>(p_v, p_vTh, p_vTl);

    att1_k<<<dim3(NCHUNK, BB*HH), 512, ATT_SMEM>>>(p_vTh, p_vTl, p_kTh, p_kTl, p_attp);
    att_reduce_k<<<(BB*HH*DHH*DHH)/256, 256>>>(p_attp, p_ath, p_atl);

    emb_gemm_k<<<dim3((2*DD)/256, BB), 256>>>(p_emba, W_emb, b_emb, p_embout);

    att2_k<<<dim3(MM/128, HH), 512, ATT_SMEM>>>(p_qh, p_ql, p_ath, p_atl, p_y);

    film_k<<<MM, 256>>>(p_y, ln2_w, ln2_b, p_embout, p_acth, p_actl);

    hgemm_k<<<ggrid, 256, HG_SMEM>>>(p_acth, p_actl, p_wth + 3*(size_t)DD*DD, p_wtl + 3*(size_t)DD*DD,
                                     b_out, nullptr, x, out, nullptr, nullptr, 3);
}

// round 9
// speedup vs baseline: 1.0621x; 1.0621x over previous
#include <cuda_runtime.h>
#include <cuda_bf16.h>
#include <math.h>
#include <stdint.h>

#define BB 4
#define TT 2048
#define DD 1024
#define HH 8
#define DHH 128
#define TEE 2048
#define MM (BB*TT)          // 8192 rows
#define NCHUNK 16

__device__ __forceinline__ uint32_t smem_to_u32(const void* p) {
    uint32_t a;
    asm("{ .reg .u64 t; cvta.to.shared.u64 t, %1; cvt.u32.u64 %0, t; }" : "=r"(a) : "l"(p));
    return a;
}

#define LDSM4(R, addr) \
    asm volatile("ldmatrix.sync.aligned.m8n8.x4.shared.b16 {%0,%1,%2,%3}, [%4];" \
        : "=r"((R)[0]), "=r"((R)[1]), "=r"((R)[2]), "=r"((R)[3]) : "r"(addr))

#define MMA_BF16(c, a, b0, b1) \
    asm volatile("mma.sync.aligned.m16n8k16.row.col.f32.bf16.bf16.f32 " \
        "{%0,%1,%2,%3}, {%4,%5,%6,%7}, {%8,%9}, {%0,%1,%2,%3};" \
        : "+f"((c)[0]), "+f"((c)[1]), "+f"((c)[2]), "+f"((c)[3]) \
        : "r"((a)[0]), "r"((a)[1]), "r"((a)[2]), "r"((a)[3]), "r"(b0), "r"(b1))

#define CP16(dst, src) \
    asm volatile("cp.async.cg.shared.global [%0], [%1], 16;" :: "r"(dst), "l"(src))
#define CP_COMMIT() asm volatile("cp.async.commit_group;")
#define CP_WAIT1()  asm volatile("cp.async.wait_group 1;")
#define CP_WAIT0()  asm volatile("cp.async.wait_group 0;")

// ======================= device scratch =======================
__device__ __nv_bfloat16 g_xnhi[MM*DD];
__device__ __nv_bfloat16 g_xnlo[MM*DD];
__device__ __nv_bfloat16 g_acthi[MM*DD];
__device__ __nv_bfloat16 g_actlo[MM*DD];
__device__ __nv_bfloat16 g_wthi[4][DD*DD];
__device__ __nv_bfloat16 g_wtlo[4][DD*DD];
__device__ float g_k [MM*DD];
__device__ float g_v [MM*DD];
__device__ float g_y [MM*DD];
__device__ __nv_bfloat16 g_qhi[MM*DD];
__device__ __nv_bfloat16 g_qlo[MM*DD];
__device__ __nv_bfloat16 g_kThi[MM*DD];
__device__ __nv_bfloat16 g_kTlo[MM*DD];
__device__ __nv_bfloat16 g_vThi[MM*DD];
__device__ __nv_bfloat16 g_vTlo[MM*DD];
__device__ float g_att_part[NCHUNK*BB*HH*DHH*DHH];
__device__ __nv_bfloat16 g_attThi[BB*HH*DHH*DHH];
__device__ __nv_bfloat16 g_attTlo[BB*HH*DHH*DHH];
__device__ float g_emb_act[BB*TEE];
__device__ float g_embout[BB*2*DD];

__device__ __forceinline__ void split_store4(__nv_bfloat16* ph, __nv_bfloat16* pl, float4 v) {
    __nv_bfloat162 h0 = __floats2bfloat162_rn(v.x, v.y);
    __nv_bfloat162 h1 = __floats2bfloat162_rn(v.z, v.w);
    float rx = v.x - __bfloat162float(h0.x);
    float ry = v.y - __bfloat162float(h0.y);
    float rz = v.z - __bfloat162float(h1.x);
    float rw = v.w - __bfloat162float(h1.y);
    __nv_bfloat162 l0 = __floats2bfloat162_rn(rx, ry);
    __nv_bfloat162 l1 = __floats2bfloat162_rn(rz, rw);
    uint2 uh; uh.x = *(uint32_t*)&h0; uh.y = *(uint32_t*)&h1;
    uint2 ul; ul.x = *(uint32_t*)&l0; ul.y = *(uint32_t*)&l1;
    *(uint2*)ph = uh;
    *(uint2*)pl = ul;
}

// ======================= LayerNorm -> bf16 hi/lo =======================
__global__ __launch_bounds__(256) void ln_kernel(const float* __restrict__ x,
                                                 const float* __restrict__ w,
                                                 const float* __restrict__ b,
                                                 __nv_bfloat16* __restrict__ outh,
                                                 __nv_bfloat16* __restrict__ outl)
{
    int row = blockIdx.x;
    int tid = threadIdx.x;
    const float4* xr = (const float4*)(x + (size_t)row*DD);
    float4 v = xr[tid];
    float s  = v.x+v.y+v.z+v.w;
    float ss = v.x*v.x+v.y*v.y+v.z*v.z+v.w*v.w;
    #pragma unroll
    for (int o=16;o>0;o>>=1){ s += __shfl_down_sync(0xffffffffu,s,o); ss += __shfl_down_sync(0xffffffffu,ss,o); }
    __shared__ float sm[8], sm2[8];
    int wid = tid>>5, lane = tid&31;
    if (lane==0){ sm[wid]=s; sm2[wid]=ss; }
    __syncthreads();
    if (tid==0){
        float a=0.f, c=0.f;
        #pragma unroll
        for (int i=0;i<8;i++){ a+=sm[i]; c+=sm2[i]; }
        float mean = a*(1.0f/DD);
        float var  = c*(1.0f/DD) - mean*mean;
        sm[0]=mean; sm2[0]=rsqrtf(var+1e-5f);
    }
    __syncthreads();
    float mean=sm[0], rinv=sm2[0];
    float4 wv=((const float4*)w)[tid];
    float4 bv=((const float4*)b)[tid];
    float4 o;
    o.x=(v.x-mean)*rinv*wv.x+bv.x;
    o.y=(v.y-mean)*rinv*wv.y+bv.y;
    o.z=(v.z-mean)*rinv*wv.z+bv.z;
    o.w=(v.w-mean)*rinv*wv.w+bv.w;
    split_store4(outh + (size_t)row*DD + tid*4, outl + (size_t)row*DD + tid*4, o);
}

// ======================= weight transpose + bf16 split (4 weights) ==========
__global__ __launch_bounds__(1024) void wsplit4_k(const float* __restrict__ W0,
                                                  const float* __restrict__ W1,
                                                  const float* __restrict__ W2,
                                                  const float* __restrict__ W3,
                                                  __nv_bfloat16* __restrict__ Thi,
                                                  __nv_bfloat16* __restrict__ Tlo)
{
    __shared__ float t[32][33];
    int tx = threadIdx.x, ty = threadIdx.y;
    int wsel = blockIdx.z;
    const float* W = (wsel==0)?W0:(wsel==1)?W1:(wsel==2)?W2:W3;
    t[ty][tx] = W[(size_t)(blockIdx.y*32+ty)*DD + blockIdx.x*32+tx];
    __syncthreads();
    int n = blockIdx.x*32 + ty;
    int k = blockIdx.y*32 + tx;
    float v = t[tx][ty];
    __nv_bfloat16 h = __float2bfloat16(v);
    size_t base = (size_t)wsel*DD*DD;
    Thi[base + (size_t)n*DD + k] = h;
    Tlo[base + (size_t)n*DD + k] = __float2bfloat16(v - __bfloat162float(h));
}

// ======================= HMMA GEMM, BM=256 BN=128, 64x64 warp tiles =========
// mode 0: softmax-over-dh epilogue -> Qh/Ql (bf16 hi/lo)
// mode 1: +bias+(1-mask)*-1e6 -> C
// mode 2: (+bias)*mask -> C
// mode 3: +bias+resid -> C
#define LDSE    40                        // smem row stride (elements)
#define SUBA    (64*LDSE*2)               // 5120 B per 64-row subtile
#define TA_B    (4*SUBA)                  // 20480 B (A hi or lo, 256 rows)
#define TB_B    (2*SUBA)                  // 10240 B (B hi or lo, 128 rows)
#define STAGE_B (2*TA_B + 2*TB_B)         // 61440 B per stage
#define HG_SMEM (3*STAGE_B)               // 184320 B

__global__ __launch_bounds__(256, 1) void hgemm_k(
        const __nv_bfloat16* __restrict__ Ahi, const __nv_bfloat16* __restrict__ Alo,
        const __nv_bfloat16* __restrict__ Bhi, const __nv_bfloat16* __restrict__ Blo,
        const float* __restrict__ bias, const float* __restrict__ mask,
        const float* __restrict__ resid, float* __restrict__ C,
        __nv_bfloat16* __restrict__ Qh, __nv_bfloat16* __restrict__ Ql, int mode)
{
    extern __shared__ __nv_bfloat16 smbuf[];
    const int tid  = threadIdx.x;
    const int lane = tid & 31;
    const int w    = tid >> 5;      // 0..7
    const int wm   = w >> 1;        // 0..3 : 64 rows each
    const int wn   = w & 1;         // 0..1 : 64 cols each
    const int m0 = blockIdx.y * 256;
    const int n0 = blockIdx.x * 128;

    const uint32_t smb = smem_to_u32(smbuf);
    const int lr = tid >> 2;            // 0..63
    const int lc = (tid & 3) * 8;
    const __nv_bfloat16* gAh = Ahi + (size_t)(m0+lr)*DD + lc;
    const __nv_bfloat16* gAl = Alo + (size_t)(m0+lr)*DD + lc;
    const __nv_bfloat16* gBh = Bhi + (size_t)(n0+lr)*DD + lc;
    const __nv_bfloat16* gBl = Blo + (size_t)(n0+lr)*DD + lc;
    const uint32_t dst0 = smb + (lr*LDSE + lc)*2;

    const int arow  = wm*64 + (lane & 7) + ((lane >> 3) & 1) * 8;   // + mt*16
    const int akoff = ((lane >> 4) & 1) * 8;
    const int brow  = wn*64 + (lane & 7) + ((lane >> 4) & 1) * 8;   // + nb*16
    const int bkoff = ((lane >> 3) & 1) * 8;

    float acc[4][8][4];
    #pragma unroll
    for (int i=0;i<4;i++)
        #pragma unroll
        for (int j=0;j<8;j++)
            #pragma unroll
            for (int l=0;l<4;l++) acc[i][j][l]=0.f;

    // prologue: stages 0,1
    #pragma unroll
    for (int s = 0; s < 2; s++) {
        int k0 = s*32;
        uint32_t so = s*STAGE_B;
        #pragma unroll
        for (int i=0;i<4;i++){
            CP16(dst0 + so + i*SUBA,        gAh + (size_t)i*64*DD + k0);
            CP16(dst0 + so + TA_B + i*SUBA, gAl + (size_t)i*64*DD + k0);
        }
        #pragma unroll
        for (int i=0;i<2;i++){
            CP16(dst0 + so + 2*TA_B + i*SUBA,        gBh + (size_t)i*64*DD + k0);
            CP16(dst0 + so + 2*TA_B + TB_B + i*SUBA, gBl + (size_t)i*64*DD + k0);
        }
        CP_COMMIT();
    }

    int st_r = 0, st_w = 2;
    for (int kc = 0; kc < 32; kc++) {
        CP_WAIT1();
        __syncthreads();
        if (kc + 2 < 32) {
            int k0 = (kc+2)*32;
            uint32_t so = st_w*STAGE_B;
            #pragma unroll
            for (int i=0;i<4;i++){
                CP16(dst0 + so + i*SUBA,        gAh + (size_t)i*64*DD + k0);
                CP16(dst0 + so + TA_B + i*SUBA, gAl + (size_t)i*64*DD + k0);
            }
            #pragma unroll
            for (int i=0;i<2;i++){
                CP16(dst0 + so + 2*TA_B + i*SUBA,        gBh + (size_t)i*64*DD + k0);
                CP16(dst0 + so + 2*TA_B + TB_B + i*SUBA, gBl + (size_t)i*64*DD + k0);
            }
        }
        CP_COMMIT();

        uint32_t base = smb + st_r*STAGE_B;
        #pragma unroll
        for (int ks = 0; ks < 2; ks++) {
            uint32_t ah[4][4], al[4][4];
            #pragma unroll
            for (int mt = 0; mt < 4; mt++) {
                uint32_t ra = base + ((arow + mt*16)*LDSE + ks*16 + akoff) * 2;
                LDSM4(ah[mt], ra);
                LDSM4(al[mt], ra + TA_B);
            }
            uint32_t bh[4][4], bl[4][4];
            #pragma unroll
            for (int nb = 0; nb < 4; nb++) {
                uint32_t rb = base + 2*TA_B + ((brow + nb*16)*LDSE + ks*16 + bkoff) * 2;
                LDSM4(bh[nb], rb);
                LDSM4(bl[nb], rb + TB_B);
            }
            #pragma unroll
            for (int mt = 0; mt < 4; mt++)
                #pragma unroll
                for (int nt = 0; nt < 8; nt++) {
                    int nb = nt >> 1, sub = (nt & 1) * 2;
                    MMA_BF16(acc[mt][nt], ah[mt], bh[nb][sub], bh[nb][sub+1]);
                }
            #pragma unroll
            for (int mt = 0; mt < 4; mt++)
                #pragma unroll
                for (int nt = 0; nt < 8; nt++) {
                    int nb = nt >> 1, sub = (nt & 1) * 2;
                    MMA_BF16(acc[mt][nt], ah[mt], bl[nb][sub], bl[nb][sub+1]);
                }
            #pragma unroll
            for (int mt = 0; mt < 4; mt++)
                #pragma unroll
                for (int nt = 0; nt < 8; nt++) {
                    int nb = nt >> 1, sub = (nt & 1) * 2;
                    MMA_BF16(acc[mt][nt], al[mt], bh[nb][sub], bh[nb][sub+1]);
                }
        }
        if (++st_r == 3) st_r = 0;
        if (++st_w == 3) st_w = 0;
    }

    const int t4 = lane >> 2;
    const int t2 = (lane & 3) * 2;

    #pragma unroll
    for (int mt = 0; mt < 4; mt++)
        #pragma unroll
        for (int nt = 0; nt < 8; nt++) {
            int col = n0 + wn*64 + nt*8 + t2;
            float2 bi = *(const float2*)(bias + col);
            acc[mt][nt][0] += bi.x; acc[mt][nt][1] += bi.y;
            acc[mt][nt][2] += bi.x; acc[mt][nt][3] += bi.y;
        }

    if (mode == 0) {
        // fused softmax over 128 cols (one head), rows split 4 warps, cols 2 warps
        CP_WAIT0();
        __syncthreads();
        float* red  = (float*)smbuf;    // [256][2]
        float* red2 = red + 512;
        float mrow[4][2];
        #pragma unroll
        for (int mt = 0; mt < 4; mt++) {
            float a0 = -1e30f, a1 = -1e30f;
            #pragma unroll
            for (int nt = 0; nt < 8; nt++) {
                a0 = fmaxf(a0, fmaxf(acc[mt][nt][0], acc[mt][nt][1]));
                a1 = fmaxf(a1, fmaxf(acc[mt][nt][2], acc[mt][nt][3]));
            }
            a0 = fmaxf(a0, __shfl_xor_sync(0xffffffffu, a0, 1));
            a0 = fmaxf(a0, __shfl_xor_sync(0xffffffffu, a0, 2));
            a1 = fmaxf(a1, __shfl_xor_sync(0xffffffffu, a1, 1));
            a1 = fmaxf(a1, __shfl_xor_sync(0xffffffffu, a1, 2));
            if ((lane & 3) == 0) {
                int r = wm*64 + mt*16 + t4;
                red[r*2 + wn] = a0;
                red[(r+8)*2 + wn] = a1;
            }
        }
        __syncthreads();
        #pragma unroll
        for (int mt = 0; mt < 4; mt++) {
            int r = wm*64 + mt*16 + t4;
            mrow[mt][0] = fmaxf(red[r*2+0], red[r*2+1]);
            mrow[mt][1] = fmaxf(red[(r+8)*2+0], red[(r+8)*2+1]);
        }
        float srow[4][2];
        #pragma unroll
        for (int mt = 0; mt < 4; mt++) {
            float s0 = 0.f, s1 = 0.f;
            #pragma unroll
            for (int nt = 0; nt < 8; nt++) {
                acc[mt][nt][0] = expf(acc[mt][nt][0] - mrow[mt][0]);
                acc[mt][nt][1] = expf(acc[mt][nt][1] - mrow[mt][0]);
                acc[mt][nt][2] = expf(acc[mt][nt][2] - mrow[mt][1]);
                acc[mt][nt][3] = expf(acc[mt][nt][3] - mrow[mt][1]);
                s0 += acc[mt][nt][0] + acc[mt][nt][1];
                s1 += acc[mt][nt][2] + acc[mt][nt][3];
            }
            s0 += __shfl_xor_sync(0xffffffffu, s0, 1);
            s0 += __shfl_xor_sync(0xffffffffu, s0, 2);
            s1 += __shfl_xor_sync(0xffffffffu, s1, 1);
            s1 += __shfl_xor_sync(0xffffffffu, s1, 2);
            if ((lane & 3) == 0) {
                int r = wm*64 + mt*16 + t4;
                red2[r*2 + wn] = s0;
                red2[(r+8)*2 + wn] = s1;
            }
        }
        __syncthreads();
        #pragma unroll
        for (int mt = 0; mt < 4; mt++) {
            int r = wm*64 + mt*16 + t4;
            srow[mt][0] = 1.0f / (red2[r*2+0] + red2[r*2+1]);
            srow[mt][1] = 1.0f / (red2[(r+8)*2+0] + red2[(r+8)*2+1]);
        }
        #pragma unroll
        for (int mt = 0; mt < 4; mt++) {
            int row0 = m0 + wm*64 + mt*16 + t4;
            int row1 = row0 + 8;
            #pragma unroll
            for (int nt = 0; nt < 8; nt++) {
                int col = n0 + wn*64 + nt*8 + t2;
                float v0 = acc[mt][nt][0] * srow[mt][0];
                float v1 = acc[mt][nt][1] * srow[mt][0];
                float v2 = acc[mt][nt][2] * srow[mt][1];
                float v3 = acc[mt][nt][3] * srow[mt][1];
                __nv_bfloat162 h0 = __floats2bfloat162_rn(v0, v1);
                __nv_bfloat162 h1 = __floats2bfloat162_rn(v2, v3);
                __nv_bfloat162 l0 = __floats2bfloat162_rn(v0 - __bfloat162float(h0.x), v1 - __bfloat162float(h0.y));
                __nv_bfloat162 l1 = __floats2bfloat162_rn(v2 - __bfloat162float(h1.x), v3 - __bfloat162float(h1.y));
                *(uint32_t*)(Qh + (size_t)row0*DD + col) = *(uint32_t*)&h0;
                *(uint32_t*)(Qh + (size_t)row1*DD + col) = *(uint32_t*)&h1;
                *(uint32_t*)(Ql + (size_t)row0*DD + col) = *(uint32_t*)&l0;
                *(uint32_t*)(Ql + (size_t)row1*DD + col) = *(uint32_t*)&l1;
            }
        }
        return;
    }

    #pragma unroll
    for (int mt = 0; mt < 4; mt++) {
        int row0 = m0 + wm*64 + mt*16 + t4;
        int row1 = row0 + 8;
        float m0v = 0.f, m1v = 0.f;
        if (mode == 1 || mode == 2) { m0v = mask[row0]; m1v = mask[row1]; }
        float add0 = (mode==1) ? (1.0f-m0v)*(-1000000.0f) : 0.f;
        float add1 = (mode==1) ? (1.0f-m1v)*(-1000000.0f) : 0.f;
        float mul0 = (mode==2) ? m0v : 1.f;
        float mul1 = (mode==2) ? m1v : 1.f;
        #pragma unroll
        for (int nt = 0; nt < 8; nt++) {
            int col = n0 + wn*64 + nt*8 + t2;
            float a0 = acc[mt][nt][0];
            float a1 = acc[mt][nt][1];
            float a2 = acc[mt][nt][2];
            float a3 = acc[mt][nt][3];
            if (mode == 1) { a0 += add0; a1 += add0; a2 += add1; a3 += add1; }
            else if (mode == 2) { a0 *= mul0; a1 *= mul0; a2 *= mul1; a3 *= mul1; }
            else if (mode == 3) {
                float2 r0 = *(const float2*)(resid + (size_t)row0*DD + col);
                float2 r1 = *(const float2*)(resid + (size_t)row1*DD + col);
                a0 += r0.x; a1 += r0.y; a2 += r1.x; a3 += r1.y;
            }
            *(float2*)(C + (size_t)row0*DD + col) = make_float2(a0, a1);
            *(float2*)(C + (size_t)row1*DD + col) = make_float2(a2, a3);
        }
    }
}

// ======================= softmax over time -> transposed bf16 hi/lo =========
__global__ void ksoftmaxT_k(const float* __restrict__ k,
                            __nv_bfloat16* __restrict__ kTh,
                            __nv_bfloat16* __restrict__ kTl)
{
    int b = blockIdx.x >> 5;
    int g = blockIdx.x & 31;
    int tx = threadIdx.x, ty = threadIdx.y;
    int d = g*32 + tx;
    float m = -INFINITY, s = 0.f;
    for (int t=ty; t<TT; t+=8){
        float val = k[((size_t)b*TT + t)*DD + d];
        float nm = fmaxf(m, val);
        s = s*expf(m-nm) + expf(val-nm);
        m = nm;
    }
    __shared__ float smax[8][32], ssum[8][32];
    smax[ty][tx]=m; ssum[ty][tx]=s;
    __syncthreads();
    if (ty==0){
        float M=smax[0][tx], S=ssum[0][tx];
        #pragma unroll
        for (int i=1;i<8;i++){
            float m2=smax[i][tx], s2=ssum[i][tx];
            float nm=fmaxf(M,m2);
            S = S*expf(M-nm) + s2*expf(m2-nm);
            M = nm;
        }
        smax[0][tx]=M; ssum[0][tx]=1.0f/S;
    }
    __syncthreads();
    float M=smax[0][tx], R=ssum[0][tx];
    __syncthreads();

    __shared__ __nv_bfloat16 sh[32][33], sl[32][33];
    int dg0 = g*32;
    int h = dg0 >> 7;
    int dl0 = dg0 & 127;
    size_t kbase = ((size_t)(b*HH + h))*DHH + dl0;

    for (int t0 = 0; t0 < TT; t0 += 32) {
        #pragma unroll
        for (int i = 0; i < 4; i++) {
            int t = t0 + ty + i*8;
            float val = expf(k[((size_t)b*TT + t)*DD + d] - M) * R;
            __nv_bfloat16 hv = __float2bfloat16(val);
            sh[tx][ty + i*8] = hv;
            sl[tx][ty + i*8] = __float2bfloat16(val - __bfloat162float(hv));
        }
        __syncthreads();
        #pragma unroll
        for (int i = 0; i < 4; i++) {
            int row = ty + i*8;
            kTh[(kbase + row)*TT + t0 + tx] = sh[row][tx];
            kTl[(kbase + row)*TT + t0 + tx] = sl[row][tx];
        }
        __syncthreads();
    }
}

// ======================= v transpose + split =======================
__global__ __launch_bounds__(1024) void vsplitT_k(const float* __restrict__ v,
                                                  __nv_bfloat16* __restrict__ vTh,
                                                  __nv_bfloat16* __restrict__ vTl)
{
    __shared__ float t[32][33];
    int tx = threadIdx.x, ty = threadIdx.y;
    int bh = blockIdx.z;
    int b = bh >> 3, h = bh & 7;
    int t0 = blockIdx.x * 32;
    int l0 = blockIdx.y * 32;
    t[ty][tx] = v[((size_t)(b*TT) + t0 + ty)*DD + h*DHH + l0 + tx];
    __syncthreads();
    float val = t[tx][ty];
    __nv_bfloat16 hv = __float2bfloat16(val);
    size_t idx = ((size_t)bh*DHH + l0 + ty)*TT + t0 + tx;
    vTh[idx] = hv;
    vTl[idx] = __float2bfloat16(val - __bfloat162float(hv));
}

// ======================= attention core HMMA ================================
#define LD2    136
#define ATE    (128*LD2)
#define ATT_SMEM (4*ATE*2)

__global__ __launch_bounds__(512, 1) void att1_k(
        const __nv_bfloat16* __restrict__ vTh, const __nv_bfloat16* __restrict__ vTl,
        const __nv_bfloat16* __restrict__ kTh, const __nv_bfloat16* __restrict__ kTl,
        float* __restrict__ part)
{
    extern __shared__ __nv_bfloat16 smbuf[];
    const int tid  = threadIdx.x;
    const int lane = tid & 31;
    const int w    = tid >> 5;
    const int wm   = w >> 2;
    const int wn   = w & 3;
    const int chunk = blockIdx.x;
    const int bh    = blockIdx.y;
    const int t0 = chunk * 128;

    #pragma unroll
    for (int i = 0; i < 4; i++) {
        int c = tid + i*512;
        int r = c >> 4;
        int c16 = (c & 15) * 8;
        size_t g = ((size_t)bh*DHH + r)*TT + t0 + c16;
        __nv_bfloat16* d = smbuf + r*LD2 + c16;
        *(uint4*)(d + 0*ATE) = *(const uint4*)(vTh + g);
        *(uint4*)(d + 1*ATE) = *(const uint4*)(vTl + g);
        *(uint4*)(d + 2*ATE) = *(const uint4*)(kTh + g);
        *(uint4*)(d + 3*ATE) = *(const uint4*)(kTl + g);
    }
    __syncthreads();

    const uint32_t smb = smem_to_u32(smbuf);
    const int arow  = wm*32 + (lane & 7) + ((lane >> 3) & 1) * 8;
    const int akoff = ((lane >> 4) & 1) * 8;
    const int brow  = wn*32 + (lane & 7) + ((lane >> 4) & 1) * 8;
    const int bkoff = ((lane >> 3) & 1) * 8;

    float acc[2][4][4];
    #pragma unroll
    for (int i=0;i<2;i++)
        #pragma unroll
        for (int j=0;j<4;j++)
            #pragma unroll
            for (int l=0;l<4;l++) acc[i][j][l]=0.f;

    #pragma unroll
    for (int ks = 0; ks < 8; ks++) {
        uint32_t ah[2][4], al[2][4];
        #pragma unroll
        for (int mt = 0; mt < 2; mt++) {
            uint32_t ra = smb + ((arow + mt*16)*LD2 + ks*16 + akoff) * 2;
            LDSM4(ah[mt], ra);
            LDSM4(al[mt], ra + ATE*2);
        }
        uint32_t bhf[2][4], blf[2][4];
        #pragma unroll
        for (int nb = 0; nb < 2; nb++) {
            uint32_t rb = smb + 2*ATE*2 + ((brow + nb*16)*LD2 + ks*16 + bkoff) * 2;
            LDSM4(bhf[nb], rb);
            LDSM4(blf[nb], rb + ATE*2);
        }
        #pragma unroll
        for (int mt = 0; mt < 2; mt++)
            #pragma unroll
            for (int nt = 0; nt < 4; nt++) {
                int nb = nt >> 1, sub = (nt & 1) * 2;
                MMA_BF16(acc[mt][nt], ah[mt], bhf[nb][sub], bhf[nb][sub+1]);
            }
        #pragma unroll
        for (int mt = 0; mt < 2; mt++)
            #pragma unroll
            for (int nt = 0; nt < 4; nt++) {
                int nb = nt >> 1, sub = (nt & 1) * 2;
                MMA_BF16(acc[mt][nt], ah[mt], blf[nb][sub], blf[nb][sub+1]);
            }
        #pragma unroll
        for (int mt = 0; mt < 2; mt++)
            #pragma unroll
            for (int nt = 0; nt < 4; nt++) {
                int nb = nt >> 1, sub = (nt & 1) * 2;
                MMA_BF16(acc[mt][nt], al[mt], bhf[nb][sub], bhf[nb][sub+1]);
            }
    }

    float* dst = part + ((size_t)(chunk*(BB*HH) + bh))*(DHH*DHH);
    const int t4 = lane >> 2;
    const int t2 = (lane & 3) * 2;
    #pragma unroll
    for (int mt = 0; mt < 2; mt++) {
        int row0 = wm*32 + mt*16 + t4;
        int row1 = row0 + 8;
        #pragma unroll
        for (int nt = 0; nt < 4; nt++) {
            int col = wn*32 + nt*8 + t2;
            *(float2*)(dst + row0*DHH + col) = make_float2(acc[mt][nt][0], acc[mt][nt][1]);
            *(float2*)(dst + row1*DHH + col) = make_float2(acc[mt][nt][2], acc[mt][nt][3]);
        }
    }
}

__global__ void att_reduce_k(const float* __restrict__ part,
                             __nv_bfloat16* __restrict__ ath,
                             __nv_bfloat16* __restrict__ atl)
{
    int i = blockIdx.x*256 + threadIdx.x;
    float s = 0.f;
    #pragma unroll
    for (int c=0;c<NCHUNK;c++) s += part[(size_t)c*(BB*HH*DHH*DHH) + i];
    __nv_bfloat16 h = __float2bfloat16(s);
    ath[i] = h;
    atl[i] = __float2bfloat16(s - __bfloat162float(h));
}

__global__ __launch_bounds__(512, 1) void att2_k(
        const __nv_bfloat16* __restrict__ qh, const __nv_bfloat16* __restrict__ ql,
        const __nv_bfloat16* __restrict__ ath, const __nv_bfloat16* __restrict__ atl,
        float* __restrict__ y)
{
    extern __shared__ __nv_bfloat16 smbuf[];
    const int tid  = threadIdx.x;
    const int lane = tid & 31;
    const int w    = tid >> 5;
    const int wm   = w >> 2;
    const int wn   = w & 3;
    const int m0 = blockIdx.x * 128;
    const int h  = blockIdx.y;
    const int bh = (m0 >> 11) * HH + h;

    #pragma unroll
    for (int i = 0; i < 4; i++) {
        int c = tid + i*512;
        int r = c >> 4;
        int c16 = (c & 15) * 8;
        size_t ga = (size_t)(m0 + r)*DD + h*DHH + c16;
        size_t gb = ((size_t)bh*DHH + r)*DHH + c16;
        __nv_bfloat16* d = smbuf + r*LD2 + c16;
        *(uint4*)(d + 0*ATE) = *(const uint4*)(qh + ga);
        *(uint4*)(d + 1*ATE) = *(const uint4*)(ql + ga);
        *(uint4*)(d + 2*ATE) = *(const uint4*)(ath + gb);
        *(uint4*)(d + 3*ATE) = *(const uint4*)(atl + gb);
    }
    __syncthreads();

    const uint32_t smb = smem_to_u32(smbuf);
    const int arow  = wm*32 + (lane & 7) + ((lane >> 3) & 1) * 8;
    const int akoff = ((lane >> 4) & 1) * 8;
    const int brow  = wn*32 + (lane & 7) + ((lane >> 4) & 1) * 8;
    const int bkoff = ((lane >> 3) & 1) * 8;

    float acc[2][4][4];
    #pragma unroll
    for (int i=0;i<2;i++)
        #pragma unroll
        for (int j=0;j<4;j++)
            #pragma unroll
            for (int l=0;l<4;l++) acc[i][j][l]=0.f;

    #pragma unroll
    for (int ks = 0; ks < 8; ks++) {
        uint32_t ah[2][4], al[2][4];
        #pragma unroll
        for (int mt = 0; mt < 2; mt++) {
            uint32_t ra = smb + ((arow + mt*16)*LD2 + ks*16 + akoff) * 2;
            LDSM4(ah[mt], ra);
            LDSM4(al[mt], ra + ATE*2);
        }
        uint32_t bhf[2][4], blf[2][4];
        #pragma unroll
        for (int nb = 0; nb < 2; nb++) {
            uint32_t rb = smb + 2*ATE*2 + ((brow + nb*16)*LD2 + ks*16 + bkoff) * 2;
            LDSM4(bhf[nb], rb);
            LDSM4(blf[nb], rb + ATE*2);
        }
        #pragma unroll
        for (int mt = 0; mt < 2; mt++)
            #pragma unroll
            for (int nt = 0; nt < 4; nt++) {
                int nb = nt >> 1, sub = (nt & 1) * 2;
                MMA_BF16(acc[mt][nt], ah[mt], bhf[nb][sub], bhf[nb][sub+1]);
            }
        #pragma unroll
        for (int mt = 0; mt < 2; mt++)
            #pragma unroll
            for (int nt = 0; nt < 4; nt++) {
                int nb = nt >> 1, sub = (nt & 1) * 2;
                MMA_BF16(acc[mt][nt], ah[mt], blf[nb][sub], blf[nb][sub+1]);
            }
        #pragma unroll
        for (int mt = 0; mt < 2; mt++)
            #pragma unroll
            for (int nt = 0; nt < 4; nt++) {
                int nb = nt >> 1, sub = (nt & 1) * 2;
                MMA_BF16(acc[mt][nt], al[mt], bhf[nb][sub], bhf[nb][sub+1]);
            }
    }

    const int t4 = lane >> 2;
    const int t2 = (lane & 3) * 2;
    #pragma unroll
    for (int mt = 0; mt < 2; mt++) {
        int row0 = m0 + wm*32 + mt*16 + t4;
        int row1 = row0 + 8;
        #pragma unroll
        for (int nt = 0; nt < 4; nt++) {
            int col = h*DHH + wn*32 + nt*8 + t2;
            *(float2*)(y + (size_t)row0*DD + col) = make_float2(acc[mt][nt][0], acc[mt][nt][1]);
            *(float2*)(y + (size_t)row1*DD + col) = make_float2(acc[mt][nt][2], acc[mt][nt][3]);
        }
    }
}

// ======================= emb path =======================
__global__ void silu_emb_k(const float* __restrict__ emb, float* __restrict__ out)
{
    int i = blockIdx.x*256 + threadIdx.x;
    float e = emb[i];
    out[i] = e / (1.0f + expf(-e));
}

__global__ __launch_bounds__(256) void emb_gemm_k(const float* __restrict__ ea,
                                                  const float* __restrict__ W,
                                                  const float* __restrict__ bias,
                                                  float* __restrict__ out)
{
    int n = blockIdx.x*256 + threadIdx.x;
    int b = blockIdx.y;
    const float* e = ea + b*TEE;
    float acc = 0.f;
    #pragma unroll 8
    for (int t=0;t<TEE;t++)
        acc = fmaf(e[t], W[(size_t)t*(2*DD) + n], acc);
    out[b*(2*DD) + n] = acc + bias[n];
}

// ======================= LN2 + FiLM + SiLU -> bf16 hi/lo =======================
__global__ __launch_bounds__(256) void film_k(const float* __restrict__ y,
                                              const float* __restrict__ w2,
                                              const float* __restrict__ b2,
                                              const float* __restrict__ embout,
                                              __nv_bfloat16* __restrict__ acth,
                                              __nv_bfloat16* __restrict__ actl)
{
    int row = blockIdx.x;
    int b = row / TT;
    int tid = threadIdx.x;
    const float4* yr = (const float4*)(y + (size_t)row*DD);
    float4 v = yr[tid];
    float s  = v.x+v.y+v.z+v.w;
    float ss = v.x*v.x+v.y*v.y+v.z*v.z+v.w*v.w;
    #pragma unroll
    for (int o=16;o>0;o>>=1){ s += __shfl_down_sync(0xffffffffu,s,o); ss += __shfl_down_sync(0xffffffffu,ss,o); }
    __shared__ float sm[8], sm2[8];
    int wid = tid>>5, lane = tid&31;
    if (lane==0){ sm[wid]=s; sm2[wid]=ss; }
    __syncthreads();
    if (tid==0){
        float a=0.f, c=0.f;
        #pragma unroll
        for (int i=0;i<8;i++){ a+=sm[i]; c+=sm2[i]; }
        float mean = a*(1.0f/DD);
        float var  = c*(1.0f/DD) - mean*mean;
        sm[0]=mean; sm2[0]=rsqrtf(var+1e-5f);
    }
    __syncthreads();
    float mean=sm[0], rinv=sm2[0];
    float4 wv=((const float4*)w2)[tid];
    float4 bv=((const float4*)b2)[tid];
    float4 sc=((const float4*)(embout + (size_t)b*(2*DD)))[tid];
    float4 sh=((const float4*)(embout + (size_t)b*(2*DD) + DD))[tid];
    float4 o;
    float h;
    h=(v.x-mean)*rinv*wv.x+bv.x; h=h*(1.0f+sc.x)+sh.x; o.x=h/(1.0f+expf(-h));
    h=(v.y-mean)*rinv*wv.y+bv.y; h=h*(1.0f+sc.y)+sh.y; o.y=h/(1.0f+expf(-h));
    h=(v.z-mean)*rinv*wv.z+bv.z; h=h*(1.0f+sc.z)+sh.z; o.z=h/(1.0f+expf(-h));
    h=(v.w-mean)*rinv*wv.w+bv.w; h=h*(1.0f+sc.w)+sh.w; o.w=h/(1.0f+expf(-h));
    split_store4(acth + (size_t)row*DD + tid*4, actl + (size_t)row*DD + tid*4, o);
}

// ======================= launch =======================
extern "C" void kernel_launch(void* const* d_in, const int* in_sizes, int n_in,
                              void* d_out, int out_size)
{
    (void)in_sizes; (void)n_in; (void)out_size;
    const float* x     = (const float*)d_in[0];
    const float* emb   = (const float*)d_in[1];
    const float* mask  = (const float*)d_in[2];
    const float* ln_w  = (const float*)d_in[4];
    const float* ln_b  = (const float*)d_in[5];
    const float* Wq    = (const float*)d_in[6];
    const float* bq    = (const float*)d_in[7];
    const float* Wk    = (const float*)d_in[8];
    const float* bk    = (const float*)d_in[9];
    const float* Wv    = (const float*)d_in[10];
    const float* bv    = (const float*)d_in[11];
    const float* W_emb = (const float*)d_in[12];
    const float* b_emb = (const float*)d_in[13];
    const float* ln2_w = (const float*)d_in[14];
    const float* ln2_b = (const float*)d_in[15];
    const float* W_out = (const float*)d_in[16];
    const float* b_out = (const float*)d_in[17];
    float* out = (float*)d_out;

    __nv_bfloat16 *p_xnh, *p_xnl, *p_acth, *p_actl, *p_wth, *p_wtl;
    __nv_bfloat16 *p_qh, *p_ql, *p_kTh, *p_kTl, *p_vTh, *p_vTl, *p_ath, *p_atl;
    float *p_k, *p_v, *p_y, *p_attp, *p_emba, *p_embout;
    cudaGetSymbolAddress((void**)&p_xnh,    g_xnhi);
    cudaGetSymbolAddress((void**)&p_xnl,    g_xnlo);
    cudaGetSymbolAddress((void**)&p_acth,   g_acthi);
    cudaGetSymbolAddress((void**)&p_actl,   g_actlo);
    cudaGetSymbolAddress((void**)&p_wth,    g_wthi);
    cudaGetSymbolAddress((void**)&p_wtl,    g_wtlo);
    cudaGetSymbolAddress((void**)&p_k,      g_k);
    cudaGetSymbolAddress((void**)&p_v,      g_v);
    cudaGetSymbolAddress((void**)&p_y,      g_y);
    cudaGetSymbolAddress((void**)&p_qh,     g_qhi);
    cudaGetSymbolAddress((void**)&p_ql,     g_qlo);
    cudaGetSymbolAddress((void**)&p_kTh,    g_kThi);
    cudaGetSymbolAddress((void**)&p_kTl,    g_kTlo);
    cudaGetSymbolAddress((void**)&p_vTh,    g_vThi);
    cudaGetSymbolAddress((void**)&p_vTl,    g_vTlo);
    cudaGetSymbolAddress((void**)&p_ath,    g_attThi);
    cudaGetSymbolAddress((void**)&p_atl,    g_attTlo);
    cudaGetSymbolAddress((void**)&p_attp,   g_att_part);
    cudaGetSymbolAddress((void**)&p_emba,   g_emb_act);
    cudaGetSymbolAddress((void**)&p_embout, g_embout);

    cudaFuncSetAttribute(hgemm_k, cudaFuncAttributeMaxDynamicSharedMemorySize, HG_SMEM);
    cudaFuncSetAttribute(att1_k,  cudaFuncAttributeMaxDynamicSharedMemorySize, ATT_SMEM);
    cudaFuncSetAttribute(att2_k,  cudaFuncAttributeMaxDynamicSharedMemorySize, ATT_SMEM);

    wsplit4_k<<<dim3(32,32,4), dim3(32,32)>>>(Wq, Wk, Wv, W_out, p_wth, p_wtl);
    ln_kernel<<<MM, 256>>>(x, ln_w, ln_b, p_xnh, p_xnl);
    silu_emb_k<<<(BB*TEE)/256, 256>>>(emb, p_emba);

    dim3 ggrid(DD/128, MM/256);    // (8, 32) = 256 blocks, 256 threads
    hgemm_k<<<ggrid, 256, HG_SMEM>>>(p_xnh, p_xnl, p_wth + 0*(size_t)DD*DD, p_wtl + 0*(size_t)DD*DD,
                                     bq, nullptr, nullptr, nullptr, p_qh, p_ql, 0);
    hgemm_k<<<ggrid, 256, HG_SMEM>>>(p_xnh, p_xnl, p_wth + 1*(size_t)DD*DD, p_wtl + 1*(size_t)DD*DD,
                                     bk, mask, nullptr, p_k, nullptr, nullptr, 1);
    hgemm_k<<<ggrid, 256, HG_SMEM>>>(p_xnh, p_xnl, p_wth + 2*(size_t)DD*DD, p_wtl + 2*(size_t)DD*DD,
                                     bv, mask, nullptr, p_v, nullptr, nullptr, 2);

    ksoftmaxT_k<<<BB*32, dim3(32,8)>>>(p_k, p_kTh, p_kTl);
    vsplitT_k<<<dim3(TT/32, DHH/32, BB*HH), dim3(32,32)>>>(p_v, p_vTh, p_vTl);

    att1_k<<<dim3(NCHUNK, BB*HH), 512, ATT_SMEM>>>(p_vTh, p_vTl, p_kTh, p_kTl, p_attp);
    att_reduce_k<<<(BB*HH*DHH*DHH)/256, 256>>>(p_attp, p_ath, p_atl);

    emb_gemm_k<<<dim3((2*DD)/256, BB), 256>>>(p_emba, W_emb, b_emb, p_embout);

    att2_k<<<dim3(MM/128, HH), 512, ATT_SMEM>>>(p_qh, p_ql, p_ath, p_atl, p_y);

    film_k<<<MM, 256>>>(p_y, ln2_w, ln2_b, p_embout, p_acth, p_actl);

    hgemm_k<<<ggrid, 256, HG_SMEM>>>(p_acth, p_actl, p_wth + 3*(size_t)DD*DD, p_wtl + 3*(size_t)DD*DD,
                                     b_out, nullptr, x, out, nullptr, nullptr, 3);
}

// round 10
// speedup vs baseline: 1.1215x; 1.0560x over previous
#include <cuda_runtime.h>
#include <cuda_bf16.h>
#include <math.h>
#include <stdint.h>

#define BB 4
#define TT 2048
#define DD 1024
#define HH 8
#define DHH 128
#define TEE 2048
#define MM (BB*TT)          // 8192 rows
#define NCHUNK 8            // att1 t-chunks (256 t per block)

__device__ __forceinline__ uint32_t smem_to_u32(const void* p) {
    uint32_t a;
    asm("{ .reg .u64 t; cvta.to.shared.u64 t, %1; cvt.u32.u64 %0, t; }" : "=r"(a) : "l"(p));
    return a;
}

#define LDSM4(R, addr) \
    asm volatile("ldmatrix.sync.aligned.m8n8.x4.shared.b16 {%0,%1,%2,%3}, [%4];" \
        : "=r"((R)[0]), "=r"((R)[1]), "=r"((R)[2]), "=r"((R)[3]) : "r"(addr))

#define MMA_BF16(c, a, b0, b1) \
    asm volatile("mma.sync.aligned.m16n8k16.row.col.f32.bf16.bf16.f32 " \
        "{%0,%1,%2,%3}, {%4,%5,%6,%7}, {%8,%9}, {%0,%1,%2,%3};" \
        : "+f"((c)[0]), "+f"((c)[1]), "+f"((c)[2]), "+f"((c)[3]) \
        : "r"((a)[0]), "r"((a)[1]), "r"((a)[2]), "r"((a)[3]), "r"(b0), "r"(b1))

#define CP16(dst, src) \
    asm volatile("cp.async.cg.shared.global [%0], [%1], 16;" :: "r"(dst), "l"(src))
#define CP_COMMIT() asm volatile("cp.async.commit_group;")
#define CP_WAIT1()  asm volatile("cp.async.wait_group 1;")

// ======================= device scratch =======================
__device__ __nv_bfloat16 g_xnhi[MM*DD];
__device__ __nv_bfloat16 g_xnlo[MM*DD];
__device__ __nv_bfloat16 g_acthi[MM*DD];
__device__ __nv_bfloat16 g_actlo[MM*DD];
__device__ __nv_bfloat16 g_wthi[4][DD*DD];
__device__ __nv_bfloat16 g_wtlo[4][DD*DD];
__device__ float g_k [MM*DD];
__device__ float g_y [MM*DD];
__device__ __nv_bfloat16 g_qhi[MM*DD];
__device__ __nv_bfloat16 g_qlo[MM*DD];
__device__ __nv_bfloat16 g_kThi[MM*DD];
__device__ __nv_bfloat16 g_kTlo[MM*DD];
__device__ __nv_bfloat16 g_vThi[MM*DD];
__device__ __nv_bfloat16 g_vTlo[MM*DD];
__device__ float g_att_part[NCHUNK*BB*HH*DHH*DHH];
__device__ __nv_bfloat16 g_attThi[BB*HH*DHH*DHH];
__device__ __nv_bfloat16 g_attTlo[BB*HH*DHH*DHH];
__device__ float g_emb_act[BB*TEE];
__device__ float g_embout[BB*2*DD];

__device__ __forceinline__ void split_store4(__nv_bfloat16* ph, __nv_bfloat16* pl, float4 v) {
    __nv_bfloat162 h0 = __floats2bfloat162_rn(v.x, v.y);
    __nv_bfloat162 h1 = __floats2bfloat162_rn(v.z, v.w);
    float rx = v.x - __bfloat162float(h0.x);
    float ry = v.y - __bfloat162float(h0.y);
    float rz = v.z - __bfloat162float(h1.x);
    float rw = v.w - __bfloat162float(h1.y);
    __nv_bfloat162 l0 = __floats2bfloat162_rn(rx, ry);
    __nv_bfloat162 l1 = __floats2bfloat162_rn(rz, rw);
    uint2 uh; uh.x = *(uint32_t*)&h0; uh.y = *(uint32_t*)&h1;
    uint2 ul; ul.x = *(uint32_t*)&l0; ul.y = *(uint32_t*)&l1;
    *(uint2*)ph = uh;
    *(uint2*)pl = ul;
}

// ======================= LayerNorm -> bf16 hi/lo =======================
__global__ __launch_bounds__(256) void ln_kernel(const float* __restrict__ x,
                                                 const float* __restrict__ w,
                                                 const float* __restrict__ b,
                                                 __nv_bfloat16* __restrict__ outh,
                                                 __nv_bfloat16* __restrict__ outl)
{
    int row = blockIdx.x;
    int tid = threadIdx.x;
    const float4* xr = (const float4*)(x + (size_t)row*DD);
    float4 v = xr[tid];
    float s  = v.x+v.y+v.z+v.w;
    float ss = v.x*v.x+v.y*v.y+v.z*v.z+v.w*v.w;
    #pragma unroll
    for (int o=16;o>0;o>>=1){ s += __shfl_down_sync(0xffffffffu,s,o); ss += __shfl_down_sync(0xffffffffu,ss,o); }
    __shared__ float sm[8], sm2[8];
    int wid = tid>>5, lane = tid&31;
    if (lane==0){ sm[wid]=s; sm2[wid]=ss; }
    __syncthreads();
    if (tid==0){
        float a=0.f, c=0.f;
        #pragma unroll
        for (int i=0;i<8;i++){ a+=sm[i]; c+=sm2[i]; }
        float mean = a*(1.0f/DD);
        float var  = c*(1.0f/DD) - mean*mean;
        sm[0]=mean; sm2[0]=rsqrtf(var+1e-5f);
    }
    __syncthreads();
    float mean=sm[0], rinv=sm2[0];
    float4 wv=((const float4*)w)[tid];
    float4 bv=((const float4*)b)[tid];
    float4 o;
    o.x=(v.x-mean)*rinv*wv.x+bv.x;
    o.y=(v.y-mean)*rinv*wv.y+bv.y;
    o.z=(v.z-mean)*rinv*wv.z+bv.z;
    o.w=(v.w-mean)*rinv*wv.w+bv.w;
    split_store4(outh + (size_t)row*DD + tid*4, outl + (size_t)row*DD + tid*4, o);
}

// ======================= weight transpose + bf16 split (4 weights) ==========
__global__ __launch_bounds__(1024) void wsplit4_k(const float* __restrict__ W0,
                                                  const float* __restrict__ W1,
                                                  const float* __restrict__ W2,
                                                  const float* __restrict__ W3,
                                                  __nv_bfloat16* __restrict__ Thi,
                                                  __nv_bfloat16* __restrict__ Tlo)
{
    __shared__ float t[32][33];
    int tx = threadIdx.x, ty = threadIdx.y;
    int wsel = blockIdx.z;
    const float* W = (wsel==0)?W0:(wsel==1)?W1:(wsel==2)?W2:W3;
    t[ty][tx] = W[(size_t)(blockIdx.y*32+ty)*DD + blockIdx.x*32+tx];
    __syncthreads();
    int n = blockIdx.x*32 + ty;
    int k = blockIdx.y*32 + tx;
    float v = t[tx][ty];
    __nv_bfloat16 h = __float2bfloat16(v);
    size_t base = (size_t)wsel*DD*DD;
    Thi[base + (size_t)n*DD + k] = h;
    Tlo[base + (size_t)n*DD + k] = __float2bfloat16(v - __bfloat162float(h));
}

// ======================= HMMA GEMM, BM=64 BN=128, 2 CTAs/SM =================
// mode 0: softmax-over-dh epilogue -> Qh/Ql (bf16 hi/lo)
// mode 1: +bias+(1-mask)*-1e6 -> C
// mode 2: (+bias)*mask -> transposed vT hi/lo via Qh/Ql [b,h,l,t]
// mode 3: +bias+resid -> C
#define LDSE    40                        // smem row stride (elements)
#define TA_B    (64*LDSE*2)               // 5120 bytes (A tile, 64 rows)
#define TB_B    (128*LDSE*2)              // 10240 bytes (B tile, 128 rows)
#define STAGE_B (2*TA_B + 2*TB_B)         // 30720 bytes per stage
#define HG_SMEM (3*STAGE_B)               // 92160 bytes

__global__ __launch_bounds__(256, 2) void hgemm_k(
        const __nv_bfloat16* __restrict__ Ahi, const __nv_bfloat16* __restrict__ Alo,
        const __nv_bfloat16* __restrict__ Bhi, const __nv_bfloat16* __restrict__ Blo,
        const float* __restrict__ bias, const float* __restrict__ mask,
        const float* __restrict__ resid, float* __restrict__ C,
        __nv_bfloat16* __restrict__ Qh, __nv_bfloat16* __restrict__ Ql, int mode)
{
    extern __shared__ __nv_bfloat16 smbuf[];
    const int tid  = threadIdx.x;
    const int lane = tid & 31;
    const int w    = tid >> 5;      // 0..7
    const int wm   = w >> 2;        // 0..1 (M)
    const int wn   = w & 3;         // 0..3 (N)
    const int m0 = blockIdx.y * 64;
    const int n0 = blockIdx.x * 128;

    const uint32_t smb = smem_to_u32(smbuf);
    const int ra = tid >> 2;            // 0..63
    const int ca = (tid & 3) * 8;
    const __nv_bfloat16* gA0 = Ahi + (size_t)(m0+ra)*DD + ca;
    const __nv_bfloat16* gA1 = Alo + (size_t)(m0+ra)*DD + ca;
    const uint32_t dA = smb + (ra*LDSE + ca)*2;
    const __nv_bfloat16* gB0a = Bhi + (size_t)(n0+ra)*DD + ca;
    const __nv_bfloat16* gB0b = Bhi + (size_t)(n0+64+ra)*DD + ca;
    const __nv_bfloat16* gB1a = Blo + (size_t)(n0+ra)*DD + ca;
    const __nv_bfloat16* gB1b = Blo + (size_t)(n0+64+ra)*DD + ca;
    const uint32_t dBa = smb + 2*TA_B + (ra*LDSE + ca)*2;
    const uint32_t dBb = smb + 2*TA_B + ((64+ra)*LDSE + ca)*2;

    const int arow  = wm*32 + (lane & 7) + ((lane >> 3) & 1) * 8;   // 0..63
    const int akoff = ((lane >> 4) & 1) * 8;
    const int brow  = wn*32 + (lane & 7) + ((lane >> 4) & 1) * 8;   // 0..127
    const int bkoff = ((lane >> 3) & 1) * 8;

    float acc[2][4][4];
    #pragma unroll
    for (int i=0;i<2;i++)
        #pragma unroll
        for (int j=0;j<4;j++)
            #pragma unroll
            for (int l=0;l<4;l++) acc[i][j][l]=0.f;

    #pragma unroll
    for (int s = 0; s < 2; s++) {
        int k0 = s*32;
        uint32_t so = s*STAGE_B;
        CP16(dA  + so,        gA0  + k0);
        CP16(dA  + so + TA_B, gA1  + k0);
        CP16(dBa + so,        gB0a + k0);
        CP16(dBb + so,        gB0b + k0);
        CP16(dBa + so + TB_B, gB1a + k0);
        CP16(dBb + so + TB_B, gB1b + k0);
        CP_COMMIT();
    }

    int st_r = 0, st_w = 2;
    for (int kc = 0; kc < 32; kc++) {
        CP_WAIT1();
        __syncthreads();
        if (kc + 2 < 32) {
            int k0 = (kc+2)*32;
            uint32_t so = st_w*STAGE_B;
            CP16(dA  + so,        gA0  + k0);
            CP16(dA  + so + TA_B, gA1  + k0);
            CP16(dBa + so,        gB0a + k0);
            CP16(dBb + so,        gB0b + k0);
            CP16(dBa + so + TB_B, gB1a + k0);
            CP16(dBb + so + TB_B, gB1b + k0);
        }
        CP_COMMIT();

        uint32_t base = smb + st_r*STAGE_B;
        #pragma unroll
        for (int ks = 0; ks < 2; ks++) {
            uint32_t ah[2][4], al[2][4];
            #pragma unroll
            for (int mt = 0; mt < 2; mt++) {
                uint32_t raddr = base + ((arow + mt*16)*LDSE + ks*16 + akoff) * 2;
                LDSM4(ah[mt], raddr);
                LDSM4(al[mt], raddr + TA_B);
            }
            uint32_t bh[2][4], bl[2][4];
            #pragma unroll
            for (int nb = 0; nb < 2; nb++) {
                uint32_t rb = base + 2*TA_B + ((brow + nb*16)*LDSE + ks*16 + bkoff) * 2;
                LDSM4(bh[nb], rb);
                LDSM4(bl[nb], rb + TB_B);
            }
            #pragma unroll
            for (int mt = 0; mt < 2; mt++)
                #pragma unroll
                for (int nt = 0; nt < 4; nt++) {
                    int nb = nt >> 1, sub = (nt & 1) * 2;
                    MMA_BF16(acc[mt][nt], ah[mt], bh[nb][sub], bh[nb][sub+1]);
                }
            #pragma unroll
            for (int mt = 0; mt < 2; mt++)
                #pragma unroll
                for (int nt = 0; nt < 4; nt++) {
                    int nb = nt >> 1, sub = (nt & 1) * 2;
                    MMA_BF16(acc[mt][nt], ah[mt], bl[nb][sub], bl[nb][sub+1]);
                }
            #pragma unroll
            for (int mt = 0; mt < 2; mt++)
                #pragma unroll
                for (int nt = 0; nt < 4; nt++) {
                    int nb = nt >> 1, sub = (nt & 1) * 2;
                    MMA_BF16(acc[mt][nt], al[mt], bh[nb][sub], bh[nb][sub+1]);
                }
        }
        if (++st_r == 3) st_r = 0;
        if (++st_w == 3) st_w = 0;
    }

    const int t4 = lane >> 2;
    const int t2 = (lane & 3) * 2;

    #pragma unroll
    for (int mt = 0; mt < 2; mt++)
        #pragma unroll
        for (int nt = 0; nt < 4; nt++) {
            int col = n0 + wn*32 + nt*8 + t2;
            float2 bi = *(const float2*)(bias + col);
            acc[mt][nt][0] += bi.x; acc[mt][nt][1] += bi.y;
            acc[mt][nt][2] += bi.x; acc[mt][nt][3] += bi.y;
        }

    if (mode == 0) {
        // fused softmax over 128 cols (one head), 64 rows in this block
        __syncthreads();
        float* red  = (float*)smbuf;    // [64][4]
        float* red2 = red + 256;
        float mrow[2][2];
        #pragma unroll
        for (int mt = 0; mt < 2; mt++) {
            float a0 = -1e30f, a1 = -1e30f;
            #pragma unroll
            for (int nt = 0; nt < 4; nt++) {
                a0 = fmaxf(a0, fmaxf(acc[mt][nt][0], acc[mt][nt][1]));
                a1 = fmaxf(a1, fmaxf(acc[mt][nt][2], acc[mt][nt][3]));
            }
            a0 = fmaxf(a0, __shfl_xor_sync(0xffffffffu, a0, 1));
            a0 = fmaxf(a0, __shfl_xor_sync(0xffffffffu, a0, 2));
            a1 = fmaxf(a1, __shfl_xor_sync(0xffffffffu, a1, 1));
            a1 = fmaxf(a1, __shfl_xor_sync(0xffffffffu, a1, 2));
            if ((lane & 3) == 0) {
                int r = wm*32 + mt*16 + t4;
                red[r*4 + wn] = a0;
                red[(r+8)*4 + wn] = a1;
            }
        }
        __syncthreads();
        #pragma unroll
        for (int mt = 0; mt < 2; mt++) {
            int r = wm*32 + mt*16 + t4;
            mrow[mt][0] = fmaxf(fmaxf(red[r*4+0], red[r*4+1]), fmaxf(red[r*4+2], red[r*4+3]));
            mrow[mt][1] = fmaxf(fmaxf(red[(r+8)*4+0], red[(r+8)*4+1]), fmaxf(red[(r+8)*4+2], red[(r+8)*4+3]));
        }
        float srow[2][2];
        #pragma unroll
        for (int mt = 0; mt < 2; mt++) {
            float s0 = 0.f, s1 = 0.f;
            #pragma unroll
            for (int nt = 0; nt < 4; nt++) {
                acc[mt][nt][0] = expf(acc[mt][nt][0] - mrow[mt][0]);
                acc[mt][nt][1] = expf(acc[mt][nt][1] - mrow[mt][0]);
                acc[mt][nt][2] = expf(acc[mt][nt][2] - mrow[mt][1]);
                acc[mt][nt][3] = expf(acc[mt][nt][3] - mrow[mt][1]);
                s0 += acc[mt][nt][0] + acc[mt][nt][1];
                s1 += acc[mt][nt][2] + acc[mt][nt][3];
            }
            s0 += __shfl_xor_sync(0xffffffffu, s0, 1);
            s0 += __shfl_xor_sync(0xffffffffu, s0, 2);
            s1 += __shfl_xor_sync(0xffffffffu, s1, 1);
            s1 += __shfl_xor_sync(0xffffffffu, s1, 2);
            if ((lane & 3) == 0) {
                int r = wm*32 + mt*16 + t4;
                red2[r*4 + wn] = s0;
                red2[(r+8)*4 + wn] = s1;
            }
        }
        __syncthreads();
        #pragma unroll
        for (int mt = 0; mt < 2; mt++) {
            int r = wm*32 + mt*16 + t4;
            srow[mt][0] = 1.0f / (red2[r*4+0] + red2[r*4+1] + red2[r*4+2] + red2[r*4+3]);
            srow[mt][1] = 1.0f / (red2[(r+8)*4+0] + red2[(r+8)*4+1] + red2[(r+8)*4+2] + red2[(r+8)*4+3]);
        }
        #pragma unroll
        for (int mt = 0; mt < 2; mt++) {
            int row0 = m0 + wm*32 + mt*16 + t4;
            int row1 = row0 + 8;
            #pragma unroll
            for (int nt = 0; nt < 4; nt++) {
                int col = n0 + wn*32 + nt*8 + t2;
                float v0 = acc[mt][nt][0] * srow[mt][0];
                float v1 = acc[mt][nt][1] * srow[mt][0];
                float v2 = acc[mt][nt][2] * srow[mt][1];
                float v3 = acc[mt][nt][3] * srow[mt][1];
                __nv_bfloat162 h0 = __floats2bfloat162_rn(v0, v1);
                __nv_bfloat162 h1 = __floats2bfloat162_rn(v2, v3);
                __nv_bfloat162 l0 = __floats2bfloat162_rn(v0 - __bfloat162float(h0.x), v1 - __bfloat162float(h0.y));
                __nv_bfloat162 l1 = __floats2bfloat162_rn(v2 - __bfloat162float(h1.x), v3 - __bfloat162float(h1.y));
                *(uint32_t*)(Qh + (size_t)row0*DD + col) = *(uint32_t*)&h0;
                *(uint32_t*)(Qh + (size_t)row1*DD + col) = *(uint32_t*)&h1;
                *(uint32_t*)(Ql + (size_t)row0*DD + col) = *(uint32_t*)&l0;
                *(uint32_t*)(Ql + (size_t)row1*DD + col) = *(uint32_t*)&l1;
            }
        }
        return;
    }

    if (mode == 2) {
        // V projection: (acc+bias)*mask -> transposed vT[b][h][l][t] hi/lo
        #pragma unroll
        for (int mt = 0; mt < 2; mt++) {
            int row0 = m0 + wm*32 + mt*16 + t4;
            int row1 = row0 + 8;
            float m0v = mask[row0], m1v = mask[row1];
            int b0 = row0 >> 11, tt0 = row0 & (TT-1);
            int b1 = row1 >> 11, tt1 = row1 & (TT-1);
            #pragma unroll
            for (int nt = 0; nt < 4; nt++) {
                int col = n0 + wn*32 + nt*8 + t2;
                int h = col >> 7, l = col & 127;
                float a0 = acc[mt][nt][0] * m0v;
                float a1 = acc[mt][nt][1] * m0v;
                float a2 = acc[mt][nt][2] * m1v;
                float a3 = acc[mt][nt][3] * m1v;
                size_t i00 = ((size_t)(b0*HH + h)*DHH + l)*TT + tt0;
                size_t i10 = ((size_t)(b1*HH + h)*DHH + l)*TT + tt1;
                __nv_bfloat16 h0 = __float2bfloat16(a0);
                __nv_bfloat16 h1 = __float2bfloat16(a1);
                __nv_bfloat16 h2 = __float2bfloat16(a2);
                __nv_bfloat16 h3 = __float2bfloat16(a3);
                Qh[i00]      = h0;
                Qh[i00 + TT] = h1;
                Qh[i10]      = h2;
                Qh[i10 + TT] = h3;
                Ql[i00]      = __float2bfloat16(a0 - __bfloat162float(h0));
                Ql[i00 + TT] = __float2bfloat16(a1 - __bfloat162float(h1));
                Ql[i10]      = __float2bfloat16(a2 - __bfloat162float(h2));
                Ql[i10 + TT] = __float2bfloat16(a3 - __bfloat162float(h3));
            }
        }
        return;
    }

    #pragma unroll
    for (int mt = 0; mt < 2; mt++) {
        int row0 = m0 + wm*32 + mt*16 + t4;
        int row1 = row0 + 8;
        float m0v = 0.f, m1v = 0.f;
        if (mode == 1) { m0v = mask[row0]; m1v = mask[row1]; }
        float add0 = (mode==1) ? (1.0f-m0v)*(-1000000.0f) : 0.f;
        float add1 = (mode==1) ? (1.0f-m1v)*(-1000000.0f) : 0.f;
        #pragma unroll
        for (int nt = 0; nt < 4; nt++) {
            int col = n0 + wn*32 + nt*8 + t2;
            float a0 = acc[mt][nt][0];
            float a1 = acc[mt][nt][1];
            float a2 = acc[mt][nt][2];
            float a3 = acc[mt][nt][3];
            if (mode == 1) { a0 += add0; a1 += add0; a2 += add1; a3 += add1; }
            else if (mode == 3) {
                float2 r0 = *(const float2*)(resid + (size_t)row0*DD + col);
                float2 r1 = *(const float2*)(resid + (size_t)row1*DD + col);
                a0 += r0.x; a1 += r0.y; a2 += r1.x; a3 += r1.y;
            }
            *(float2*)(C + (size_t)row0*DD + col) = make_float2(a0, a1);
            *(float2*)(C + (size_t)row1*DD + col) = make_float2(a2, a3);
        }
    }
}

// ======================= softmax over time -> transposed bf16 hi/lo =========
__global__ void ksoftmaxT_k(const float* __restrict__ k,
                            __nv_bfloat16* __restrict__ kTh,
                            __nv_bfloat16* __restrict__ kTl)
{
    int b = blockIdx.x >> 5;
    int g = blockIdx.x & 31;
    int tx = threadIdx.x, ty = threadIdx.y;
    int d = g*32 + tx;
    float m = -INFINITY, s = 0.f;
    for (int t=ty; t<TT; t+=8){
        float val = k[((size_t)b*TT + t)*DD + d];
        float nm = fmaxf(m, val);
        s = s*expf(m-nm) + expf(val-nm);
        m = nm;
    }
    __shared__ float smax[8][32], ssum[8][32];
    smax[ty][tx]=m; ssum[ty][tx]=s;
    __syncthreads();
    if (ty==0){
        float M=smax[0][tx], S=ssum[0][tx];
        #pragma unroll
        for (int i=1;i<8;i++){
            float m2=smax[i][tx], s2=ssum[i][tx];
            float nm=fmaxf(M,m2);
            S = S*expf(M-nm) + s2*expf(m2-nm);
            M = nm;
        }
        smax[0][tx]=M; ssum[0][tx]=1.0f/S;
    }
    __syncthreads();
    float M=smax[0][tx], R=ssum[0][tx];
    __syncthreads();

    __shared__ __nv_bfloat16 sh[32][33], sl[32][33];
    int dg0 = g*32;
    int h = dg0 >> 7;
    int dl0 = dg0 & 127;
    size_t kbase = ((size_t)(b*HH + h))*DHH + dl0;

    for (int t0 = 0; t0 < TT; t0 += 32) {
        #pragma unroll
        for (int i = 0; i < 4; i++) {
            int t = t0 + ty + i*8;
            float val = expf(k[((size_t)b*TT + t)*DD + d] - M) * R;
            __nv_bfloat16 hv = __float2bfloat16(val);
            sh[tx][ty + i*8] = hv;
            sl[tx][ty + i*8] = __float2bfloat16(val - __bfloat162float(hv));
        }
        __syncthreads();
        #pragma unroll
        for (int i = 0; i < 4; i++) {
            int row = ty + i*8;
            kTh[(kbase + row)*TT + t0 + tx] = sh[row][tx];
            kTl[(kbase + row)*TT + t0 + tx] = sl[row][tx];
        }
        __syncthreads();
    }
}

// ======================= attention core HMMA ================================
#define LD2    136
#define ATE    (128*LD2)
#define ATT_SMEM (4*ATE*2)

__global__ __launch_bounds__(512, 1) void att1_k(
        const __nv_bfloat16* __restrict__ vTh, const __nv_bfloat16* __restrict__ vTl,
        const __nv_bfloat16* __restrict__ kTh, const __nv_bfloat16* __restrict__ kTl,
        float* __restrict__ part)
{
    extern __shared__ __nv_bfloat16 smbuf[];
    const int tid  = threadIdx.x;
    const int lane = tid & 31;
    const int w    = tid >> 5;
    const int wm   = w >> 2;
    const int wn   = w & 3;
    const int chunk = blockIdx.x;       // 0..7 (256 t each)
    const int bh    = blockIdx.y;

    const uint32_t smb = smem_to_u32(smbuf);
    const int arow  = wm*32 + (lane & 7) + ((lane >> 3) & 1) * 8;
    const int akoff = ((lane >> 4) & 1) * 8;
    const int brow  = wn*32 + (lane & 7) + ((lane >> 4) & 1) * 8;
    const int bkoff = ((lane >> 3) & 1) * 8;

    float acc[2][4][4];
    #pragma unroll
    for (int i=0;i<2;i++)
        #pragma unroll
        for (int j=0;j<4;j++)
            #pragma unroll
            for (int l=0;l<4;l++) acc[i][j][l]=0.f;

    for (int sub = 0; sub < 2; sub++) {
        int t0 = chunk*256 + sub*128;
        #pragma unroll
        for (int i = 0; i < 4; i++) {
            int c = tid + i*512;
            int r = c >> 4;
            int c16 = (c & 15) * 8;
            size_t g = ((size_t)bh*DHH + r)*TT + t0 + c16;
            __nv_bfloat16* d = smbuf + r*LD2 + c16;
            *(uint4*)(d + 0*ATE) = *(const uint4*)(vTh + g);
            *(uint4*)(d + 1*ATE) = *(const uint4*)(vTl + g);
            *(uint4*)(d + 2*ATE) = *(const uint4*)(kTh + g);
            *(uint4*)(d + 3*ATE) = *(const uint4*)(kTl + g);
        }
        __syncthreads();

        #pragma unroll
        for (int ks = 0; ks < 8; ks++) {
            uint32_t ah[2][4], al[2][4];
            #pragma unroll
            for (int mt = 0; mt < 2; mt++) {
                uint32_t ra = smb + ((arow + mt*16)*LD2 + ks*16 + akoff) * 2;
                LDSM4(ah[mt], ra);
                LDSM4(al[mt], ra + ATE*2);
            }
            uint32_t bhf[2][4], blf[2][4];
            #pragma unroll
            for (int nb = 0; nb < 2; nb++) {
                uint32_t rb = smb + 2*ATE*2 + ((brow + nb*16)*LD2 + ks*16 + bkoff) * 2;
                LDSM4(bhf[nb], rb);
                LDSM4(blf[nb], rb + ATE*2);
            }
            #pragma unroll
            for (int mt = 0; mt < 2; mt++)
                #pragma unroll
                for (int nt = 0; nt < 4; nt++) {
                    int nb = nt >> 1, sub2 = (nt & 1) * 2;
                    MMA_BF16(acc[mt][nt], ah[mt], bhf[nb][sub2], bhf[nb][sub2+1]);
                }
            #pragma unroll
            for (int mt = 0; mt < 2; mt++)
                #pragma unroll
                for (int nt = 0; nt < 4; nt++) {
                    int nb = nt >> 1, sub2 = (nt & 1) * 2;
                    MMA_BF16(acc[mt][nt], ah[mt], blf[nb][sub2], blf[nb][sub2+1]);
                }
            #pragma unroll
            for (int mt = 0; mt < 2; mt++)
                #pragma unroll
                for (int nt = 0; nt < 4; nt++) {
                    int nb = nt >> 1, sub2 = (nt & 1) * 2;
                    MMA_BF16(acc[mt][nt], al[mt], bhf[nb][sub2], bhf[nb][sub2+1]);
                }
        }
        __syncthreads();
    }

    float* dst = part + ((size_t)(chunk*(BB*HH) + bh))*(DHH*DHH);
    const int t4 = lane >> 2;
    const int t2 = (lane & 3) * 2;
    #pragma unroll
    for (int mt = 0; mt < 2; mt++) {
        int row0 = wm*32 + mt*16 + t4;
        int row1 = row0 + 8;
        #pragma unroll
        for (int nt = 0; nt < 4; nt++) {
            int col = wn*32 + nt*8 + t2;
            *(float2*)(dst + row0*DHH + col) = make_float2(acc[mt][nt][0], acc[mt][nt][1]);
            *(float2*)(dst + row1*DHH + col) = make_float2(acc[mt][nt][2], acc[mt][nt][3]);
        }
    }
}

__global__ void att_reduce_k(const float* __restrict__ part,
                             __nv_bfloat16* __restrict__ ath,
                             __nv_bfloat16* __restrict__ atl)
{
    int i = blockIdx.x*256 + threadIdx.x;
    float s = 0.f;
    #pragma unroll
    for (int c=0;c<NCHUNK;c++) s += part[(size_t)c*(BB*HH*DHH*DHH) + i];
    __nv_bfloat16 h = __float2bfloat16(s);
    ath[i] = h;
    atl[i] = __float2bfloat16(s - __bfloat162float(h));
}

__global__ __launch_bounds__(512, 1) void att2_k(
        const __nv_bfloat16* __restrict__ qh, const __nv_bfloat16* __restrict__ ql,
        const __nv_bfloat16* __restrict__ ath, const __nv_bfloat16* __restrict__ atl,
        float* __restrict__ y)
{
    extern __shared__ __nv_bfloat16 smbuf[];
    const int tid  = threadIdx.x;
    const int lane = tid & 31;
    const int w    = tid >> 5;
    const int wm   = w >> 2;
    const int wn   = w & 3;
    const int m0 = blockIdx.x * 128;
    const int h  = blockIdx.y;
    const int bh = (m0 >> 11) * HH + h;

    #pragma unroll
    for (int i = 0; i < 4; i++) {
        int c = tid + i*512;
        int r = c >> 4;
        int c16 = (c & 15) * 8;
        size_t ga = (size_t)(m0 + r)*DD + h*DHH + c16;
        size_t gb = ((size_t)bh*DHH + r)*DHH + c16;
        __nv_bfloat16* d = smbuf + r*LD2 + c16;
        *(uint4*)(d + 0*ATE) = *(const uint4*)(qh + ga);
        *(uint4*)(d + 1*ATE) = *(const uint4*)(ql + ga);
        *(uint4*)(d + 2*ATE) = *(const uint4*)(ath + gb);
        *(uint4*)(d + 3*ATE) = *(const uint4*)(atl + gb);
    }
    __syncthreads();

    const uint32_t smb = smem_to_u32(smbuf);
    const int arow  = wm*32 + (lane & 7) + ((lane >> 3) & 1) * 8;
    const int akoff = ((lane >> 4) & 1) * 8;
    const int brow  = wn*32 + (lane & 7) + ((lane >> 4) & 1) * 8;
    const int bkoff = ((lane >> 3) & 1) * 8;

    float acc[2][4][4];
    #pragma unroll
    for (int i=0;i<2;i++)
        #pragma unroll
        for (int j=0;j<4;j++)
            #pragma unroll
            for (int l=0;l<4;l++) acc[i][j][l]=0.f;

    #pragma unroll
    for (int ks = 0; ks < 8; ks++) {
        uint32_t ah[2][4], al[2][4];
        #pragma unroll
        for (int mt = 0; mt < 2; mt++) {
            uint32_t ra = smb + ((arow + mt*16)*LD2 + ks*16 + akoff) * 2;
            LDSM4(ah[mt], ra);
            LDSM4(al[mt], ra + ATE*2);
        }
        uint32_t bhf[2][4], blf[2][4];
        #pragma unroll
        for (int nb = 0; nb < 2; nb++) {
            uint32_t rb = smb + 2*ATE*2 + ((brow + nb*16)*LD2 + ks*16 + bkoff) * 2;
            LDSM4(bhf[nb], rb);
            LDSM4(blf[nb], rb + ATE*2);
        }
        #pragma unroll
        for (int mt = 0; mt < 2; mt++)
            #pragma unroll
            for (int nt = 0; nt < 4; nt++) {
                int nb = nt >> 1, sub = (nt & 1) * 2;
                MMA_BF16(acc[mt][nt], ah[mt], bhf[nb][sub], bhf[nb][sub+1]);
            }
        #pragma unroll
        for (int mt = 0; mt < 2; mt++)
            #pragma unroll
            for (int nt = 0; nt < 4; nt++) {
                int nb = nt >> 1, sub = (nt & 1) * 2;
                MMA_BF16(acc[mt][nt], ah[mt], blf[nb][sub], blf[nb][sub+1]);
            }
        #pragma unroll
        for (int mt = 0; mt < 2; mt++)
            #pragma unroll
            for (int nt = 0; nt < 4; nt++) {
                int nb = nt >> 1, sub = (nt & 1) * 2;
                MMA_BF16(acc[mt][nt], al[mt], bhf[nb][sub], bhf[nb][sub+1]);
            }
    }

    const int t4 = lane >> 2;
    const int t2 = (lane & 3) * 2;
    #pragma unroll
    for (int mt = 0; mt < 2; mt++) {
        int row0 = m0 + wm*32 + mt*16 + t4;
        int row1 = row0 + 8;
        #pragma unroll
        for (int nt = 0; nt < 4; nt++) {
            int col = h*DHH + wn*32 + nt*8 + t2;
            *(float2*)(y + (size_t)row0*DD + col) = make_float2(acc[mt][nt][0], acc[mt][nt][1]);
            *(float2*)(y + (size_t)row1*DD + col) = make_float2(acc[mt][nt][2], acc[mt][nt][3]);
        }
    }
}

// ======================= emb path =======================
__global__ void silu_emb_k(const float* __restrict__ emb, float* __restrict__ out)
{
    int i = blockIdx.x*256 + threadIdx.x;
    float e = emb[i];
    out[i] = e / (1.0f + expf(-e));
}

__global__ __launch_bounds__(256) void emb_gemm_k(const float* __restrict__ ea,
                                                  const float* __restrict__ W,
                                                  const float* __restrict__ bias,
                                                  float* __restrict__ out)
{
    int n = blockIdx.x*256 + threadIdx.x;
    int b = blockIdx.y;
    const float* e = ea + b*TEE;
    float acc = 0.f;
    #pragma unroll 8
    for (int t=0;t<TEE;t++)
        acc = fmaf(e[t], W[(size_t)t*(2*DD) + n], acc);
    out[b*(2*DD) + n] = acc + bias[n];
}

// ======================= LN2 + FiLM + SiLU -> bf16 hi/lo =======================
__global__ __launch_bounds__(256) void film_k(const float* __restrict__ y,
                                              const float* __restrict__ w2,
                                              const float* __restrict__ b2,
                                              const float* __restrict__ embout,
                                              __nv_bfloat16* __restrict__ acth,
                                              __nv_bfloat16* __restrict__ actl)
{
    int row = blockIdx.x;
    int b = row / TT;
    int tid = threadIdx.x;
    const float4* yr = (const float4*)(y + (size_t)row*DD);
    float4 v = yr[tid];
    float s  = v.x+v.y+v.z+v.w;
    float ss = v.x*v.x+v.y*v.y+v.z*v.z+v.w*v.w;
    #pragma unroll
    for (int o=16;o>0;o>>=1){ s += __shfl_down_sync(0xffffffffu,s,o); ss += __shfl_down_sync(0xffffffffu,ss,o); }
    __shared__ float sm[8], sm2[8];
    int wid = tid>>5, lane = tid&31;
    if (lane==0){ sm[wid]=s; sm2[wid]=ss; }
    __syncthreads();
    if (tid==0){
        float a=0.f, c=0.f;
        #pragma unroll
        for (int i=0;i<8;i++){ a+=sm[i]; c+=sm2[i]; }
        float mean = a*(1.0f/DD);
        float var  = c*(1.0f/DD) - mean*mean;
        sm[0]=mean; sm2[0]=rsqrtf(var+1e-5f);
    }
    __syncthreads();
    float mean=sm[0], rinv=sm2[0];
    float4 wv=((const float4*)w2)[tid];
    float4 bv=((const float4*)b2)[tid];
    float4 sc=((const float4*)(embout + (size_t)b*(2*DD)))[tid];
    float4 sh=((const float4*)(embout + (size_t)b*(2*DD) + DD))[tid];
    float4 o;
    float h;
    h=(v.x-mean)*rinv*wv.x+bv.x; h=h*(1.0f+sc.x)+sh.x; o.x=h/(1.0f+expf(-h));
    h=(v.y-mean)*rinv*wv.y+bv.y; h=h*(1.0f+sc.y)+sh.y; o.y=h/(1.0f+expf(-h));
    h=(v.z-mean)*rinv*wv.z+bv.z; h=h*(1.0f+sc.z)+sh.z; o.z=h/(1.0f+expf(-h));
    h=(v.w-mean)*rinv*wv.w+bv.w; h=h*(1.0f+sc.w)+sh.w; o.w=h/(1.0f+expf(-h));
    split_store4(acth + (size_t)row*DD + tid*4, actl + (size_t)row*DD + tid*4, o);
}

// ======================= launch =======================
extern "C" void kernel_launch(void* const* d_in, const int* in_sizes, int n_in,
                              void* d_out, int out_size)
{
    (void)in_sizes; (void)n_in; (void)out_size;
    const float* x     = (const float*)d_in[0];
    const float* emb   = (const float*)d_in[1];
    const float* mask  = (const float*)d_in[2];
    const float* ln_w  = (const float*)d_in[4];
    const float* ln_b  = (const float*)d_in[5];
    const float* Wq    = (const float*)d_in[6];
    const float* bq    = (const float*)d_in[7];
    const float* Wk    = (const float*)d_in[8];
    const float* bk    = (const float*)d_in[9];
    const float* Wv    = (const float*)d_in[10];
    const float* bv    = (const float*)d_in[11];
    const float* W_emb = (const float*)d_in[12];
    const float* b_emb = (const float*)d_in[13];
    const float* ln2_w = (const float*)d_in[14];
    const float* ln2_b = (const float*)d_in[15];
    const float* W_out = (const float*)d_in[16];
    const float* b_out = (const float*)d_in[17];
    float* out = (float*)d_out;

    __nv_bfloat16 *p_xnh, *p_xnl, *p_acth, *p_actl, *p_wth, *p_wtl;
    __nv_bfloat16 *p_qh, *p_ql, *p_kTh, *p_kTl, *p_vTh, *p_vTl, *p_ath, *p_atl;
    float *p_k, *p_y, *p_attp, *p_emba, *p_embout;
    cudaGetSymbolAddress((void**)&p_xnh,    g_xnhi);
    cudaGetSymbolAddress((void**)&p_xnl,    g_xnlo);
    cudaGetSymbolAddress((void**)&p_acth,   g_acthi);
    cudaGetSymbolAddress((void**)&p_actl,   g_actlo);
    cudaGetSymbolAddress((void**)&p_wth,    g_wthi);
    cudaGetSymbolAddress((void**)&p_wtl,    g_wtlo);
    cudaGetSymbolAddress((void**)&p_k,      g_k);
    cudaGetSymbolAddress((void**)&p_y,      g_y);
    cudaGetSymbolAddress((void**)&p_qh,     g_qhi);
    cudaGetSymbolAddress((void**)&p_ql,     g_qlo);
    cudaGetSymbolAddress((void**)&p_kTh,    g_kThi);
    cudaGetSymbolAddress((void**)&p_kTl,    g_kTlo);
    cudaGetSymbolAddress((void**)&p_vTh,    g_vThi);
    cudaGetSymbolAddress((void**)&p_vTl,    g_vTlo);
    cudaGetSymbolAddress((void**)&p_ath,    g_attThi);
    cudaGetSymbolAddress((void**)&p_atl,    g_attTlo);
    cudaGetSymbolAddress((void**)&p_attp,   g_att_part);
    cudaGetSymbolAddress((void**)&p_emba,   g_emb_act);
    cudaGetSymbolAddress((void**)&p_embout, g_embout);

    cudaFuncSetAttribute(hgemm_k, cudaFuncAttributeMaxDynamicSharedMemorySize, HG_SMEM);
    cudaFuncSetAttribute(att1_k,  cudaFuncAttributeMaxDynamicSharedMemorySize, ATT_SMEM);
    cudaFuncSetAttribute(att2_k,  cudaFuncAttributeMaxDynamicSharedMemorySize, ATT_SMEM);

    wsplit4_k<<<dim3(32,32,4), dim3(32,32)>>>(Wq, Wk, Wv, W_out, p_wth, p_wtl);
    ln_kernel<<<MM, 256>>>(x, ln_w, ln_b, p_xnh, p_xnl);
    silu_emb_k<<<(BB*TEE)/256, 256>>>(emb, p_emba);

    dim3 ggrid(DD/128, MM/64);    // (8, 128) = 1024 blocks, 256 threads
    hgemm_k<<<ggrid, 256, HG_SMEM>>>(p_xnh, p_xnl, p_wth + 0*(size_t)DD*DD, p_wtl + 0*(size_t)DD*DD,
                                     bq, nullptr, nullptr, nullptr, p_qh, p_ql, 0);
    hgemm_k<<<ggrid, 256, HG_SMEM>>>(p_xnh, p_xnl, p_wth + 1*(size_t)DD*DD, p_wtl + 1*(size_t)DD*DD,
                                     bk, mask, nullptr, p_k, nullptr, nullptr, 1);
    hgemm_k<<<ggrid, 256, HG_SMEM>>>(p_xnh, p_xnl, p_wth + 2*(size_t)DD*DD, p_wtl + 2*(size_t)DD*DD,
                                     bv, mask, nullptr, nullptr, p_vTh, p_vTl, 2);

    ksoftmaxT_k<<<BB*32, dim3(32,8)>>>(p_k, p_kTh, p_kTl);

    att1_k<<<dim3(NCHUNK, BB*HH), 512, ATT_SMEM>>>(p_vTh, p_vTl, p_kTh, p_kTl, p_attp);
    att_reduce_k<<<(BB*HH*DHH*DHH)/256, 256>>>(p_attp, p_ath, p_atl);

    emb_gemm_k<<<dim3((2*DD)/256, BB), 256>>>(p_emba, W_emb, b_emb, p_embout);

    att2_k<<<dim3(MM/128, HH), 512, ATT_SMEM>>>(p_qh, p_ql, p_ath, p_atl, p_y);

    film_k<<<MM, 256>>>(p_y, ln2_w, ln2_b, p_embout, p_acth, p_actl);

    hgemm_k<<<ggrid, 256, HG_SMEM>>>(p_acth, p_actl, p_wth + 3*(size_t)DD*DD, p_wtl + 3*(size_t)DD*DD,
                                     b_out, nullptr, x, out, nullptr, nullptr, 3);
}

// round 11
// speedup vs baseline: 1.1610x; 1.0352x over previous
#include <cuda_runtime.h>
#include <cuda_bf16.h>
#include <math.h>
#include <stdint.h>

#define BB 4
#define TT 2048
#define DD 1024
#define HH 8
#define DHH 128
#define TEE 2048
#define MM (BB*TT)          // 8192 rows
#define NCHUNK 8            // att1 t-chunks (256 t per block)

__device__ __forceinline__ uint32_t smem_to_u32(const void* p) {
    uint32_t a;
    asm("{ .reg .u64 t; cvta.to.shared.u64 t, %1; cvt.u32.u64 %0, t; }" : "=r"(a) : "l"(p));
    return a;
}

#define LDSM4(R, addr) \
    asm volatile("ldmatrix.sync.aligned.m8n8.x4.shared.b16 {%0,%1,%2,%3}, [%4];" \
        : "=r"((R)[0]), "=r"((R)[1]), "=r"((R)[2]), "=r"((R)[3]) : "r"(addr))

#define MMA_BF16(c, a, b0, b1) \
    asm volatile("mma.sync.aligned.m16n8k16.row.col.f32.bf16.bf16.f32 " \
        "{%0,%1,%2,%3}, {%4,%5,%6,%7}, {%8,%9}, {%0,%1,%2,%3};" \
        : "+f"((c)[0]), "+f"((c)[1]), "+f"((c)[2]), "+f"((c)[3]) \
        : "r"((a)[0]), "r"((a)[1]), "r"((a)[2]), "r"((a)[3]), "r"(b0), "r"(b1))

#define CP16(dst, src) \
    asm volatile("cp.async.cg.shared.global [%0], [%1], 16;" :: "r"(dst), "l"(src))
#define CP_COMMIT() asm volatile("cp.async.commit_group;")
#define CP_WAIT1()  asm volatile("cp.async.wait_group 1;")

// ======================= device scratch =======================
__device__ __nv_bfloat16 g_xnhi[MM*DD];
__device__ __nv_bfloat16 g_xnlo[MM*DD];
__device__ __nv_bfloat16 g_acthi[MM*DD];
__device__ __nv_bfloat16 g_actlo[MM*DD];
__device__ __nv_bfloat16 g_wthi[4][DD*DD];
__device__ __nv_bfloat16 g_wtlo[4][DD*DD];
__device__ float g_k [MM*DD];
__device__ float g_y [MM*DD];
__device__ __nv_bfloat16 g_qhi[MM*DD];
__device__ __nv_bfloat16 g_qlo[MM*DD];
__device__ __nv_bfloat16 g_kThi[MM*DD];
__device__ __nv_bfloat16 g_kTlo[MM*DD];
__device__ __nv_bfloat16 g_vThi[MM*DD];
__device__ __nv_bfloat16 g_vTlo[MM*DD];
__device__ float g_att_part[NCHUNK*BB*HH*DHH*DHH];
__device__ __nv_bfloat16 g_attThi[BB*HH*DHH*DHH];
__device__ __nv_bfloat16 g_attTlo[BB*HH*DHH*DHH];
__device__ float g_emb_act[BB*TEE];
__device__ float g_embout[BB*2*DD];

__device__ __forceinline__ void split_store4(__nv_bfloat16* ph, __nv_bfloat16* pl, float4 v) {
    __nv_bfloat162 h0 = __floats2bfloat162_rn(v.x, v.y);
    __nv_bfloat162 h1 = __floats2bfloat162_rn(v.z, v.w);
    float rx = v.x - __bfloat162float(h0.x);
    float ry = v.y - __bfloat162float(h0.y);
    float rz = v.z - __bfloat162float(h1.x);
    float rw = v.w - __bfloat162float(h1.y);
    __nv_bfloat162 l0 = __floats2bfloat162_rn(rx, ry);
    __nv_bfloat162 l1 = __floats2bfloat162_rn(rz, rw);
    uint2 uh; uh.x = *(uint32_t*)&h0; uh.y = *(uint32_t*)&h1;
    uint2 ul; ul.x = *(uint32_t*)&l0; ul.y = *(uint32_t*)&l1;
    *(uint2*)ph = uh;
    *(uint2*)pl = ul;
}

// ======================= LayerNorm -> bf16 hi/lo =======================
__global__ __launch_bounds__(256) void ln_kernel(const float* __restrict__ x,
                                                 const float* __restrict__ w,
                                                 const float* __restrict__ b,
                                                 __nv_bfloat16* __restrict__ outh,
                                                 __nv_bfloat16* __restrict__ outl)
{
    int row = blockIdx.x;
    int tid = threadIdx.x;
    const float4* xr = (const float4*)(x + (size_t)row*DD);
    float4 v = xr[tid];
    float s  = v.x+v.y+v.z+v.w;
    float ss = v.x*v.x+v.y*v.y+v.z*v.z+v.w*v.w;
    #pragma unroll
    for (int o=16;o>0;o>>=1){ s += __shfl_down_sync(0xffffffffu,s,o); ss += __shfl_down_sync(0xffffffffu,ss,o); }
    __shared__ float sm[8], sm2[8];
    int wid = tid>>5, lane = tid&31;
    if (lane==0){ sm[wid]=s; sm2[wid]=ss; }
    __syncthreads();
    if (tid==0){
        float a=0.f, c=0.f;
        #pragma unroll
        for (int i=0;i<8;i++){ a+=sm[i]; c+=sm2[i]; }
        float mean = a*(1.0f/DD);
        float var  = c*(1.0f/DD) - mean*mean;
        sm[0]=mean; sm2[0]=rsqrtf(var+1e-5f);
    }
    __syncthreads();
    float mean=sm[0], rinv=sm2[0];
    float4 wv=((const float4*)w)[tid];
    float4 bv=((const float4*)b)[tid];
    float4 o;
    o.x=(v.x-mean)*rinv*wv.x+bv.x;
    o.y=(v.y-mean)*rinv*wv.y+bv.y;
    o.z=(v.z-mean)*rinv*wv.z+bv.z;
    o.w=(v.w-mean)*rinv*wv.w+bv.w;
    split_store4(outh + (size_t)row*DD + tid*4, outl + (size_t)row*DD + tid*4, o);
}

// ======================= weight transpose + bf16 split (4 weights) ==========
__global__ __launch_bounds__(1024) void wsplit4_k(const float* __restrict__ W0,
                                                  const float* __restrict__ W1,
                                                  const float* __restrict__ W2,
                                                  const float* __restrict__ W3,
                                                  __nv_bfloat16* __restrict__ Thi,
                                                  __nv_bfloat16* __restrict__ Tlo)
{
    __shared__ float t[32][33];
    int tx = threadIdx.x, ty = threadIdx.y;
    int wsel = blockIdx.z;
    const float* W = (wsel==0)?W0:(wsel==1)?W1:(wsel==2)?W2:W3;
    t[ty][tx] = W[(size_t)(blockIdx.y*32+ty)*DD + blockIdx.x*32+tx];
    __syncthreads();
    int n = blockIdx.x*32 + ty;
    int k = blockIdx.y*32 + tx;
    float v = t[tx][ty];
    __nv_bfloat16 h = __float2bfloat16(v);
    size_t base = (size_t)wsel*DD*DD;
    Thi[base + (size_t)n*DD + k] = h;
    Tlo[base + (size_t)n*DD + k] = __float2bfloat16(v - __bfloat162float(h));
}

// ======================= HMMA GEMM, BM=64 BN=128, 2 CTAs/SM =================
// mode 0: softmax-over-dh epilogue -> Qh/Ql (bf16 hi/lo)
// mode 1: +bias+(1-mask)*-1e6 -> C (fp32)
// mode 2: (+bias)*mask -> transposed vT hi/lo [b,h,l,t]
// mode 3: +bias+resid -> C
// mode_ov < 0: QKV fused — mode = blockIdx.z, weight slice = z
#define LDSE    40                        // smem row stride (elements)
#define TA_B    (64*LDSE*2)               // 5120 bytes (A tile, 64 rows)
#define TB_B    (128*LDSE*2)              // 10240 bytes (B tile, 128 rows)
#define STAGE_B (2*TA_B + 2*TB_B)         // 30720 bytes per stage
#define HG_SMEM (3*STAGE_B)               // 92160 bytes

__global__ __launch_bounds__(256, 2) void hgemm_k(
        const __nv_bfloat16* __restrict__ Ahi, const __nv_bfloat16* __restrict__ Alo,
        const __nv_bfloat16* __restrict__ Whi, const __nv_bfloat16* __restrict__ Wlo,
        const float* __restrict__ bias0, const float* __restrict__ bias1,
        const float* __restrict__ bias2,
        const float* __restrict__ mask,
        const float* __restrict__ resid, float* __restrict__ C,
        __nv_bfloat16* __restrict__ Qh, __nv_bfloat16* __restrict__ Ql,
        __nv_bfloat16* __restrict__ Vh, __nv_bfloat16* __restrict__ Vl,
        int mode_ov)
{
    extern __shared__ __nv_bfloat16 smbuf[];
    const int tid  = threadIdx.x;
    const int lane = tid & 31;
    const int w    = tid >> 5;      // 0..7
    const int wm   = w >> 2;        // 0..1 (M)
    const int wn   = w & 3;         // 0..3 (N)
    const int m0 = blockIdx.y * 64;
    const int n0 = blockIdx.x * 128;
    const int mode = (mode_ov >= 0) ? mode_ov : (int)blockIdx.z;
    const int wsel = (mode_ov >= 0) ? 0 : (int)blockIdx.z;
    const float* bias = (mode == 1) ? bias1 : (mode == 2) ? bias2 : bias0;
    const __nv_bfloat16* Bhi = Whi + (size_t)wsel*DD*DD;
    const __nv_bfloat16* Blo = Wlo + (size_t)wsel*DD*DD;

    const uint32_t smb = smem_to_u32(smbuf);
    const int ra = tid >> 2;            // 0..63
    const int ca = (tid & 3) * 8;
    const __nv_bfloat16* gA0 = Ahi + (size_t)(m0+ra)*DD + ca;
    const __nv_bfloat16* gA1 = Alo + (size_t)(m0+ra)*DD + ca;
    const uint32_t dA = smb + (ra*LDSE + ca)*2;
    const __nv_bfloat16* gB0a = Bhi + (size_t)(n0+ra)*DD + ca;
    const __nv_bfloat16* gB0b = Bhi + (size_t)(n0+64+ra)*DD + ca;
    const __nv_bfloat16* gB1a = Blo + (size_t)(n0+ra)*DD + ca;
    const __nv_bfloat16* gB1b = Blo + (size_t)(n0+64+ra)*DD + ca;
    const uint32_t dBa = smb + 2*TA_B + (ra*LDSE + ca)*2;
    const uint32_t dBb = smb + 2*TA_B + ((64+ra)*LDSE + ca)*2;

    const int arow  = wm*32 + (lane & 7) + ((lane >> 3) & 1) * 8;   // 0..63
    const int akoff = ((lane >> 4) & 1) * 8;
    const int brow  = wn*32 + (lane & 7) + ((lane >> 4) & 1) * 8;   // 0..127
    const int bkoff = ((lane >> 3) & 1) * 8;

    float acc[2][4][4];
    #pragma unroll
    for (int i=0;i<2;i++)
        #pragma unroll
        for (int j=0;j<4;j++)
            #pragma unroll
            for (int l=0;l<4;l++) acc[i][j][l]=0.f;

    #pragma unroll
    for (int s = 0; s < 2; s++) {
        int k0 = s*32;
        uint32_t so = s*STAGE_B;
        CP16(dA  + so,        gA0  + k0);
        CP16(dA  + so + TA_B, gA1  + k0);
        CP16(dBa + so,        gB0a + k0);
        CP16(dBb + so,        gB0b + k0);
        CP16(dBa + so + TB_B, gB1a + k0);
        CP16(dBb + so + TB_B, gB1b + k0);
        CP_COMMIT();
    }

    int st_r = 0, st_w = 2;
    for (int kc = 0; kc < 32; kc++) {
        CP_WAIT1();
        __syncthreads();
        if (kc + 2 < 32) {
            int k0 = (kc+2)*32;
            uint32_t so = st_w*STAGE_B;
            CP16(dA  + so,        gA0  + k0);
            CP16(dA  + so + TA_B, gA1  + k0);
            CP16(dBa + so,        gB0a + k0);
            CP16(dBb + so,        gB0b + k0);
            CP16(dBa + so + TB_B, gB1a + k0);
            CP16(dBb + so + TB_B, gB1b + k0);
        }
        CP_COMMIT();

        uint32_t base = smb + st_r*STAGE_B;
        #pragma unroll
        for (int ks = 0; ks < 2; ks++) {
            uint32_t ah[2][4], al[2][4];
            #pragma unroll
            for (int mt = 0; mt < 2; mt++) {
                uint32_t raddr = base + ((arow + mt*16)*LDSE + ks*16 + akoff) * 2;
                LDSM4(ah[mt], raddr);
                LDSM4(al[mt], raddr + TA_B);
            }
            uint32_t bh[2][4], bl[2][4];
            #pragma unroll
            for (int nb = 0; nb < 2; nb++) {
                uint32_t rb = base + 2*TA_B + ((brow + nb*16)*LDSE + ks*16 + bkoff) * 2;
                LDSM4(bh[nb], rb);
                LDSM4(bl[nb], rb + TB_B);
            }
            #pragma unroll
            for (int mt = 0; mt < 2; mt++)
                #pragma unroll
                for (int nt = 0; nt < 4; nt++) {
                    int nb = nt >> 1, sub = (nt & 1) * 2;
                    MMA_BF16(acc[mt][nt], ah[mt], bh[nb][sub], bh[nb][sub+1]);
                }
            #pragma unroll
            for (int mt = 0; mt < 2; mt++)
                #pragma unroll
                for (int nt = 0; nt < 4; nt++) {
                    int nb = nt >> 1, sub = (nt & 1) * 2;
                    MMA_BF16(acc[mt][nt], ah[mt], bl[nb][sub], bl[nb][sub+1]);
                }
            #pragma unroll
            for (int mt = 0; mt < 2; mt++)
                #pragma unroll
                for (int nt = 0; nt < 4; nt++) {
                    int nb = nt >> 1, sub = (nt & 1) * 2;
                    MMA_BF16(acc[mt][nt], al[mt], bh[nb][sub], bh[nb][sub+1]);
                }
        }
        if (++st_r == 3) st_r = 0;
        if (++st_w == 3) st_w = 0;
    }

    const int t4 = lane >> 2;
    const int t2 = (lane & 3) * 2;

    #pragma unroll
    for (int mt = 0; mt < 2; mt++)
        #pragma unroll
        for (int nt = 0; nt < 4; nt++) {
            int col = n0 + wn*32 + nt*8 + t2;
            float2 bi = *(const float2*)(bias + col);
            acc[mt][nt][0] += bi.x; acc[mt][nt][1] += bi.y;
            acc[mt][nt][2] += bi.x; acc[mt][nt][3] += bi.y;
        }

    if (mode == 0) {
        // fused softmax over 128 cols (one head), 64 rows in this block
        __syncthreads();
        float* red  = (float*)smbuf;    // [64][4]
        float* red2 = red + 256;
        float mrow[2][2];
        #pragma unroll
        for (int mt = 0; mt < 2; mt++) {
            float a0 = -1e30f, a1 = -1e30f;
            #pragma unroll
            for (int nt = 0; nt < 4; nt++) {
                a0 = fmaxf(a0, fmaxf(acc[mt][nt][0], acc[mt][nt][1]));
                a1 = fmaxf(a1, fmaxf(acc[mt][nt][2], acc[mt][nt][3]));
            }
            a0 = fmaxf(a0, __shfl_xor_sync(0xffffffffu, a0, 1));
            a0 = fmaxf(a0, __shfl_xor_sync(0xffffffffu, a0, 2));
            a1 = fmaxf(a1, __shfl_xor_sync(0xffffffffu, a1, 1));
            a1 = fmaxf(a1, __shfl_xor_sync(0xffffffffu, a1, 2));
            if ((lane & 3) == 0) {
                int r = wm*32 + mt*16 + t4;
                red[r*4 + wn] = a0;
                red[(r+8)*4 + wn] = a1;
            }
        }
        __syncthreads();
        #pragma unroll
        for (int mt = 0; mt < 2; mt++) {
            int r = wm*32 + mt*16 + t4;
            mrow[mt][0] = fmaxf(fmaxf(red[r*4+0], red[r*4+1]), fmaxf(red[r*4+2], red[r*4+3]));
            mrow[mt][1] = fmaxf(fmaxf(red[(r+8)*4+0], red[(r+8)*4+1]), fmaxf(red[(r+8)*4+2], red[(r+8)*4+3]));
        }
        float srow[2][2];
        #pragma unroll
        for (int mt = 0; mt < 2; mt++) {
            float s0 = 0.f, s1 = 0.f;
            #pragma unroll
            for (int nt = 0; nt < 4; nt++) {
                acc[mt][nt][0] = expf(acc[mt][nt][0] - mrow[mt][0]);
                acc[mt][nt][1] = expf(acc[mt][nt][1] - mrow[mt][0]);
                acc[mt][nt][2] = expf(acc[mt][nt][2] - mrow[mt][1]);
                acc[mt][nt][3] = expf(acc[mt][nt][3] - mrow[mt][1]);
                s0 += acc[mt][nt][0] + acc[mt][nt][1];
                s1 += acc[mt][nt][2] + acc[mt][nt][3];
            }
            s0 += __shfl_xor_sync(0xffffffffu, s0, 1);
            s0 += __shfl_xor_sync(0xffffffffu, s0, 2);
            s1 += __shfl_xor_sync(0xffffffffu, s1, 1);
            s1 += __shfl_xor_sync(0xffffffffu, s1, 2);
            if ((lane & 3) == 0) {
                int r = wm*32 + mt*16 + t4;
                red2[r*4 + wn] = s0;
                red2[(r+8)*4 + wn] = s1;
            }
        }
        __syncthreads();
        #pragma unroll
        for (int mt = 0; mt < 2; mt++) {
            int r = wm*32 + mt*16 + t4;
            srow[mt][0] = 1.0f / (red2[r*4+0] + red2[r*4+1] + red2[r*4+2] + red2[r*4+3]);
            srow[mt][1] = 1.0f / (red2[(r+8)*4+0] + red2[(r+8)*4+1] + red2[(r+8)*4+2] + red2[(r+8)*4+3]);
        }
        #pragma unroll
        for (int mt = 0; mt < 2; mt++) {
            int row0 = m0 + wm*32 + mt*16 + t4;
            int row1 = row0 + 8;
            #pragma unroll
            for (int nt = 0; nt < 4; nt++) {
                int col = n0 + wn*32 + nt*8 + t2;
                float v0 = acc[mt][nt][0] * srow[mt][0];
                float v1 = acc[mt][nt][1] * srow[mt][0];
                float v2 = acc[mt][nt][2] * srow[mt][1];
                float v3 = acc[mt][nt][3] * srow[mt][1];
                __nv_bfloat162 h0 = __floats2bfloat162_rn(v0, v1);
                __nv_bfloat162 h1 = __floats2bfloat162_rn(v2, v3);
                __nv_bfloat162 l0 = __floats2bfloat162_rn(v0 - __bfloat162float(h0.x), v1 - __bfloat162float(h0.y));
                __nv_bfloat162 l1 = __floats2bfloat162_rn(v2 - __bfloat162float(h1.x), v3 - __bfloat162float(h1.y));
                *(uint32_t*)(Qh + (size_t)row0*DD + col) = *(uint32_t*)&h0;
                *(uint32_t*)(Qh + (size_t)row1*DD + col) = *(uint32_t*)&h1;
                *(uint32_t*)(Ql + (size_t)row0*DD + col) = *(uint32_t*)&l0;
                *(uint32_t*)(Ql + (size_t)row1*DD + col) = *(uint32_t*)&l1;
            }
        }
        return;
    }

    if (mode == 2) {
        // V projection: (acc+bias)*mask -> transposed vT[b][h][l][t] hi/lo
        #pragma unroll
        for (int mt = 0; mt < 2; mt++) {
            int row0 = m0 + wm*32 + mt*16 + t4;
            int row1 = row0 + 8;
            float m0v = mask[row0], m1v = mask[row1];
            int b0 = row0 >> 11, tt0 = row0 & (TT-1);
            int b1 = row1 >> 11, tt1 = row1 & (TT-1);
            #pragma unroll
            for (int nt = 0; nt < 4; nt++) {
                int col = n0 + wn*32 + nt*8 + t2;
                int h = col >> 7, l = col & 127;
                float a0 = acc[mt][nt][0] * m0v;
                float a1 = acc[mt][nt][1] * m0v;
                float a2 = acc[mt][nt][2] * m1v;
                float a3 = acc[mt][nt][3] * m1v;
                size_t i00 = ((size_t)(b0*HH + h)*DHH + l)*TT + tt0;
                size_t i10 = ((size_t)(b1*HH + h)*DHH + l)*TT + tt1;
                __nv_bfloat16 h0 = __float2bfloat16(a0);
                __nv_bfloat16 h1 = __float2bfloat16(a1);
                __nv_bfloat16 h2 = __float2bfloat16(a2);
                __nv_bfloat16 h3 = __float2bfloat16(a3);
                Vh[i00]      = h0;
                Vh[i00 + TT] = h1;
                Vh[i10]      = h2;
                Vh[i10 + TT] = h3;
                Vl[i00]      = __float2bfloat16(a0 - __bfloat162float(h0));
                Vl[i00 + TT] = __float2bfloat16(a1 - __bfloat162float(h1));
                Vl[i10]      = __float2bfloat16(a2 - __bfloat162float(h2));
                Vl[i10 + TT] = __float2bfloat16(a3 - __bfloat162float(h3));
            }
        }
        return;
    }

    #pragma unroll
    for (int mt = 0; mt < 2; mt++) {
        int row0 = m0 + wm*32 + mt*16 + t4;
        int row1 = row0 + 8;
        float m0v = 0.f, m1v = 0.f;
        if (mode == 1) { m0v = mask[row0]; m1v = mask[row1]; }
        float add0 = (mode==1) ? (1.0f-m0v)*(-1000000.0f) : 0.f;
        float add1 = (mode==1) ? (1.0f-m1v)*(-1000000.0f) : 0.f;
        #pragma unroll
        for (int nt = 0; nt < 4; nt++) {
            int col = n0 + wn*32 + nt*8 + t2;
            float a0 = acc[mt][nt][0];
            float a1 = acc[mt][nt][1];
            float a2 = acc[mt][nt][2];
            float a3 = acc[mt][nt][3];
            if (mode == 1) { a0 += add0; a1 += add0; a2 += add1; a3 += add1; }
            else if (mode == 3) {
                float2 r0 = *(const float2*)(resid + (size_t)row0*DD + col);
                float2 r1 = *(const float2*)(resid + (size_t)row1*DD + col);
                a0 += r0.x; a1 += r0.y; a2 += r1.x; a3 += r1.y;
            }
            *(float2*)(C + (size_t)row0*DD + col) = make_float2(a0, a1);
            *(float2*)(C + (size_t)row1*DD + col) = make_float2(a2, a3);
        }
    }
}

// ======================= softmax over time -> transposed bf16 hi/lo =========
__global__ void ksoftmaxT_k(const float* __restrict__ k,
                            __nv_bfloat16* __restrict__ kTh,
                            __nv_bfloat16* __restrict__ kTl)
{
    int b = blockIdx.x >> 5;
    int g = blockIdx.x & 31;
    int tx = threadIdx.x, ty = threadIdx.y;
    int d = g*32 + tx;
    float m = -INFINITY, s = 0.f;
    for (int t=ty; t<TT; t+=8){
        float val = k[((size_t)b*TT + t)*DD + d];
        float nm = fmaxf(m, val);
        s = s*expf(m-nm) + expf(val-nm);
        m = nm;
    }
    __shared__ float smax[8][32], ssum[8][32];
    smax[ty][tx]=m; ssum[ty][tx]=s;
    __syncthreads();
    if (ty==0){
        float M=smax[0][tx], S=ssum[0][tx];
        #pragma unroll
        for (int i=1;i<8;i++){
            float m2=smax[i][tx], s2=ssum[i][tx];
            float nm=fmaxf(M,m2);
            S = S*expf(M-nm) + s2*expf(m2-nm);
            M = nm;
        }
        smax[0][tx]=M; ssum[0][tx]=1.0f/S;
    }
    __syncthreads();
    float M=smax[0][tx], R=ssum[0][tx];
    __syncthreads();

    __shared__ __nv_bfloat16 sh[32][33], sl[32][33];
    int dg0 = g*32;
    int h = dg0 >> 7;
    int dl0 = dg0 & 127;
    size_t kbase = ((size_t)(b*HH + h))*DHH + dl0;

    for (int t0 = 0; t0 < TT; t0 += 32) {
        #pragma unroll
        for (int i = 0; i < 4; i++) {
            int t = t0 + ty + i*8;
            float val = expf(k[((size_t)b*TT + t)*DD + d] - M) * R;
            __nv_bfloat16 hv = __float2bfloat16(val);
            sh[tx][ty + i*8] = hv;
            sl[tx][ty + i*8] = __float2bfloat16(val - __bfloat162float(hv));
        }
        __syncthreads();
        #pragma unroll
        for (int i = 0; i < 4; i++) {
            int row = ty + i*8;
            kTh[(kbase + row)*TT + t0 + tx] = sh[row][tx];
            kTl[(kbase + row)*TT + t0 + tx] = sl[row][tx];
        }
        __syncthreads();
    }
}

// ======================= attention core HMMA ================================
#define LD2    136
#define ATE    (128*LD2)
#define ATT_SMEM (4*ATE*2)

__global__ __launch_bounds__(512, 1) void att1_k(
        const __nv_bfloat16* __restrict__ vTh, const __nv_bfloat16* __restrict__ vTl,
        const __nv_bfloat16* __restrict__ kTh, const __nv_bfloat16* __restrict__ kTl,
        float* __restrict__ part)
{
    extern __shared__ __nv_bfloat16 smbuf[];
    const int tid  = threadIdx.x;
    const int lane = tid & 31;
    const int w    = tid >> 5;
    const int wm   = w >> 2;
    const int wn   = w & 3;
    const int chunk = blockIdx.x;       // 0..7 (256 t each)
    const int bh    = blockIdx.y;

    const uint32_t smb = smem_to_u32(smbuf);
    const int arow  = wm*32 + (lane & 7) + ((lane >> 3) & 1) * 8;
    const int akoff = ((lane >> 4) & 1) * 8;
    const int brow  = wn*32 + (lane & 7) + ((lane >> 4) & 1) * 8;
    const int bkoff = ((lane >> 3) & 1) * 8;

    float acc[2][4][4];
    #pragma unroll
    for (int i=0;i<2;i++)
        #pragma unroll
        for (int j=0;j<4;j++)
            #pragma unroll
            for (int l=0;l<4;l++) acc[i][j][l]=0.f;

    for (int sub = 0; sub < 2; sub++) {
        int t0 = chunk*256 + sub*128;
        #pragma unroll
        for (int i = 0; i < 4; i++) {
            int c = tid + i*512;
            int r = c >> 4;
            int c16 = (c & 15) * 8;
            size_t g = ((size_t)bh*DHH + r)*TT + t0 + c16;
            __nv_bfloat16* d = smbuf + r*LD2 + c16;
            *(uint4*)(d + 0*ATE) = *(const uint4*)(vTh + g);
            *(uint4*)(d + 1*ATE) = *(const uint4*)(vTl + g);
            *(uint4*)(d + 2*ATE) = *(const uint4*)(kTh + g);
            *(uint4*)(d + 3*ATE) = *(const uint4*)(kTl + g);
        }
        __syncthreads();

        #pragma unroll
        for (int ks = 0; ks < 8; ks++) {
            uint32_t ah[2][4], al[2][4];
            #pragma unroll
            for (int mt = 0; mt < 2; mt++) {
                uint32_t ra = smb + ((arow + mt*16)*LD2 + ks*16 + akoff) * 2;
                LDSM4(ah[mt], ra);
                LDSM4(al[mt], ra + ATE*2);
            }
            uint32_t bhf[2][4], blf[2][4];
            #pragma unroll
            for (int nb = 0; nb < 2; nb++) {
                uint32_t rb = smb + 2*ATE*2 + ((brow + nb*16)*LD2 + ks*16 + bkoff) * 2;
                LDSM4(bhf[nb], rb);
                LDSM4(blf[nb], rb + ATE*2);
            }
            #pragma unroll
            for (int mt = 0; mt < 2; mt++)
                #pragma unroll
                for (int nt = 0; nt < 4; nt++) {
                    int nb = nt >> 1, sub2 = (nt & 1) * 2;
                    MMA_BF16(acc[mt][nt], ah[mt], bhf[nb][sub2], bhf[nb][sub2+1]);
                }
            #pragma unroll
            for (int mt = 0; mt < 2; mt++)
                #pragma unroll
                for (int nt = 0; nt < 4; nt++) {
                    int nb = nt >> 1, sub2 = (nt & 1) * 2;
                    MMA_BF16(acc[mt][nt], ah[mt], blf[nb][sub2], blf[nb][sub2+1]);
                }
            #pragma unroll
            for (int mt = 0; mt < 2; mt++)
                #pragma unroll
                for (int nt = 0; nt < 4; nt++) {
                    int nb = nt >> 1, sub2 = (nt & 1) * 2;
                    MMA_BF16(acc[mt][nt], al[mt], bhf[nb][sub2], bhf[nb][sub2+1]);
                }
        }
        __syncthreads();
    }

    float* dst = part + ((size_t)(chunk*(BB*HH) + bh))*(DHH*DHH);
    const int t4 = lane >> 2;
    const int t2 = (lane & 3) * 2;
    #pragma unroll
    for (int mt = 0; mt < 2; mt++) {
        int row0 = wm*32 + mt*16 + t4;
        int row1 = row0 + 8;
        #pragma unroll
        for (int nt = 0; nt < 4; nt++) {
            int col = wn*32 + nt*8 + t2;
            *(float2*)(dst + row0*DHH + col) = make_float2(acc[mt][nt][0], acc[mt][nt][1]);
            *(float2*)(dst + row1*DHH + col) = make_float2(acc[mt][nt][2], acc[mt][nt][3]);
        }
    }
}

__global__ void att_reduce_k(const float* __restrict__ part,
                             __nv_bfloat16* __restrict__ ath,
                             __nv_bfloat16* __restrict__ atl)
{
    int i = blockIdx.x*256 + threadIdx.x;
    float s = 0.f;
    #pragma unroll
    for (int c=0;c<NCHUNK;c++) s += part[(size_t)c*(BB*HH*DHH*DHH) + i];
    __nv_bfloat16 h = __float2bfloat16(s);
    ath[i] = h;
    atl[i] = __float2bfloat16(s - __bfloat162float(h));
}

__global__ __launch_bounds__(512, 1) void att2_k(
        const __nv_bfloat16* __restrict__ qh, const __nv_bfloat16* __restrict__ ql,
        const __nv_bfloat16* __restrict__ ath, const __nv_bfloat16* __restrict__ atl,
        float* __restrict__ y)
{
    extern __shared__ __nv_bfloat16 smbuf[];
    const int tid  = threadIdx.x;
    const int lane = tid & 31;
    const int w    = tid >> 5;
    const int wm   = w >> 2;
    const int wn   = w & 3;
    const int m0 = blockIdx.x * 128;
    const int h  = blockIdx.y;
    const int bh = (m0 >> 11) * HH + h;

    #pragma unroll
    for (int i = 0; i < 4; i++) {
        int c = tid + i*512;
        int r = c >> 4;
        int c16 = (c & 15) * 8;
        size_t ga = (size_t)(m0 + r)*DD + h*DHH + c16;
        size_t gb = ((size_t)bh*DHH + r)*DHH + c16;
        __nv_bfloat16* d = smbuf + r*LD2 + c16;
        *(uint4*)(d + 0*ATE) = *(const uint4*)(qh + ga);
        *(uint4*)(d + 1*ATE) = *(const uint4*)(ql + ga);
        *(uint4*)(d + 2*ATE) = *(const uint4*)(ath + gb);
        *(uint4*)(d + 3*ATE) = *(const uint4*)(atl + gb);
    }
    __syncthreads();

    const uint32_t smb = smem_to_u32(smbuf);
    const int arow  = wm*32 + (lane & 7) + ((lane >> 3) & 1) * 8;
    const int akoff = ((lane >> 4) & 1) * 8;
    const int brow  = wn*32 + (lane & 7) + ((lane >> 4) & 1) * 8;
    const int bkoff = ((lane >> 3) & 1) * 8;

    float acc[2][4][4];
    #pragma unroll
    for (int i=0;i<2;i++)
        #pragma unroll
        for (int j=0;j<4;j++)
            #pragma unroll
            for (int l=0;l<4;l++) acc[i][j][l]=0.f;

    #pragma unroll
    for (int ks = 0; ks < 8; ks++) {
        uint32_t ah[2][4], al[2][4];
        #pragma unroll
        for (int mt = 0; mt < 2; mt++) {
            uint32_t ra = smb + ((arow + mt*16)*LD2 + ks*16 + akoff) * 2;
            LDSM4(ah[mt], ra);
            LDSM4(al[mt], ra + ATE*2);
        }
        uint32_t bhf[2][4], blf[2][4];
        #pragma unroll
        for (int nb = 0; nb < 2; nb++) {
            uint32_t rb = smb + 2*ATE*2 + ((brow + nb*16)*LD2 + ks*16 + bkoff) * 2;
            LDSM4(bhf[nb], rb);
            LDSM4(blf[nb], rb + ATE*2);
        }
        #pragma unroll
        for (int mt = 0; mt < 2; mt++)
            #pragma unroll
            for (int nt = 0; nt < 4; nt++) {
                int nb = nt >> 1, sub = (nt & 1) * 2;
                MMA_BF16(acc[mt][nt], ah[mt], bhf[nb][sub], bhf[nb][sub+1]);
            }
        #pragma unroll
        for (int mt = 0; mt < 2; mt++)
            #pragma unroll
            for (int nt = 0; nt < 4; nt++) {
                int nb = nt >> 1, sub = (nt & 1) * 2;
                MMA_BF16(acc[mt][nt], ah[mt], blf[nb][sub], blf[nb][sub+1]);
            }
        #pragma unroll
        for (int mt = 0; mt < 2; mt++)
            #pragma unroll
            for (int nt = 0; nt < 4; nt++) {
                int nb = nt >> 1, sub = (nt & 1) * 2;
                MMA_BF16(acc[mt][nt], al[mt], bhf[nb][sub], bhf[nb][sub+1]);
            }
    }

    const int t4 = lane >> 2;
    const int t2 = (lane & 3) * 2;
    #pragma unroll
    for (int mt = 0; mt < 2; mt++) {
        int row0 = m0 + wm*32 + mt*16 + t4;
        int row1 = row0 + 8;
        #pragma unroll
        for (int nt = 0; nt < 4; nt++) {
            int col = h*DHH + wn*32 + nt*8 + t2;
            *(float2*)(y + (size_t)row0*DD + col) = make_float2(acc[mt][nt][0], acc[mt][nt][1]);
            *(float2*)(y + (size_t)row1*DD + col) = make_float2(acc[mt][nt][2], acc[mt][nt][3]);
        }
    }
}

// ======================= emb path =======================
__global__ void silu_emb_k(const float* __restrict__ emb, float* __restrict__ out)
{
    int i = blockIdx.x*256 + threadIdx.x;
    float e = emb[i];
    out[i] = e / (1.0f + expf(-e));
}

__global__ __launch_bounds__(256) void emb_gemm_k(const float* __restrict__ ea,
                                                  const float* __restrict__ W,
                                                  const float* __restrict__ bias,
                                                  float* __restrict__ out)
{
    int n = blockIdx.x*256 + threadIdx.x;
    int b = blockIdx.y;
    const float* e = ea + b*TEE;
    float acc = 0.f;
    #pragma unroll 8
    for (int t=0;t<TEE;t++)
        acc = fmaf(e[t], W[(size_t)t*(2*DD) + n], acc);
    out[b*(2*DD) + n] = acc + bias[n];
}

// ======================= LN2 + FiLM + SiLU -> bf16 hi/lo =======================
__global__ __launch_bounds__(256) void film_k(const float* __restrict__ y,
                                              const float* __restrict__ w2,
                                              const float* __restrict__ b2,
                                              const float* __restrict__ embout,
                                              __nv_bfloat16* __restrict__ acth,
                                              __nv_bfloat16* __restrict__ actl)
{
    int row = blockIdx.x;
    int b = row / TT;
    int tid = threadIdx.x;
    const float4* yr = (const float4*)(y + (size_t)row*DD);
    float4 v = yr[tid];
    float s  = v.x+v.y+v.z+v.w;
    float ss = v.x*v.x+v.y*v.y+v.z*v.z+v.w*v.w;
    #pragma unroll
    for (int o=16;o>0;o>>=1){ s += __shfl_down_sync(0xffffffffu,s,o); ss += __shfl_down_sync(0xffffffffu,ss,o); }
    __shared__ float sm[8], sm2[8];
    int wid = tid>>5, lane = tid&31;
    if (lane==0){ sm[wid]=s; sm2[wid]=ss; }
    __syncthreads();
    if (tid==0){
        float a=0.f, c=0.f;
        #pragma unroll
        for (int i=0;i<8;i++){ a+=sm[i]; c+=sm2[i]; }
        float mean = a*(1.0f/DD);
        float var  = c*(1.0f/DD) - mean*mean;
        sm[0]=mean; sm2[0]=rsqrtf(var+1e-5f);
    }
    __syncthreads();
    float mean=sm[0], rinv=sm2[0];
    float4 wv=((const float4*)w2)[tid];
    float4 bv=((const float4*)b2)[tid];
    float4 sc=((const float4*)(embout + (size_t)b*(2*DD)))[tid];
    float4 sh=((const float4*)(embout + (size_t)b*(2*DD) + DD))[tid];
    float4 o;
    float h;
    h=(v.x-mean)*rinv*wv.x+bv.x; h=h*(1.0f+sc.x)+sh.x; o.x=h/(1.0f+expf(-h));
    h=(v.y-mean)*rinv*wv.y+bv.y; h=h*(1.0f+sc.y)+sh.y; o.y=h/(1.0f+expf(-h));
    h=(v.z-mean)*rinv*wv.z+bv.z; h=h*(1.0f+sc.z)+sh.z; o.z=h/(1.0f+expf(-h));
    h=(v.w-mean)*rinv*wv.w+bv.w; h=h*(1.0f+sc.w)+sh.w; o.w=h/(1.0f+expf(-h));
    split_store4(acth + (size_t)row*DD + tid*4, actl + (size_t)row*DD + tid*4, o);
}

// ======================= launch =======================
extern "C" void kernel_launch(void* const* d_in, const int* in_sizes, int n_in,
                              void* d_out, int out_size)
{
    (void)in_sizes; (void)n_in; (void)out_size;
    const float* x     = (const float*)d_in[0];
    const float* emb   = (const float*)d_in[1];
    const float* mask  = (const float*)d_in[2];
    const float* ln_w  = (const float*)d_in[4];
    const float* ln_b  = (const float*)d_in[5];
    const float* Wq    = (const float*)d_in[6];
    const float* bq    = (const float*)d_in[7];
    const float* Wk    = (const float*)d_in[8];
    const float* bk    = (const float*)d_in[9];
    const float* Wv    = (const float*)d_in[10];
    const float* bv    = (const float*)d_in[11];
    const float* W_emb = (const float*)d_in[12];
    const float* b_emb = (const float*)d_in[13];
    const float* ln2_w = (const float*)d_in[14];
    const float* ln2_b = (const float*)d_in[15];
    const float* W_out = (const float*)d_in[16];
    const float* b_out = (const float*)d_in[17];
    float* out = (float*)d_out;

    __nv_bfloat16 *p_xnh, *p_xnl, *p_acth, *p_actl, *p_wth, *p_wtl;
    __nv_bfloat16 *p_qh, *p_ql, *p_kTh, *p_kTl, *p_vTh, *p_vTl, *p_ath, *p_atl;
    float *p_k, *p_y, *p_attp, *p_emba, *p_embout;
    cudaGetSymbolAddress((void**)&p_xnh,    g_xnhi);
    cudaGetSymbolAddress((void**)&p_xnl,    g_xnlo);
    cudaGetSymbolAddress((void**)&p_acth,   g_acthi);
    cudaGetSymbolAddress((void**)&p_actl,   g_actlo);
    cudaGetSymbolAddress((void**)&p_wth,    g_wthi);
    cudaGetSymbolAddress((void**)&p_wtl,    g_wtlo);
    cudaGetSymbolAddress((void**)&p_k,      g_k);
    cudaGetSymbolAddress((void**)&p_y,      g_y);
    cudaGetSymbolAddress((void**)&p_qh,     g_qhi);
    cudaGetSymbolAddress((void**)&p_ql,     g_qlo);
    cudaGetSymbolAddress((void**)&p_kTh,    g_kThi);
    cudaGetSymbolAddress((void**)&p_kTl,    g_kTlo);
    cudaGetSymbolAddress((void**)&p_vTh,    g_vThi);
    cudaGetSymbolAddress((void**)&p_vTl,    g_vTlo);
    cudaGetSymbolAddress((void**)&p_ath,    g_attThi);
    cudaGetSymbolAddress((void**)&p_atl,    g_attTlo);
    cudaGetSymbolAddress((void**)&p_attp,   g_att_part);
    cudaGetSymbolAddress((void**)&p_emba,   g_emb_act);
    cudaGetSymbolAddress((void**)&p_embout, g_embout);

    cudaFuncSetAttribute(hgemm_k, cudaFuncAttributeMaxDynamicSharedMemorySize, HG_SMEM);
    cudaFuncSetAttribute(att1_k,  cudaFuncAttributeMaxDynamicSharedMemorySize, ATT_SMEM);
    cudaFuncSetAttribute(att2_k,  cudaFuncAttributeMaxDynamicSharedMemorySize, ATT_SMEM);

    wsplit4_k<<<dim3(32,32,4), dim3(32,32)>>>(Wq, Wk, Wv, W_out, p_wth, p_wtl);
    ln_kernel<<<MM, 256>>>(x, ln_w, ln_b, p_xnh, p_xnl);
    silu_emb_k<<<(BB*TEE)/256, 256>>>(emb, p_emba);

    // QKV fused: grid.z = 3 selects weight slice + epilogue
    hgemm_k<<<dim3(DD/128, MM/64, 3), 256, HG_SMEM>>>(
        p_xnh, p_xnl, p_wth, p_wtl,
        bq, bk, bv, mask, nullptr, p_k, p_qh, p_ql, p_vTh, p_vTl, -1);

    ksoftmaxT_k<<<BB*32, dim3(32,8)>>>(p_k, p_kTh, p_kTl);

    att1_k<<<dim3(NCHUNK, BB*HH), 512, ATT_SMEM>>>(p_vTh, p_vTl, p_kTh, p_kTl, p_attp);
    att_reduce_k<<<(BB*HH*DHH*DHH)/256, 256>>>(p_attp, p_ath, p_atl);

    emb_gemm_k<<<dim3((2*DD)/256, BB), 256>>>(p_emba, W_emb, b_emb, p_embout);

    att2_k<<<dim3(MM/128, HH), 512, ATT_SMEM>>>(p_qh, p_ql, p_ath, p_atl, p_y);

    film_k<<<MM, 256>>>(p_y, ln2_w, ln2_b, p_embout, p_acth, p_actl);

    // OUT projection (+residual)
    hgemm_k<<<dim3(DD/128, MM/64, 1), 256, HG_SMEM>>>(
        p_acth, p_actl, p_wth + 3*(size_t)DD*DD, p_wtl + 3*(size_t)DD*DD,
        b_out, nullptr, nullptr, nullptr, x, out, nullptr, nullptr, nullptr, nullptr, 3);
}

// round 13
// speedup vs baseline: 1.4042x; 1.2095x over previous
#include <cuda_runtime.h>
#include <cuda_bf16.h>
#include <math.h>
#include <stdint.h>

#define BB 4
#define TT 2048
#define DD 1024
#define HH 8
#define DHH 128
#define TEE 2048
#define MM (BB*TT)          // 8192 rows
#define NCHUNK 8            // att1 t-chunks (256 t per block)

__device__ __forceinline__ uint32_t smem_to_u32(const void* p) {
    uint32_t a;
    asm("{ .reg .u64 t; cvta.to.shared.u64 t, %1; cvt.u32.u64 %0, t; }" : "=r"(a) : "l"(p));
    return a;
}
__device__ __forceinline__ float to_tf32(float v) {
    uint32_t u;
    asm("cvt.rna.tf32.f32 %0, %1;" : "=r"(u) : "f"(v));
    return __uint_as_float(u);
}

#define LDSM4(R, addr) \
    asm volatile("ldmatrix.sync.aligned.m8n8.x4.shared.b16 {%0,%1,%2,%3}, [%4];" \
        : "=r"((R)[0]), "=r"((R)[1]), "=r"((R)[2]), "=r"((R)[3]) : "r"(addr))

#define MMA_BF16(c, a, b0, b1) \
    asm volatile("mma.sync.aligned.m16n8k16.row.col.f32.bf16.bf16.f32 " \
        "{%0,%1,%2,%3}, {%4,%5,%6,%7}, {%8,%9}, {%0,%1,%2,%3};" \
        : "+f"((c)[0]), "+f"((c)[1]), "+f"((c)[2]), "+f"((c)[3]) \
        : "r"((a)[0]), "r"((a)[1]), "r"((a)[2]), "r"((a)[3]), "r"(b0), "r"(b1))

#define MMA_TF32(c, a, b0, b1) \
    asm volatile("mma.sync.aligned.m16n8k8.row.col.f32.tf32.tf32.f32 " \
        "{%0,%1,%2,%3}, {%4,%5,%6,%7}, {%8,%9}, {%0,%1,%2,%3};" \
        : "+f"((c)[0]), "+f"((c)[1]), "+f"((c)[2]), "+f"((c)[3]) \
        : "r"((a)[0]), "r"((a)[1]), "r"((a)[2]), "r"((a)[3]), "r"(b0), "r"(b1))

#define CP16(dst, src) \
    asm volatile("cp.async.cg.shared.global [%0], [%1], 16;" :: "r"(dst), "l"(src))
#define CP_COMMIT() asm volatile("cp.async.commit_group;")
#define CP_WAIT1()  asm volatile("cp.async.wait_group 1;")

// ======================= device scratch =======================
__device__ float g_xn [MM*DD];          // tf32-rounded LN output
__device__ float g_act[MM*DD];          // tf32-rounded FiLM output
__device__ float g_wt [4][DD*DD];       // tf32-rounded transposed weights
__device__ float g_k  [MM*DD];
__device__ float g_y  [MM*DD];
__device__ __nv_bfloat16 g_qhi[MM*DD];
__device__ __nv_bfloat16 g_qlo[MM*DD];
__device__ __nv_bfloat16 g_kThi[MM*DD];
__device__ __nv_bfloat16 g_kTlo[MM*DD];
__device__ __nv_bfloat16 g_vThi[MM*DD];
__device__ __nv_bfloat16 g_vTlo[MM*DD];
__device__ float g_att_part[NCHUNK*BB*HH*DHH*DHH];
__device__ __nv_bfloat16 g_attThi[BB*HH*DHH*DHH];
__device__ __nv_bfloat16 g_attTlo[BB*HH*DHH*DHH];
__device__ float g_emb_act[BB*TEE];
__device__ float g_embout[BB*2*DD];

// ======================= LayerNorm -> tf32 fp32 =======================
__global__ __launch_bounds__(256) void ln_kernel(const float* __restrict__ x,
                                                 const float* __restrict__ w,
                                                 const float* __restrict__ b,
                                                 float* __restrict__ outx)
{
    int row = blockIdx.x;
    int tid = threadIdx.x;
    const float4* xr = (const float4*)(x + (size_t)row*DD);
    float4 v = xr[tid];
    float s  = v.x+v.y+v.z+v.w;
    float ss = v.x*v.x+v.y*v.y+v.z*v.z+v.w*v.w;
    #pragma unroll
    for (int o=16;o>0;o>>=1){ s += __shfl_down_sync(0xffffffffu,s,o); ss += __shfl_down_sync(0xffffffffu,ss,o); }
    __shared__ float sm[8], sm2[8];
    int wid = tid>>5, lane = tid&31;
    if (lane==0){ sm[wid]=s; sm2[wid]=ss; }
    __syncthreads();
    if (tid==0){
        float a=0.f, c=0.f;
        #pragma unroll
        for (int i=0;i<8;i++){ a+=sm[i]; c+=sm2[i]; }
        float mean = a*(1.0f/DD);
        float var  = c*(1.0f/DD) - mean*mean;
        sm[0]=mean; sm2[0]=rsqrtf(var+1e-5f);
    }
    __syncthreads();
    float mean=sm[0], rinv=sm2[0];
    float4 wv=((const float4*)w)[tid];
    float4 bv=((const float4*)b)[tid];
    float4 o;
    o.x=to_tf32((v.x-mean)*rinv*wv.x+bv.x);
    o.y=to_tf32((v.y-mean)*rinv*wv.y+bv.y);
    o.z=to_tf32((v.z-mean)*rinv*wv.z+bv.z);
    o.w=to_tf32((v.w-mean)*rinv*wv.w+bv.w);
    ((float4*)(outx + (size_t)row*DD))[tid]=o;
}

// ======================= weight transpose -> tf32 fp32 ======================
__global__ __launch_bounds__(1024) void wsplit4_k(const float* __restrict__ W0,
                                                  const float* __restrict__ W1,
                                                  const float* __restrict__ W2,
                                                  const float* __restrict__ W3,
                                                  float* __restrict__ Wt)
{
    __shared__ float t[32][33];
    int tx = threadIdx.x, ty = threadIdx.y;
    int wsel = blockIdx.z;
    const float* W = (wsel==0)?W0:(wsel==1)?W1:(wsel==2)?W2:W3;
    t[ty][tx] = W[(size_t)(blockIdx.y*32+ty)*DD + blockIdx.x*32+tx];
    __syncthreads();
    int n = blockIdx.x*32 + ty;
    int k = blockIdx.y*32 + tx;
    Wt[(size_t)wsel*DD*DD + (size_t)n*DD + k] = to_tf32(t[tx][ty]);
}

// ======================= TF32 GEMM, BM=64 BN=128, 4 warps, 2 CTAs/SM ========
// smem row stride: 36 floats = 144 B (16B-aligned, conflict-free ldmatrix)
#define LDSB    144                       // smem row stride in BYTES
#define TA_B    (64*LDSB)                 // 9216 B (A tile)
#define TB_B    (128*LDSB)                // 18432 B (B tile)
#define STAGE_B (TA_B + TB_B)             // 27648 B per stage
#define HG_SMEM (3*STAGE_B)               // 82944 B

__global__ __launch_bounds__(128, 2) void hgemm_k(
        const float* __restrict__ A,
        const float* __restrict__ Wt,
        const float* __restrict__ bias0, const float* __restrict__ bias1,
        const float* __restrict__ bias2,
        const float* __restrict__ mask,
        const float* __restrict__ resid, float* __restrict__ C,
        __nv_bfloat16* __restrict__ Qh, __nv_bfloat16* __restrict__ Ql,
        __nv_bfloat16* __restrict__ Vh, __nv_bfloat16* __restrict__ Vl,
        int mode_ov)
{
    extern __shared__ float smbuf[];
    const int tid  = threadIdx.x;
    const int lane = tid & 31;
    const int w    = tid >> 5;      // 0..3
    const int wm   = w >> 1;        // 0..1 : 32 rows
    const int wn   = w & 1;         // 0..1 : 64 cols
    const int m0 = blockIdx.y * 64;
    const int n0 = blockIdx.x * 128;
    const int mode = (mode_ov >= 0) ? mode_ov : (int)blockIdx.z;
    const int wsel = (mode_ov >= 0) ? 0 : (int)blockIdx.z;
    const float* bias = (mode == 1) ? bias1 : (mode == 2) ? bias2 : bias0;
    const float* B = Wt + (size_t)wsel*DD*DD;

    const uint32_t smb = smem_to_u32(smbuf);
    const uint32_t dA = smb;
    const uint32_t dB = smb + TA_B;

    const int arow = wm*32 + (lane & 7) + ((lane >> 3) & 1) * 8;     // +mt*16
    const int akb  = ((lane >> 4) & 1) * 16;
    const int brow = wn*64 + ((lane >> 4) & 1) * 8 + (lane & 7);     // +nb*16
    const int bkb  = ((lane >> 3) & 1) * 16;

    float acc[2][8][4];
    #pragma unroll
    for (int i=0;i<2;i++)
        #pragma unroll
        for (int j=0;j<8;j++)
            #pragma unroll
            for (int l=0;l<4;l++) acc[i][j][l]=0.f;

    // prologue stages 0,1
    #pragma unroll
    for (int s = 0; s < 2; s++) {
        int k0 = s*32;
        uint32_t so = s*STAGE_B;
        #pragma unroll
        for (int i = 0; i < 4; i++) {
            int idx = tid + i*128;      // 0..511
            int r = idx >> 3, ch = idx & 7;
            CP16(dA + so + (uint32_t)(r*LDSB + ch*16), A + (size_t)(m0+r)*DD + k0 + ch*4);
        }
        #pragma unroll
        for (int i = 0; i < 8; i++) {
            int idx = tid + i*128;      // 0..1023
            int r = idx >> 3, ch = idx & 7;
            CP16(dB + so + (uint32_t)(r*LDSB + ch*16), B + (size_t)(n0+r)*DD + k0 + ch*4);
        }
        CP_COMMIT();
    }

    int st_r = 0, st_w = 2;
    for (int kc = 0; kc < 32; kc++) {
        CP_WAIT1();
        __syncthreads();
        if (kc + 2 < 32) {
            int k0 = (kc+2)*32;
            uint32_t so = st_w*STAGE_B;
            #pragma unroll
            for (int i = 0; i < 4; i++) {
                int idx = tid + i*128;
                int r = idx >> 3, ch = idx & 7;
                CP16(dA + so + (uint32_t)(r*LDSB + ch*16), A + (size_t)(m0+r)*DD + k0 + ch*4);
            }
            #pragma unroll
            for (int i = 0; i < 8; i++) {
                int idx = tid + i*128;
                int r = idx >> 3, ch = idx & 7;
                CP16(dB + so + (uint32_t)(r*LDSB + ch*16), B + (size_t)(n0+r)*DD + k0 + ch*4);
            }
        }
        CP_COMMIT();

        uint32_t baseA = smb + st_r*STAGE_B;
        uint32_t baseB = baseA + TA_B;
        #pragma unroll
        for (int ks = 0; ks < 4; ks++) {        // 4 k8-steps per 32-chunk
            uint32_t a[2][4];
            #pragma unroll
            for (int mt = 0; mt < 2; mt++) {
                uint32_t ra = baseA + (uint32_t)((arow + mt*16)*LDSB + akb + ks*32);
                LDSM4(a[mt], ra);
            }
            uint32_t bf[4][4];
            #pragma unroll
            for (int nb = 0; nb < 4; nb++) {
                uint32_t rb = baseB + (uint32_t)((brow + nb*16)*LDSB + bkb + ks*32);
                LDSM4(bf[nb], rb);
            }
            #pragma unroll
            for (int mt = 0; mt < 2; mt++)
                #pragma unroll
                for (int nb = 0; nb < 4; nb++) {
                    MMA_TF32(acc[mt][nb*2],   a[mt], bf[nb][0], bf[nb][1]);
                    MMA_TF32(acc[mt][nb*2+1], a[mt], bf[nb][2], bf[nb][3]);
                }
        }
        if (++st_r == 3) st_r = 0;
        if (++st_w == 3) st_w = 0;
    }

    const int t4 = lane >> 2;
    const int t2 = (lane & 3) * 2;

    #pragma unroll
    for (int mt = 0; mt < 2; mt++)
        #pragma unroll
        for (int nt = 0; nt < 8; nt++) {
            int col = n0 + wn*64 + nt*8 + t2;
            float2 bi = *(const float2*)(bias + col);
            acc[mt][nt][0] += bi.x; acc[mt][nt][1] += bi.y;
            acc[mt][nt][2] += bi.x; acc[mt][nt][3] += bi.y;
        }

    if (mode == 0) {
        // fused softmax over 128 cols (one head), 64 rows; 2 col-warps
        __syncthreads();
        float* red  = smbuf;            // [64][2]
        float* red2 = smbuf + 128;
        float mrow[2][2];
        #pragma unroll
        for (int mt = 0; mt < 2; mt++) {
            float a0 = -1e30f, a1 = -1e30f;
            #pragma unroll
            for (int nt = 0; nt < 8; nt++) {
                a0 = fmaxf(a0, fmaxf(acc[mt][nt][0], acc[mt][nt][1]));
                a1 = fmaxf(a1, fmaxf(acc[mt][nt][2], acc[mt][nt][3]));
            }
            a0 = fmaxf(a0, __shfl_xor_sync(0xffffffffu, a0, 1));
            a0 = fmaxf(a0, __shfl_xor_sync(0xffffffffu, a0, 2));
            a1 = fmaxf(a1, __shfl_xor_sync(0xffffffffu, a1, 1));
            a1 = fmaxf(a1, __shfl_xor_sync(0xffffffffu, a1, 2));
            if ((lane & 3) == 0) {
                int r = wm*32 + mt*16 + t4;
                red[r*2 + wn] = a0;
                red[(r+8)*2 + wn] = a1;
            }
        }
        __syncthreads();
        #pragma unroll
        for (int mt = 0; mt < 2; mt++) {
            int r = wm*32 + mt*16 + t4;
            mrow[mt][0] = fmaxf(red[r*2+0], red[r*2+1]);
            mrow[mt][1] = fmaxf(red[(r+8)*2+0], red[(r+8)*2+1]);
        }
        float srow[2][2];
        #pragma unroll
        for (int mt = 0; mt < 2; mt++) {
            float s0 = 0.f, s1 = 0.f;
            #pragma unroll
            for (int nt = 0; nt < 8; nt++) {
                acc[mt][nt][0] = expf(acc[mt][nt][0] - mrow[mt][0]);
                acc[mt][nt][1] = expf(acc[mt][nt][1] - mrow[mt][0]);
                acc[mt][nt][2] = expf(acc[mt][nt][2] - mrow[mt][1]);
                acc[mt][nt][3] = expf(acc[mt][nt][3] - mrow[mt][1]);
                s0 += acc[mt][nt][0] + acc[mt][nt][1];
                s1 += acc[mt][nt][2] + acc[mt][nt][3];
            }
            s0 += __shfl_xor_sync(0xffffffffu, s0, 1);
            s0 += __shfl_xor_sync(0xffffffffu, s0, 2);
            s1 += __shfl_xor_sync(0xffffffffu, s1, 1);
            s1 += __shfl_xor_sync(0xffffffffu, s1, 2);
            if ((lane & 3) == 0) {
                int r = wm*32 + mt*16 + t4;
                red2[r*2 + wn] = s0;
                red2[(r+8)*2 + wn] = s1;
            }
        }
        __syncthreads();
        #pragma unroll
        for (int mt = 0; mt < 2; mt++) {
            int r = wm*32 + mt*16 + t4;
            srow[mt][0] = 1.0f / (red2[r*2+0] + red2[r*2+1]);
            srow[mt][1] = 1.0f / (red2[(r+8)*2+0] + red2[(r+8)*2+1]);
        }
        #pragma unroll
        for (int mt = 0; mt < 2; mt++) {
            int row0 = m0 + wm*32 + mt*16 + t4;
            int row1 = row0 + 8;
            #pragma unroll
            for (int nt = 0; nt < 8; nt++) {
                int col = n0 + wn*64 + nt*8 + t2;
                float v0 = acc[mt][nt][0] * srow[mt][0];
                float v1 = acc[mt][nt][1] * srow[mt][0];
                float v2 = acc[mt][nt][2] * srow[mt][1];
                float v3 = acc[mt][nt][3] * srow[mt][1];
                __nv_bfloat162 h0 = __floats2bfloat162_rn(v0, v1);
                __nv_bfloat162 h1 = __floats2bfloat162_rn(v2, v3);
                __nv_bfloat162 l0 = __floats2bfloat162_rn(v0 - __bfloat162float(h0.x), v1 - __bfloat162float(h0.y));
                __nv_bfloat162 l1 = __floats2bfloat162_rn(v2 - __bfloat162float(h1.x), v3 - __bfloat162float(h1.y));
                *(uint32_t*)(Qh + (size_t)row0*DD + col) = *(uint32_t*)&h0;
                *(uint32_t*)(Qh + (size_t)row1*DD + col) = *(uint32_t*)&h1;
                *(uint32_t*)(Ql + (size_t)row0*DD + col) = *(uint32_t*)&l0;
                *(uint32_t*)(Ql + (size_t)row1*DD + col) = *(uint32_t*)&l1;
            }
        }
        return;
    }

    if (mode == 2) {
        // V projection: (acc+bias)*mask -> transposed vT[b][h][l][t] hi/lo
        #pragma unroll
        for (int mt = 0; mt < 2; mt++) {
            int row0 = m0 + wm*32 + mt*16 + t4;
            int row1 = row0 + 8;
            float m0v = mask[row0], m1v = mask[row1];
            int b0 = row0 >> 11, tt0 = row0 & (TT-1);
            int b1 = row1 >> 11, tt1 = row1 & (TT-1);
            #pragma unroll
            for (int nt = 0; nt < 8; nt++) {
                int col = n0 + wn*64 + nt*8 + t2;
                int h = col >> 7, l = col & 127;
                float a0 = acc[mt][nt][0] * m0v;
                float a1 = acc[mt][nt][1] * m0v;
                float a2 = acc[mt][nt][2] * m1v;
                float a3 = acc[mt][nt][3] * m1v;
                size_t i00 = ((size_t)(b0*HH + h)*DHH + l)*TT + tt0;
                size_t i10 = ((size_t)(b1*HH + h)*DHH + l)*TT + tt1;
                __nv_bfloat16 h0 = __float2bfloat16(a0);
                __nv_bfloat16 h1 = __float2bfloat16(a1);
                __nv_bfloat16 h2 = __float2bfloat16(a2);
                __nv_bfloat16 h3 = __float2bfloat16(a3);
                Vh[i00]      = h0;
                Vh[i00 + TT] = h1;
                Vh[i10]      = h2;
                Vh[i10 + TT] = h3;
                Vl[i00]      = __float2bfloat16(a0 - __bfloat162float(h0));
                Vl[i00 + TT] = __float2bfloat16(a1 - __bfloat162float(h1));
                Vl[i10]      = __float2bfloat16(a2 - __bfloat162float(h2));
                Vl[i10 + TT] = __float2bfloat16(a3 - __bfloat162float(h3));
            }
        }
        return;
    }

    #pragma unroll
    for (int mt = 0; mt < 2; mt++) {
        int row0 = m0 + wm*32 + mt*16 + t4;
        int row1 = row0 + 8;
        float m0v = 0.f, m1v = 0.f;
        if (mode == 1) { m0v = mask[row0]; m1v = mask[row1]; }
        float add0 = (mode==1) ? (1.0f-m0v)*(-1000000.0f) : 0.f;
        float add1 = (mode==1) ? (1.0f-m1v)*(-1000000.0f) : 0.f;
        #pragma unroll
        for (int nt = 0; nt < 8; nt++) {
            int col = n0 + wn*64 + nt*8 + t2;
            float a0 = acc[mt][nt][0];
            float a1 = acc[mt][nt][1];
            float a2 = acc[mt][nt][2];
            float a3 = acc[mt][nt][3];
            if (mode == 1) { a0 += add0; a1 += add0; a2 += add1; a3 += add1; }
            else if (mode == 3) {
                float2 r0 = *(const float2*)(resid + (size_t)row0*DD + col);
                float2 r1 = *(const float2*)(resid + (size_t)row1*DD + col);
                a0 += r0.x; a1 += r0.y; a2 += r1.x; a3 += r1.y;
            }
            *(float2*)(C + (size_t)row0*DD + col) = make_float2(a0, a1);
            *(float2*)(C + (size_t)row1*DD + col) = make_float2(a2, a3);
        }
    }
}

// ======================= softmax over time -> transposed bf16 hi/lo =========
__global__ void ksoftmaxT_k(const float* __restrict__ k,
                            __nv_bfloat16* __restrict__ kTh,
                            __nv_bfloat16* __restrict__ kTl)
{
    int b = blockIdx.x >> 5;
    int g = blockIdx.x & 31;
    int tx = threadIdx.x, ty = threadIdx.y;
    int d = g*32 + tx;
    float m = -INFINITY, s = 0.f;
    for (int t=ty; t<TT; t+=8){
        float val = k[((size_t)b*TT + t)*DD + d];
        float nm = fmaxf(m, val);
        s = s*expf(m-nm) + expf(val-nm);
        m = nm;
    }
    __shared__ float smax[8][32], ssum[8][32];
    smax[ty][tx]=m; ssum[ty][tx]=s;
    __syncthreads();
    if (ty==0){
        float M=smax[0][tx], S=ssum[0][tx];
        #pragma unroll
        for (int i=1;i<8;i++){
            float m2=smax[i][tx], s2=ssum[i][tx];
            float nm=fmaxf(M,m2);
            S = S*expf(M-nm) + s2*expf(m2-nm);
            M = nm;
        }
        smax[0][tx]=M; ssum[0][tx]=1.0f/S;
    }
    __syncthreads();
    float M=smax[0][tx], R=ssum[0][tx];
    __syncthreads();

    __shared__ __nv_bfloat16 sh[32][33], sl[32][33];
    int dg0 = g*32;
    int h = dg0 >> 7;
    int dl0 = dg0 & 127;
    size_t kbase = ((size_t)(b*HH + h))*DHH + dl0;

    for (int t0 = 0; t0 < TT; t0 += 32) {
        #pragma unroll
        for (int i = 0; i < 4; i++) {
            int t = t0 + ty + i*8;
            float val = expf(k[((size_t)b*TT + t)*DD + d] - M) * R;
            __nv_bfloat16 hv = __float2bfloat16(val);
            sh[tx][ty + i*8] = hv;
            sl[tx][ty + i*8] = __float2bfloat16(val - __bfloat162float(hv));
        }
        __syncthreads();
        #pragma unroll
        for (int i = 0; i < 4; i++) {
            int row = ty + i*8;
            kTh[(kbase + row)*TT + t0 + tx] = sh[row][tx];
            kTl[(kbase + row)*TT + t0 + tx] = sl[row][tx];
        }
        __syncthreads();
    }
}

// ======================= attention core HMMA ================================
#define LD2    136
#define ATE    (128*LD2)
#define ATT_SMEM (4*ATE*2)

__global__ __launch_bounds__(512, 1) void att1_k(
        const __nv_bfloat16* __restrict__ vTh, const __nv_bfloat16* __restrict__ vTl,
        const __nv_bfloat16* __restrict__ kTh, const __nv_bfloat16* __restrict__ kTl,
        float* __restrict__ part)
{
    extern __shared__ __nv_bfloat16 smbufh[];
    const int tid  = threadIdx.x;
    const int lane = tid & 31;
    const int w    = tid >> 5;
    const int wm   = w >> 2;
    const int wn   = w & 3;
    const int chunk = blockIdx.x;       // 0..7 (256 t each)
    const int bh    = blockIdx.y;

    const uint32_t smb = smem_to_u32(smbufh);
    const int arow  = wm*32 + (lane & 7) + ((lane >> 3) & 1) * 8;
    const int akoff = ((lane >> 4) & 1) * 8;
    const int brow  = wn*32 + (lane & 7) + ((lane >> 4) & 1) * 8;
    const int bkoff = ((lane >> 3) & 1) * 8;

    float acc[2][4][4];
    #pragma unroll
    for (int i=0;i<2;i++)
        #pragma unroll
        for (int j=0;j<4;j++)
            #pragma unroll
            for (int l=0;l<4;l++) acc[i][j][l]=0.f;

    for (int sub = 0; sub < 2; sub++) {
        int t0 = chunk*256 + sub*128;
        #pragma unroll
        for (int i = 0; i < 4; i++) {
            int c = tid + i*512;
            int r = c >> 4;
            int c16 = (c & 15) * 8;
            size_t g = ((size_t)bh*DHH + r)*TT + t0 + c16;
            __nv_bfloat16* d = smbufh + r*LD2 + c16;
            *(uint4*)(d + 0*ATE) = *(const uint4*)(vTh + g);
            *(uint4*)(d + 1*ATE) = *(const uint4*)(vTl + g);
            *(uint4*)(d + 2*ATE) = *(const uint4*)(kTh + g);
            *(uint4*)(d + 3*ATE) = *(const uint4*)(kTl + g);
        }
        __syncthreads();

        #pragma unroll
        for (int ks = 0; ks < 8; ks++) {
            uint32_t ah[2][4], al[2][4];
            #pragma unroll
            for (int mt = 0; mt < 2; mt++) {
                uint32_t ra = smb + ((arow + mt*16)*LD2 + ks*16 + akoff) * 2;
                LDSM4(ah[mt], ra);
                LDSM4(al[mt], ra + ATE*2);
            }
            uint32_t bhf[2][4], blf[2][4];
            #pragma unroll
            for (int nb = 0; nb < 2; nb++) {
                uint32_t rb = smb + 2*ATE*2 + ((brow + nb*16)*LD2 + ks*16 + bkoff) * 2;
                LDSM4(bhf[nb], rb);
                LDSM4(blf[nb], rb + ATE*2);
            }
            #pragma unroll
            for (int mt = 0; mt < 2; mt++)
                #pragma unroll
                for (int nt = 0; nt < 4; nt++) {
                    int nb = nt >> 1, sub2 = (nt & 1) * 2;
                    MMA_BF16(acc[mt][nt], ah[mt], bhf[nb][sub2], bhf[nb][sub2+1]);
                }
            #pragma unroll
            for (int mt = 0; mt < 2; mt++)
                #pragma unroll
                for (int nt = 0; nt < 4; nt++) {
                    int nb = nt >> 1, sub2 = (nt & 1) * 2;
                    MMA_BF16(acc[mt][nt], ah[mt], blf[nb][sub2], blf[nb][sub2+1]);
                }
            #pragma unroll
            for (int mt = 0; mt < 2; mt++)
                #pragma unroll
                for (int nt = 0; nt < 4; nt++) {
                    int nb = nt >> 1, sub2 = (nt & 1) * 2;
                    MMA_BF16(acc[mt][nt], al[mt], bhf[nb][sub2], bhf[nb][sub2+1]);
                }
        }
        __syncthreads();
    }

    float* dst = part + ((size_t)(chunk*(BB*HH) + bh))*(DHH*DHH);
    const int t4 = lane >> 2;
    const int t2 = (lane & 3) * 2;
    #pragma unroll
    for (int mt = 0; mt < 2; mt++) {
        int row0 = wm*32 + mt*16 + t4;
        int row1 = row0 + 8;
        #pragma unroll
        for (int nt = 0; nt < 4; nt++) {
            int col = wn*32 + nt*8 + t2;
            *(float2*)(dst + row0*DHH + col) = make_float2(acc[mt][nt][0], acc[mt][nt][1]);
            *(float2*)(dst + row1*DHH + col) = make_float2(acc[mt][nt][2], acc[mt][nt][3]);
        }
    }
}

__global__ void att_reduce_k(const float* __restrict__ part,
                             __nv_bfloat16* __restrict__ ath,
                             __nv_bfloat16* __restrict__ atl)
{
    int i = blockIdx.x*256 + threadIdx.x;
    float s = 0.f;
    #pragma unroll
    for (int c=0;c<NCHUNK;c++) s += part[(size_t)c*(BB*HH*DHH*DHH) + i];
    __nv_bfloat16 h = __float2bfloat16(s);
    ath[i] = h;
    atl[i] = __float2bfloat16(s - __bfloat162float(h));
}

__global__ __launch_bounds__(512, 1) void att2_k(
        const __nv_bfloat16* __restrict__ qh, const __nv_bfloat16* __restrict__ ql,
        const __nv_bfloat16* __restrict__ ath, const __nv_bfloat16* __restrict__ atl,
        float* __restrict__ y)
{
    extern __shared__ __nv_bfloat16 smbufh[];
    const int tid  = threadIdx.x;
    const int lane = tid & 31;
    const int w    = tid >> 5;
    const int wm   = w >> 2;
    const int wn   = w & 3;
    const int m0 = blockIdx.x * 128;
    const int h  = blockIdx.y;
    const int bh = (m0 >> 11) * HH + h;

    #pragma unroll
    for (int i = 0; i < 4; i++) {
        int c = tid + i*512;
        int r = c >> 4;
        int c16 = (c & 15) * 8;
        size_t ga = (size_t)(m0 + r)*DD + h*DHH + c16;
        size_t gb = ((size_t)bh*DHH + r)*DHH + c16;
        __nv_bfloat16* d = smbufh + r*LD2 + c16;
        *(uint4*)(d + 0*ATE) = *(const uint4*)(qh + ga);
        *(uint4*)(d + 1*ATE) = *(const uint4*)(ql + ga);
        *(uint4*)(d + 2*ATE) = *(const uint4*)(ath + gb);
        *(uint4*)(d + 3*ATE) = *(const uint4*)(atl + gb);
    }
    __syncthreads();

    const uint32_t smb = smem_to_u32(smbufh);
    const int arow  = wm*32 + (lane & 7) + ((lane >> 3) & 1) * 8;
    const int akoff = ((lane >> 4) & 1) * 8;
    const int brow  = wn*32 + (lane & 7) + ((lane >> 4) & 1) * 8;
    const int bkoff = ((lane >> 3) & 1) * 8;

    float acc[2][4][4];
    #pragma unroll
    for (int i=0;i<2;i++)
        #pragma unroll
        for (int j=0;j<4;j++)
            #pragma unroll
            for (int l=0;l<4;l++) acc[i][j][l]=0.f;

    #pragma unroll
    for (int ks = 0; ks < 8; ks++) {
        uint32_t ah[2][4], al[2][4];
        #pragma unroll
        for (int mt = 0; mt < 2; mt++) {
            uint32_t ra = smb + ((arow + mt*16)*LD2 + ks*16 + akoff) * 2;
            LDSM4(ah[mt], ra);
            LDSM4(al[mt], ra + ATE*2);
        }
        uint32_t bhf[2][4], blf[2][4];
        #pragma unroll
        for (int nb = 0; nb < 2; nb++) {
            uint32_t rb = smb + 2*ATE*2 + ((brow + nb*16)*LD2 + ks*16 + bkoff) * 2;
            LDSM4(bhf[nb], rb);
            LDSM4(blf[nb], rb + ATE*2);
        }
        #pragma unroll
        for (int mt = 0; mt < 2; mt++)
            #pragma unroll
            for (int nt = 0; nt < 4; nt++) {
                int nb = nt >> 1, sub = (nt & 1) * 2;
                MMA_BF16(acc[mt][nt], ah[mt], bhf[nb][sub], bhf[nb][sub+1]);
            }
        #pragma unroll
        for (int mt = 0; mt < 2; mt++)
            #pragma unroll
            for (int nt = 0; nt < 4; nt++) {
                int nb = nt >> 1, sub = (nt & 1) * 2;
                MMA_BF16(acc[mt][nt], ah[mt], blf[nb][sub], blf[nb][sub+1]);
            }
        #pragma unroll
        for (int mt = 0; mt < 2; mt++)
            #pragma unroll
            for (int nt = 0; nt < 4; nt++) {
                int nb = nt >> 1, sub = (nt & 1) * 2;
                MMA_BF16(acc[mt][nt], al[mt], bhf[nb][sub], bhf[nb][sub+1]);
            }
    }

    const int t4 = lane >> 2;
    const int t2 = (lane & 3) * 2;
    #pragma unroll
    for (int mt = 0; mt < 2; mt++) {
        int row0 = m0 + wm*32 + mt*16 + t4;
        int row1 = row0 + 8;
        #pragma unroll
        for (int nt = 0; nt < 4; nt++) {
            int col = h*DHH + wn*32 + nt*8 + t2;
            *(float2*)(y + (size_t)row0*DD + col) = make_float2(acc[mt][nt][0], acc[mt][nt][1]);
            *(float2*)(y + (size_t)row1*DD + col) = make_float2(acc[mt][nt][2], acc[mt][nt][3]);
        }
    }
}

// ======================= emb path =======================
__global__ void silu_emb_k(const float* __restrict__ emb, float* __restrict__ out)
{
    int i = blockIdx.x*256 + threadIdx.x;
    float e = emb[i];
    out[i] = e / (1.0f + expf(-e));
}

__global__ __launch_bounds__(256) void emb_gemm_k(const float* __restrict__ ea,
                                                  const float* __restrict__ W,
                                                  const float* __restrict__ bias,
                                                  float* __restrict__ out)
{
    int n = blockIdx.x*256 + threadIdx.x;
    int b = blockIdx.y;
    const float* e = ea + b*TEE;
    float acc = 0.f;
    #pragma unroll 8
    for (int t=0;t<TEE;t++)
        acc = fmaf(e[t], W[(size_t)t*(2*DD) + n], acc);
    out[b*(2*DD) + n] = acc + bias[n];
}

// ======================= LN2 + FiLM + SiLU -> tf32 fp32 =====================
__global__ __launch_bounds__(256) void film_k(const float* __restrict__ y,
                                              const float* __restrict__ w2,
                                              const float* __restrict__ b2,
                                              const float* __restrict__ embout,
                                              float* __restrict__ act)
{
    int row = blockIdx.x;
    int b = row / TT;
    int tid = threadIdx.x;
    const float4* yr = (const float4*)(y + (size_t)row*DD);
    float4 v = yr[tid];
    float s  = v.x+v.y+v.z+v.w;
    float ss = v.x*v.x+v.y*v.y+v.z*v.z+v.w*v.w;
    #pragma unroll
    for (int o=16;o>0;o>>=1){ s += __shfl_down_sync(0xffffffffu,s,o); ss += __shfl_down_sync(0xffffffffu,ss,o); }
    __shared__ float sm[8], sm2[8];
    int wid = tid>>5, lane = tid&31;
    if (lane==0){ sm[wid]=s; sm2[wid]=ss; }
    __syncthreads();
    if (tid==0){
        float a=0.f, c=0.f;
        #pragma unroll
        for (int i=0;i<8;i++){ a+=sm[i]; c+=sm2[i]; }
        float mean = a*(1.0f/DD);
        float var  = c*(1.0f/DD) - mean*mean;
        sm[0]=mean; sm2[0]=rsqrtf(var+1e-5f);
    }
    __syncthreads();
    float mean=sm[0], rinv=sm2[0];
    float4 wv=((const float4*)w2)[tid];
    float4 bv=((const float4*)b2)[tid];
    float4 sc=((const float4*)(embout + (size_t)b*(2*DD)))[tid];
    float4 sh=((const float4*)(embout + (size_t)b*(2*DD) + DD))[tid];
    float4 o;
    float h;
    h=(v.x-mean)*rinv*wv.x+bv.x; h=h*(1.0f+sc.x)+sh.x; o.x=to_tf32(h/(1.0f+expf(-h)));
    h=(v.y-mean)*rinv*wv.y+bv.y; h=h*(1.0f+sc.y)+sh.y; o.y=to_tf32(h/(1.0f+expf(-h)));
    h=(v.z-mean)*rinv*wv.z+bv.z; h=h*(1.0f+sc.z)+sh.z; o.z=to_tf32(h/(1.0f+expf(-h)));
    h=(v.w-mean)*rinv*wv.w+bv.w; h=h*(1.0f+sc.w)+sh.w; o.w=to_tf32(h/(1.0f+expf(-h)));
    ((float4*)(act + (size_t)row*DD))[tid]=o;
}

// ======================= launch =======================
extern "C" void kernel_launch(void* const* d_in, const int* in_sizes, int n_in,
                              void* d_out, int out_size)
{
    (void)in_sizes; (void)n_in; (void)out_size;
    const float* x     = (const float*)d_in[0];
    const float* emb   = (const float*)d_in[1];
    const float* mask  = (const float*)d_in[2];
    const float* ln_w  = (const float*)d_in[4];
    const float* ln_b  = (const float*)d_in[5];
    const float* Wq    = (const float*)d_in[6];
    const float* bq    = (const float*)d_in[7];
    const float* Wk    = (const float*)d_in[8];
    const float* bk    = (const float*)d_in[9];
    const float* Wv    = (const float*)d_in[10];
    const float* bv    = (const float*)d_in[11];
    const float* W_emb = (const float*)d_in[12];
    const float* b_emb = (const float*)d_in[13];
    const float* ln2_w = (const float*)d_in[14];
    const float* ln2_b = (const float*)d_in[15];
    const float* W_out = (const float*)d_in[16];
    const float* b_out = (const float*)d_in[17];
    float* out = (float*)d_out;

    float *p_xn, *p_act, *p_wt, *p_k, *p_y, *p_attp, *p_emba, *p_embout;
    __nv_bfloat16 *p_qh, *p_ql, *p_kTh, *p_kTl, *p_vTh, *p_vTl, *p_ath, *p_atl;
    cudaGetSymbolAddress((void**)&p_xn,     g_xn);
    cudaGetSymbolAddress((void**)&p_act,    g_act);
    cudaGetSymbolAddress((void**)&p_wt,     g_wt);
    cudaGetSymbolAddress((void**)&p_k,      g_k);
    cudaGetSymbolAddress((void**)&p_y,      g_y);
    cudaGetSymbolAddress((void**)&p_qh,     g_qhi);
    cudaGetSymbolAddress((void**)&p_ql,     g_qlo);
    cudaGetSymbolAddress((void**)&p_kTh,    g_kThi);
    cudaGetSymbolAddress((void**)&p_kTl,    g_kTlo);
    cudaGetSymbolAddress((void**)&p_vTh,    g_vThi);
    cudaGetSymbolAddress((void**)&p_vTl,    g_vTlo);
    cudaGetSymbolAddress((void**)&p_ath,    g_attThi);
    cudaGetSymbolAddress((void**)&p_atl,    g_attTlo);
    cudaGetSymbolAddress((void**)&p_attp,   g_att_part);
    cudaGetSymbolAddress((void**)&p_emba,   g_emb_act);
    cudaGetSymbolAddress((void**)&p_embout, g_embout);

    cudaFuncSetAttribute(hgemm_k, cudaFuncAttributeMaxDynamicSharedMemorySize, HG_SMEM);
    cudaFuncSetAttribute(att1_k,  cudaFuncAttributeMaxDynamicSharedMemorySize, ATT_SMEM);
    cudaFuncSetAttribute(att2_k,  cudaFuncAttributeMaxDynamicSharedMemorySize, ATT_SMEM);

    wsplit4_k<<<dim3(32,32,4), dim3(32,32)>>>(Wq, Wk, Wv, W_out, p_wt);
    ln_kernel<<<MM, 256>>>(x, ln_w, ln_b, p_xn);
    silu_emb_k<<<(BB*TEE)/256, 256>>>(emb, p_emba);

    // QKV fused: grid.z = 3 selects weight slice + epilogue
    hgemm_k<<<dim3(DD/128, MM/64, 3), 128, HG_SMEM>>>(
        p_xn, p_wt,
        bq, bk, bv, mask, nullptr, p_k, p_qh, p_ql, p_vTh, p_vTl, -1);

    ksoftmaxT_k<<<BB*32, dim3(32,8)>>>(p_k, p_kTh, p_kTl);

    att1_k<<<dim3(NCHUNK, BB*HH), 512, ATT_SMEM>>>(p_vTh, p_vTl, p_kTh, p_kTl, p_attp);
    att_reduce_k<<<(BB*HH*DHH*DHH)/256, 256>>>(p_attp, p_ath, p_atl);

    emb_gemm_k<<<dim3((2*DD)/256, BB), 256>>>(p_emba, W_emb, b_emb, p_embout);

    att2_k<<<dim3(MM/128, HH), 512, ATT_SMEM>>>(p_qh, p_ql, p_ath, p_atl, p_y);

    film_k<<<MM, 256>>>(p_y, ln2_w, ln2_b, p_embout, p_act);

    // OUT projection (+residual)
    hgemm_k<<<dim3(DD/128, MM/64, 1), 128, HG_SMEM>>>(
        p_act, p_wt + 3*(size_t)DD*DD,
        b_out, nullptr, nullptr, nullptr, x, out, nullptr, nullptr, nullptr, nullptr, 3);
}

// round 14
// speedup vs baseline: 1.4828x; 1.0560x over previous
#include <cuda_runtime.h>
#include <cuda_bf16.h>
#include <math.h>
#include <stdint.h>

#define BB 4
#define TT 2048
#define DD 1024
#define HH 8
#define DHH 128
#define TEE 2048
#define MM (BB*TT)          // 8192 rows
#define NCHUNK 8            // att1 t-chunks (256 t per block)

__device__ __forceinline__ uint32_t smem_to_u32(const void* p) {
    uint32_t a;
    asm("{ .reg .u64 t; cvta.to.shared.u64 t, %1; cvt.u32.u64 %0, t; }" : "=r"(a) : "l"(p));
    return a;
}
__device__ __forceinline__ float to_tf32(float v) {
    uint32_t u;
    asm("cvt.rna.tf32.f32 %0, %1;" : "=r"(u) : "f"(v));
    return __uint_as_float(u);
}

#define LDSM4(R, addr) \
    asm volatile("ldmatrix.sync.aligned.m8n8.x4.shared.b16 {%0,%1,%2,%3}, [%4];" \
        : "=r"((R)[0]), "=r"((R)[1]), "=r"((R)[2]), "=r"((R)[3]) : "r"(addr))

#define MMA_BF16(c, a, b0, b1) \
    asm volatile("mma.sync.aligned.m16n8k16.row.col.f32.bf16.bf16.f32 " \
        "{%0,%1,%2,%3}, {%4,%5,%6,%7}, {%8,%9}, {%0,%1,%2,%3};" \
        : "+f"((c)[0]), "+f"((c)[1]), "+f"((c)[2]), "+f"((c)[3]) \
        : "r"((a)[0]), "r"((a)[1]), "r"((a)[2]), "r"((a)[3]), "r"(b0), "r"(b1))

#define MMA_TF32(c, a, b0, b1) \
    asm volatile("mma.sync.aligned.m16n8k8.row.col.f32.tf32.tf32.f32 " \
        "{%0,%1,%2,%3}, {%4,%5,%6,%7}, {%8,%9}, {%0,%1,%2,%3};" \
        : "+f"((c)[0]), "+f"((c)[1]), "+f"((c)[2]), "+f"((c)[3]) \
        : "r"((a)[0]), "r"((a)[1]), "r"((a)[2]), "r"((a)[3]), "r"(b0), "r"(b1))

#define CP16(dst, src) \
    asm volatile("cp.async.cg.shared.global [%0], [%1], 16;" :: "r"(dst), "l"(src))
#define CP_COMMIT() asm volatile("cp.async.commit_group;")
#define CP_WAIT1()  asm volatile("cp.async.wait_group 1;")

// ======================= device scratch =======================
__device__ float g_xn [MM*DD];          // tf32-rounded LN output
__device__ float g_act[MM*DD];          // tf32-rounded FiLM output
__device__ float g_wt [4][DD*DD];       // tf32-rounded transposed weights
__device__ float g_k  [MM*DD];
__device__ float g_y  [MM*DD];
__device__ __nv_bfloat16 g_qhi[MM*DD];
__device__ __nv_bfloat16 g_qlo[MM*DD];
__device__ __nv_bfloat16 g_kThi[MM*DD];
__device__ __nv_bfloat16 g_kTlo[MM*DD];
__device__ __nv_bfloat16 g_vThi[MM*DD];
__device__ __nv_bfloat16 g_vTlo[MM*DD];
__device__ float g_att_part[NCHUNK*BB*HH*DHH*DHH];
__device__ __nv_bfloat16 g_attThi[BB*HH*DHH*DHH];
__device__ __nv_bfloat16 g_attTlo[BB*HH*DHH*DHH];
__device__ float g_emb_act[BB*TEE];
__device__ float g_embout[BB*2*DD];

// ======================= LayerNorm -> tf32 fp32 =======================
__global__ __launch_bounds__(256) void ln_kernel(const float* __restrict__ x,
                                                 const float* __restrict__ w,
                                                 const float* __restrict__ b,
                                                 float* __restrict__ outx)
{
    int row = blockIdx.x;
    int tid = threadIdx.x;
    const float4* xr = (const float4*)(x + (size_t)row*DD);
    float4 v = xr[tid];
    float s  = v.x+v.y+v.z+v.w;
    float ss = v.x*v.x+v.y*v.y+v.z*v.z+v.w*v.w;
    #pragma unroll
    for (int o=16;o>0;o>>=1){ s += __shfl_down_sync(0xffffffffu,s,o); ss += __shfl_down_sync(0xffffffffu,ss,o); }
    __shared__ float sm[8], sm2[8];
    int wid = tid>>5, lane = tid&31;
    if (lane==0){ sm[wid]=s; sm2[wid]=ss; }
    __syncthreads();
    if (tid==0){
        float a=0.f, c=0.f;
        #pragma unroll
        for (int i=0;i<8;i++){ a+=sm[i]; c+=sm2[i]; }
        float mean = a*(1.0f/DD);
        float var  = c*(1.0f/DD) - mean*mean;
        sm[0]=mean; sm2[0]=rsqrtf(var+1e-5f);
    }
    __syncthreads();
    float mean=sm[0], rinv=sm2[0];
    float4 wv=((const float4*)w)[tid];
    float4 bv=((const float4*)b)[tid];
    float4 o;
    o.x=to_tf32((v.x-mean)*rinv*wv.x+bv.x);
    o.y=to_tf32((v.y-mean)*rinv*wv.y+bv.y);
    o.z=to_tf32((v.z-mean)*rinv*wv.z+bv.z);
    o.w=to_tf32((v.w-mean)*rinv*wv.w+bv.w);
    ((float4*)(outx + (size_t)row*DD))[tid]=o;
}

// ======================= weight transpose -> tf32 fp32 ======================
__global__ __launch_bounds__(1024) void wsplit4_k(const float* __restrict__ W0,
                                                  const float* __restrict__ W1,
                                                  const float* __restrict__ W2,
                                                  const float* __restrict__ W3,
                                                  float* __restrict__ Wt)
{
    __shared__ float t[32][33];
    int tx = threadIdx.x, ty = threadIdx.y;
    int wsel = blockIdx.z;
    const float* W = (wsel==0)?W0:(wsel==1)?W1:(wsel==2)?W2:W3;
    t[ty][tx] = W[(size_t)(blockIdx.y*32+ty)*DD + blockIdx.x*32+tx];
    __syncthreads();
    int n = blockIdx.x*32 + ty;
    int k = blockIdx.y*32 + tx;
    Wt[(size_t)wsel*DD*DD + (size_t)n*DD + k] = to_tf32(t[tx][ty]);
}

// ======================= TF32 GEMM, BM=64 BN=128, 4 warps, 3 CTAs/SM ========
// 2-stage double buffer; smem row stride 144 B (16B-aligned, conflict-free)
#define LDSB    144                       // smem row stride in BYTES
#define TA_B    (64*LDSB)                 // 9216 B (A tile)
#define TB_B    (128*LDSB)                // 18432 B (B tile)
#define STAGE_B (TA_B + TB_B)             // 27648 B per stage
#define HG_SMEM (2*STAGE_B)               // 55296 B

__global__ __launch_bounds__(128, 3) void hgemm_k(
        const float* __restrict__ A,
        const float* __restrict__ Wt,
        const float* __restrict__ bias0, const float* __restrict__ bias1,
        const float* __restrict__ bias2,
        const float* __restrict__ mask,
        const float* __restrict__ resid, float* __restrict__ C,
        __nv_bfloat16* __restrict__ Qh, __nv_bfloat16* __restrict__ Ql,
        __nv_bfloat16* __restrict__ Vh, __nv_bfloat16* __restrict__ Vl,
        int mode_ov)
{
    extern __shared__ float smbuf[];
    const int tid  = threadIdx.x;
    const int lane = tid & 31;
    const int w    = tid >> 5;      // 0..3
    const int wm   = w >> 1;        // 0..1 : 32 rows
    const int wn   = w & 1;         // 0..1 : 64 cols
    const int m0 = blockIdx.y * 64;
    const int n0 = blockIdx.x * 128;
    const int mode = (mode_ov >= 0) ? mode_ov : (int)blockIdx.z;
    const int wsel = (mode_ov >= 0) ? 0 : (int)blockIdx.z;
    const float* bias = (mode == 1) ? bias1 : (mode == 2) ? bias2 : bias0;
    const float* B = Wt + (size_t)wsel*DD*DD;

    const uint32_t smb = smem_to_u32(smbuf);
    const uint32_t dA = smb;
    const uint32_t dB = smb + TA_B;

    const int arow = wm*32 + (lane & 7) + ((lane >> 3) & 1) * 8;     // +mt*16
    const int akb  = ((lane >> 4) & 1) * 16;
    const int brow = wn*64 + ((lane >> 4) & 1) * 8 + (lane & 7);     // +nb*16
    const int bkb  = ((lane >> 3) & 1) * 16;

    float acc[2][8][4];
    #pragma unroll
    for (int i=0;i<2;i++)
        #pragma unroll
        for (int j=0;j<8;j++)
            #pragma unroll
            for (int l=0;l<4;l++) acc[i][j][l]=0.f;

    // prologue: stages 0,1
    #pragma unroll
    for (int s = 0; s < 2; s++) {
        int k0 = s*32;
        uint32_t so = s*STAGE_B;
        #pragma unroll
        for (int i = 0; i < 4; i++) {
            int idx = tid + i*128;      // 0..511
            int r = idx >> 3, ch = idx & 7;
            CP16(dA + so + (uint32_t)(r*LDSB + ch*16), A + (size_t)(m0+r)*DD + k0 + ch*4);
        }
        #pragma unroll
        for (int i = 0; i < 8; i++) {
            int idx = tid + i*128;      // 0..1023
            int r = idx >> 3, ch = idx & 7;
            CP16(dB + so + (uint32_t)(r*LDSB + ch*16), B + (size_t)(n0+r)*DD + k0 + ch*4);
        }
        CP_COMMIT();
    }

    for (int kc = 0; kc < 32; kc++) {
        CP_WAIT1();
        __syncthreads();

        uint32_t baseA = smb + (kc & 1)*STAGE_B;
        uint32_t baseB = baseA + TA_B;
        #pragma unroll
        for (int ks = 0; ks < 4; ks++) {        // 4 k8-steps per 32-chunk
            uint32_t a[2][4];
            #pragma unroll
            for (int mt = 0; mt < 2; mt++) {
                uint32_t ra = baseA + (uint32_t)((arow + mt*16)*LDSB + akb + ks*32);
                LDSM4(a[mt], ra);
            }
            uint32_t bf[4][4];
            #pragma unroll
            for (int nb = 0; nb < 4; nb++) {
                uint32_t rb = baseB + (uint32_t)((brow + nb*16)*LDSB + bkb + ks*32);
                LDSM4(bf[nb], rb);
            }
            #pragma unroll
            for (int mt = 0; mt < 2; mt++)
                #pragma unroll
                for (int nb = 0; nb < 4; nb++) {
                    MMA_TF32(acc[mt][nb*2],   a[mt], bf[nb][0], bf[nb][1]);
                    MMA_TF32(acc[mt][nb*2+1], a[mt], bf[nb][2], bf[nb][3]);
                }
        }

        __syncthreads();
        if (kc + 2 < 32) {
            int k0 = (kc+2)*32;
            uint32_t so = (kc & 1)*STAGE_B;
            #pragma unroll
            for (int i = 0; i < 4; i++) {
                int idx = tid + i*128;
                int r = idx >> 3, ch = idx & 7;
                CP16(dA + so + (uint32_t)(r*LDSB + ch*16), A + (size_t)(m0+r)*DD + k0 + ch*4);
            }
            #pragma unroll
            for (int i = 0; i < 8; i++) {
                int idx = tid + i*128;
                int r = idx >> 3, ch = idx & 7;
                CP16(dB + so + (uint32_t)(r*LDSB + ch*16), B + (size_t)(n0+r)*DD + k0 + ch*4);
            }
        }
        CP_COMMIT();
    }

    const int t4 = lane >> 2;
    const int t2 = (lane & 3) * 2;

    #pragma unroll
    for (int mt = 0; mt < 2; mt++)
        #pragma unroll
        for (int nt = 0; nt < 8; nt++) {
            int col = n0 + wn*64 + nt*8 + t2;
            float2 bi = *(const float2*)(bias + col);
            acc[mt][nt][0] += bi.x; acc[mt][nt][1] += bi.y;
            acc[mt][nt][2] += bi.x; acc[mt][nt][3] += bi.y;
        }

    if (mode == 0) {
        // fused softmax over 128 cols (one head), 64 rows; 2 col-warps
        __syncthreads();
        float* red  = smbuf;            // [64][2]
        float* red2 = smbuf + 128;
        float mrow[2][2];
        #pragma unroll
        for (int mt = 0; mt < 2; mt++) {
            float a0 = -1e30f, a1 = -1e30f;
            #pragma unroll
            for (int nt = 0; nt < 8; nt++) {
                a0 = fmaxf(a0, fmaxf(acc[mt][nt][0], acc[mt][nt][1]));
                a1 = fmaxf(a1, fmaxf(acc[mt][nt][2], acc[mt][nt][3]));
            }
            a0 = fmaxf(a0, __shfl_xor_sync(0xffffffffu, a0, 1));
            a0 = fmaxf(a0, __shfl_xor_sync(0xffffffffu, a0, 2));
            a1 = fmaxf(a1, __shfl_xor_sync(0xffffffffu, a1, 1));
            a1 = fmaxf(a1, __shfl_xor_sync(0xffffffffu, a1, 2));
            if ((lane & 3) == 0) {
                int r = wm*32 + mt*16 + t4;
                red[r*2 + wn] = a0;
                red[(r+8)*2 + wn] = a1;
            }
        }
        __syncthreads();
        #pragma unroll
        for (int mt = 0; mt < 2; mt++) {
            int r = wm*32 + mt*16 + t4;
            mrow[mt][0] = fmaxf(red[r*2+0], red[r*2+1]);
            mrow[mt][1] = fmaxf(red[(r+8)*2+0], red[(r+8)*2+1]);
        }
        float srow[2][2];
        #pragma unroll
        for (int mt = 0; mt < 2; mt++) {
            float s0 = 0.f, s1 = 0.f;
            #pragma unroll
            for (int nt = 0; nt < 8; nt++) {
                acc[mt][nt][0] = expf(acc[mt][nt][0] - mrow[mt][0]);
                acc[mt][nt][1] = expf(acc[mt][nt][1] - mrow[mt][0]);
                acc[mt][nt][2] = expf(acc[mt][nt][2] - mrow[mt][1]);
                acc[mt][nt][3] = expf(acc[mt][nt][3] - mrow[mt][1]);
                s0 += acc[mt][nt][0] + acc[mt][nt][1];
                s1 += acc[mt][nt][2] + acc[mt][nt][3];
            }
            s0 += __shfl_xor_sync(0xffffffffu, s0, 1);
            s0 += __shfl_xor_sync(0xffffffffu, s0, 2);
            s1 += __shfl_xor_sync(0xffffffffu, s1, 1);
            s1 += __shfl_xor_sync(0xffffffffu, s1, 2);
            if ((lane & 3) == 0) {
                int r = wm*32 + mt*16 + t4;
                red2[r*2 + wn] = s0;
                red2[(r+8)*2 + wn] = s1;
            }
        }
        __syncthreads();
        #pragma unroll
        for (int mt = 0; mt < 2; mt++) {
            int r = wm*32 + mt*16 + t4;
            srow[mt][0] = 1.0f / (red2[r*2+0] + red2[r*2+1]);
            srow[mt][1] = 1.0f / (red2[(r+8)*2+0] + red2[(r+8)*2+1]);
        }
        #pragma unroll
        for (int mt = 0; mt < 2; mt++) {
            int row0 = m0 + wm*32 + mt*16 + t4;
            int row1 = row0 + 8;
            #pragma unroll
            for (int nt = 0; nt < 8; nt++) {
                int col = n0 + wn*64 + nt*8 + t2;
                float v0 = acc[mt][nt][0] * srow[mt][0];
                float v1 = acc[mt][nt][1] * srow[mt][0];
                float v2 = acc[mt][nt][2] * srow[mt][1];
                float v3 = acc[mt][nt][3] * srow[mt][1];
                __nv_bfloat162 h0 = __floats2bfloat162_rn(v0, v1);
                __nv_bfloat162 h1 = __floats2bfloat162_rn(v2, v3);
                __nv_bfloat162 l0 = __floats2bfloat162_rn(v0 - __bfloat162float(h0.x), v1 - __bfloat162float(h0.y));
                __nv_bfloat162 l1 = __floats2bfloat162_rn(v2 - __bfloat162float(h1.x), v3 - __bfloat162float(h1.y));
                *(uint32_t*)(Qh + (size_t)row0*DD + col) = *(uint32_t*)&h0;
                *(uint32_t*)(Qh + (size_t)row1*DD + col) = *(uint32_t*)&h1;
                *(uint32_t*)(Ql + (size_t)row0*DD + col) = *(uint32_t*)&l0;
                *(uint32_t*)(Ql + (size_t)row1*DD + col) = *(uint32_t*)&l1;
            }
        }
        return;
    }

    if (mode == 2) {
        // V projection: (acc+bias)*mask -> transposed vT[b][h][l][t] hi/lo
        #pragma unroll
        for (int mt = 0; mt < 2; mt++) {
            int row0 = m0 + wm*32 + mt*16 + t4;
            int row1 = row0 + 8;
            float m0v = mask[row0], m1v = mask[row1];
            int b0 = row0 >> 11, tt0 = row0 & (TT-1);
            int b1 = row1 >> 11, tt1 = row1 & (TT-1);
            #pragma unroll
            for (int nt = 0; nt < 8; nt++) {
                int col = n0 + wn*64 + nt*8 + t2;
                int h = col >> 7, l = col & 127;
                float a0 = acc[mt][nt][0] * m0v;
                float a1 = acc[mt][nt][1] * m0v;
                float a2 = acc[mt][nt][2] * m1v;
                float a3 = acc[mt][nt][3] * m1v;
                size_t i00 = ((size_t)(b0*HH + h)*DHH + l)*TT + tt0;
                size_t i10 = ((size_t)(b1*HH + h)*DHH + l)*TT + tt1;
                __nv_bfloat16 h0 = __float2bfloat16(a0);
                __nv_bfloat16 h1 = __float2bfloat16(a1);
                __nv_bfloat16 h2 = __float2bfloat16(a2);
                __nv_bfloat16 h3 = __float2bfloat16(a3);
                Vh[i00]      = h0;
                Vh[i00 + TT] = h1;
                Vh[i10]      = h2;
                Vh[i10 + TT] = h3;
                Vl[i00]      = __float2bfloat16(a0 - __bfloat162float(h0));
                Vl[i00 + TT] = __float2bfloat16(a1 - __bfloat162float(h1));
                Vl[i10]      = __float2bfloat16(a2 - __bfloat162float(h2));
                Vl[i10 + TT] = __float2bfloat16(a3 - __bfloat162float(h3));
            }
        }
        return;
    }

    #pragma unroll
    for (int mt = 0; mt < 2; mt++) {
        int row0 = m0 + wm*32 + mt*16 + t4;
        int row1 = row0 + 8;
        float m0v = 0.f, m1v = 0.f;
        if (mode == 1) { m0v = mask[row0]; m1v = mask[row1]; }
        float add0 = (mode==1) ? (1.0f-m0v)*(-1000000.0f) : 0.f;
        float add1 = (mode==1) ? (1.0f-m1v)*(-1000000.0f) : 0.f;
        #pragma unroll
        for (int nt = 0; nt < 8; nt++) {
            int col = n0 + wn*64 + nt*8 + t2;
            float a0 = acc[mt][nt][0];
            float a1 = acc[mt][nt][1];
            float a2 = acc[mt][nt][2];
            float a3 = acc[mt][nt][3];
            if (mode == 1) { a0 += add0; a1 += add0; a2 += add1; a3 += add1; }
            else if (mode == 3) {
                float2 r0 = *(const float2*)(resid + (size_t)row0*DD + col);
                float2 r1 = *(const float2*)(resid + (size_t)row1*DD + col);
                a0 += r0.x; a1 += r0.y; a2 += r1.x; a3 += r1.y;
            }
            *(float2*)(C + (size_t)row0*DD + col) = make_float2(a0, a1);
            *(float2*)(C + (size_t)row1*DD + col) = make_float2(a2, a3);
        }
    }
}

// ======================= softmax over time -> transposed bf16 hi/lo =========
__global__ void ksoftmaxT_k(const float* __restrict__ k,
                            __nv_bfloat16* __restrict__ kTh,
                            __nv_bfloat16* __restrict__ kTl)
{
    int b = blockIdx.x >> 5;
    int g = blockIdx.x & 31;
    int tx = threadIdx.x, ty = threadIdx.y;
    int d = g*32 + tx;
    float m = -INFINITY, s = 0.f;
    for (int t=ty; t<TT; t+=8){
        float val = k[((size_t)b*TT + t)*DD + d];
        float nm = fmaxf(m, val);
        s = s*expf(m-nm) + expf(val-nm);
        m = nm;
    }
    __shared__ float smax[8][32], ssum[8][32];
    smax[ty][tx]=m; ssum[ty][tx]=s;
    __syncthreads();
    if (ty==0){
        float M=smax[0][tx], S=ssum[0][tx];
        #pragma unroll
        for (int i=1;i<8;i++){
            float m2=smax[i][tx], s2=ssum[i][tx];
            float nm=fmaxf(M,m2);
            S = S*expf(M-nm) + s2*expf(m2-nm);
            M = nm;
        }
        smax[0][tx]=M; ssum[0][tx]=1.0f/S;
    }
    __syncthreads();
    float M=smax[0][tx], R=ssum[0][tx];
    __syncthreads();

    __shared__ __nv_bfloat16 sh[32][33], sl[32][33];
    int dg0 = g*32;
    int h = dg0 >> 7;
    int dl0 = dg0 & 127;
    size_t kbase = ((size_t)(b*HH + h))*DHH + dl0;

    for (int t0 = 0; t0 < TT; t0 += 32) {
        #pragma unroll
        for (int i = 0; i < 4; i++) {
            int t = t0 + ty + i*8;
            float val = expf(k[((size_t)b*TT + t)*DD + d] - M) * R;
            __nv_bfloat16 hv = __float2bfloat16(val);
            sh[tx][ty + i*8] = hv;
            sl[tx][ty + i*8] = __float2bfloat16(val - __bfloat162float(hv));
        }
        __syncthreads();
        #pragma unroll
        for (int i = 0; i < 4; i++) {
            int row = ty + i*8;
            kTh[(kbase + row)*TT + t0 + tx] = sh[row][tx];
            kTl[(kbase + row)*TT + t0 + tx] = sl[row][tx];
        }
        __syncthreads();
    }
}

// ======================= attention core HMMA ================================
#define LD2    136
#define ATE    (128*LD2)
#define ATT_SMEM (4*ATE*2)

__global__ __launch_bounds__(512, 1) void att1_k(
        const __nv_bfloat16* __restrict__ vTh, const __nv_bfloat16* __restrict__ vTl,
        const __nv_bfloat16* __restrict__ kTh, const __nv_bfloat16* __restrict__ kTl,
        float* __restrict__ part)
{
    extern __shared__ __nv_bfloat16 smbufh[];
    const int tid  = threadIdx.x;
    const int lane = tid & 31;
    const int w    = tid >> 5;
    const int wm   = w >> 2;
    const int wn   = w & 3;
    const int chunk = blockIdx.x;       // 0..7 (256 t each)
    const int bh    = blockIdx.y;

    const uint32_t smb = smem_to_u32(smbufh);
    const int arow  = wm*32 + (lane & 7) + ((lane >> 3) & 1) * 8;
    const int akoff = ((lane >> 4) & 1) * 8;
    const int brow  = wn*32 + (lane & 7) + ((lane >> 4) & 1) * 8;
    const int bkoff = ((lane >> 3) & 1) * 8;

    float acc[2][4][4];
    #pragma unroll
    for (int i=0;i<2;i++)
        #pragma unroll
        for (int j=0;j<4;j++)
            #pragma unroll
            for (int l=0;l<4;l++) acc[i][j][l]=0.f;

    for (int sub = 0; sub < 2; sub++) {
        int t0 = chunk*256 + sub*128;
        #pragma unroll
        for (int i = 0; i < 4; i++) {
            int c = tid + i*512;
            int r = c >> 4;
            int c16 = (c & 15) * 8;
            size_t g = ((size_t)bh*DHH + r)*TT + t0 + c16;
            __nv_bfloat16* d = smbufh + r*LD2 + c16;
            *(uint4*)(d + 0*ATE) = *(const uint4*)(vTh + g);
            *(uint4*)(d + 1*ATE) = *(const uint4*)(vTl + g);
            *(uint4*)(d + 2*ATE) = *(const uint4*)(kTh + g);
            *(uint4*)(d + 3*ATE) = *(const uint4*)(kTl + g);
        }
        __syncthreads();

        #pragma unroll
        for (int ks = 0; ks < 8; ks++) {
            uint32_t ah[2][4], al[2][4];
            #pragma unroll
            for (int mt = 0; mt < 2; mt++) {
                uint32_t ra = smb + ((arow + mt*16)*LD2 + ks*16 + akoff) * 2;
                LDSM4(ah[mt], ra);
                LDSM4(al[mt], ra + ATE*2);
            }
            uint32_t bhf[2][4], blf[2][4];
            #pragma unroll
            for (int nb = 0; nb < 2; nb++) {
                uint32_t rb = smb + 2*ATE*2 + ((brow + nb*16)*LD2 + ks*16 + bkoff) * 2;
                LDSM4(bhf[nb], rb);
                LDSM4(blf[nb], rb + ATE*2);
            }
            #pragma unroll
            for (int mt = 0; mt < 2; mt++)
                #pragma unroll
                for (int nt = 0; nt < 4; nt++) {
                    int nb = nt >> 1, sub2 = (nt & 1) * 2;
                    MMA_BF16(acc[mt][nt], ah[mt], bhf[nb][sub2], bhf[nb][sub2+1]);
                }
            #pragma unroll
            for (int mt = 0; mt < 2; mt++)
                #pragma unroll
                for (int nt = 0; nt < 4; nt++) {
                    int nb = nt >> 1, sub2 = (nt & 1) * 2;
                    MMA_BF16(acc[mt][nt], ah[mt], blf[nb][sub2], blf[nb][sub2+1]);
                }
            #pragma unroll
            for (int mt = 0; mt < 2; mt++)
                #pragma unroll
                for (int nt = 0; nt < 4; nt++) {
                    int nb = nt >> 1, sub2 = (nt & 1) * 2;
                    MMA_BF16(acc[mt][nt], al[mt], bhf[nb][sub2], bhf[nb][sub2+1]);
                }
        }
        __syncthreads();
    }

    float* dst = part + ((size_t)(chunk*(BB*HH) + bh))*(DHH*DHH);
    const int t4 = lane >> 2;
    const int t2 = (lane & 3) * 2;
    #pragma unroll
    for (int mt = 0; mt < 2; mt++) {
        int row0 = wm*32 + mt*16 + t4;
        int row1 = row0 + 8;
        #pragma unroll
        for (int nt = 0; nt < 4; nt++) {
            int col = wn*32 + nt*8 + t2;
            *(float2*)(dst + row0*DHH + col) = make_float2(acc[mt][nt][0], acc[mt][nt][1]);
            *(float2*)(dst + row1*DHH + col) = make_float2(acc[mt][nt][2], acc[mt][nt][3]);
        }
    }
}

__global__ void att_reduce_k(const float* __restrict__ part,
                             __nv_bfloat16* __restrict__ ath,
                             __nv_bfloat16* __restrict__ atl)
{
    int i = blockIdx.x*256 + threadIdx.x;
    float s = 0.f;
    #pragma unroll
    for (int c=0;c<NCHUNK;c++) s += part[(size_t)c*(BB*HH*DHH*DHH) + i];
    __nv_bfloat16 h = __float2bfloat16(s);
    ath[i] = h;
    atl[i] = __float2bfloat16(s - __bfloat162float(h));
}

__global__ __launch_bounds__(512, 1) void att2_k(
        const __nv_bfloat16* __restrict__ qh, const __nv_bfloat16* __restrict__ ql,
        const __nv_bfloat16* __restrict__ ath, const __nv_bfloat16* __restrict__ atl,
        float* __restrict__ y)
{
    extern __shared__ __nv_bfloat16 smbufh[];
    const int tid  = threadIdx.x;
    const int lane = tid & 31;
    const int w    = tid >> 5;
    const int wm   = w >> 2;
    const int wn   = w & 3;
    const int m0 = blockIdx.x * 128;
    const int h  = blockIdx.y;
    const int bh = (m0 >> 11) * HH + h;

    #pragma unroll
    for (int i = 0; i < 4; i++) {
        int c = tid + i*512;
        int r = c >> 4;
        int c16 = (c & 15) * 8;
        size_t ga = (size_t)(m0 + r)*DD + h*DHH + c16;
        size_t gb = ((size_t)bh*DHH + r)*DHH + c16;
        __nv_bfloat16* d = smbufh + r*LD2 + c16;
        *(uint4*)(d + 0*ATE) = *(const uint4*)(qh + ga);
        *(uint4*)(d + 1*ATE) = *(const uint4*)(ql + ga);
        *(uint4*)(d + 2*ATE) = *(const uint4*)(ath + gb);
        *(uint4*)(d + 3*ATE) = *(const uint4*)(atl + gb);
    }
    __syncthreads();

    const uint32_t smb = smem_to_u32(smbufh);
    const int arow  = wm*32 + (lane & 7) + ((lane >> 3) & 1) * 8;
    const int akoff = ((lane >> 4) & 1) * 8;
    const int brow  = wn*32 + (lane & 7) + ((lane >> 4) & 1) * 8;
    const int bkoff = ((lane >> 3) & 1) * 8;

    float acc[2][4][4];
    #pragma unroll
    for (int i=0;i<2;i++)
        #pragma unroll
        for (int j=0;j<4;j++)
            #pragma unroll
            for (int l=0;l<4;l++) acc[i][j][l]=0.f;

    #pragma unroll
    for (int ks = 0; ks < 8; ks++) {
        uint32_t ah[2][4], al[2][4];
        #pragma unroll
        for (int mt = 0; mt < 2; mt++) {
            uint32_t ra = smb + ((arow + mt*16)*LD2 + ks*16 + akoff) * 2;
            LDSM4(ah[mt], ra);
            LDSM4(al[mt], ra + ATE*2);
        }
        uint32_t bhf[2][4], blf[2][4];
        #pragma unroll
        for (int nb = 0; nb < 2; nb++) {
            uint32_t rb = smb + 2*ATE*2 + ((brow + nb*16)*LD2 + ks*16 + bkoff) * 2;
            LDSM4(bhf[nb], rb);
            LDSM4(blf[nb], rb + ATE*2);
        }
        #pragma unroll
        for (int mt = 0; mt < 2; mt++)
            #pragma unroll
            for (int nt = 0; nt < 4; nt++) {
                int nb = nt >> 1, sub = (nt & 1) * 2;
                MMA_BF16(acc[mt][nt], ah[mt], bhf[nb][sub], bhf[nb][sub+1]);
            }
        #pragma unroll
        for (int mt = 0; mt < 2; mt++)
            #pragma unroll
            for (int nt = 0; nt < 4; nt++) {
                int nb = nt >> 1, sub = (nt & 1) * 2;
                MMA_BF16(acc[mt][nt], ah[mt], blf[nb][sub], blf[nb][sub+1]);
            }
        #pragma unroll
        for (int mt = 0; mt < 2; mt++)
            #pragma unroll
            for (int nt = 0; nt < 4; nt++) {
                int nb = nt >> 1, sub = (nt & 1) * 2;
                MMA_BF16(acc[mt][nt], al[mt], bhf[nb][sub], bhf[nb][sub+1]);
            }
    }

    const int t4 = lane >> 2;
    const int t2 = (lane & 3) * 2;
    #pragma unroll
    for (int mt = 0; mt < 2; mt++) {
        int row0 = m0 + wm*32 + mt*16 + t4;
        int row1 = row0 + 8;
        #pragma unroll
        for (int nt = 0; nt < 4; nt++) {
            int col = h*DHH + wn*32 + nt*8 + t2;
            *(float2*)(y + (size_t)row0*DD + col) = make_float2(acc[mt][nt][0], acc[mt][nt][1]);
            *(float2*)(y + (size_t)row1*DD + col) = make_float2(acc[mt][nt][2], acc[mt][nt][3]);
        }
    }
}

// ======================= emb path =======================
__global__ void silu_emb_k(const float* __restrict__ emb, float* __restrict__ out)
{
    int i = blockIdx.x*256 + threadIdx.x;
    float e = emb[i];
    out[i] = e / (1.0f + expf(-e));
}

__global__ __launch_bounds__(256) void emb_gemm_k(const float* __restrict__ ea,
                                                  const float* __restrict__ W,
                                                  const float* __restrict__ bias,
                                                  float* __restrict__ out)
{
    int n = blockIdx.x*256 + threadIdx.x;
    int b = blockIdx.y;
    const float* e = ea + b*TEE;
    float acc = 0.f;
    #pragma unroll 8
    for (int t=0;t<TEE;t++)
        acc = fmaf(e[t], W[(size_t)t*(2*DD) + n], acc);
    out[b*(2*DD) + n] = acc + bias[n];
}

// ======================= LN2 + FiLM + SiLU -> tf32 fp32 =====================
__global__ __launch_bounds__(256) void film_k(const float* __restrict__ y,
                                              const float* __restrict__ w2,
                                              const float* __restrict__ b2,
                                              const float* __restrict__ embout,
                                              float* __restrict__ act)
{
    int row = blockIdx.x;
    int b = row / TT;
    int tid = threadIdx.x;
    const float4* yr = (const float4*)(y + (size_t)row*DD);
    float4 v = yr[tid];
    float s  = v.x+v.y+v.z+v.w;
    float ss = v.x*v.x+v.y*v.y+v.z*v.z+v.w*v.w;
    #pragma unroll
    for (int o=16;o>0;o>>=1){ s += __shfl_down_sync(0xffffffffu,s,o); ss += __shfl_down_sync(0xffffffffu,ss,o); }
    __shared__ float sm[8], sm2[8];
    int wid = tid>>5, lane = tid&31;
    if (lane==0){ sm[wid]=s; sm2[wid]=ss; }
    __syncthreads();
    if (tid==0){
        float a=0.f, c=0.f;
        #pragma unroll
        for (int i=0;i<8;i++){ a+=sm[i]; c+=sm2[i]; }
        float mean = a*(1.0f/DD);
        float var  = c*(1.0f/DD) - mean*mean;
        sm[0]=mean; sm2[0]=rsqrtf(var+1e-5f);
    }
    __syncthreads();
    float mean=sm[0], rinv=sm2[0];
    float4 wv=((const float4*)w2)[tid];
    float4 bv=((const float4*)b2)[tid];
    float4 sc=((const float4*)(embout + (size_t)b*(2*DD)))[tid];
    float4 sh=((const float4*)(embout + (size_t)b*(2*DD) + DD))[tid];
    float4 o;
    float h;
    h=(v.x-mean)*rinv*wv.x+bv.x; h=h*(1.0f+sc.x)+sh.x; o.x=to_tf32(h/(1.0f+expf(-h)));
    h=(v.y-mean)*rinv*wv.y+bv.y; h=h*(1.0f+sc.y)+sh.y; o.y=to_tf32(h/(1.0f+expf(-h)));
    h=(v.z-mean)*rinv*wv.z+bv.z; h=h*(1.0f+sc.z)+sh.z; o.z=to_tf32(h/(1.0f+expf(-h)));
    h=(v.w-mean)*rinv*wv.w+bv.w; h=h*(1.0f+sc.w)+sh.w; o.w=to_tf32(h/(1.0f+expf(-h)));
    ((float4*)(act + (size_t)row*DD))[tid]=o;
}

// ======================= launch =======================
extern "C" void kernel_launch(void* const* d_in, const int* in_sizes, int n_in,
                              void* d_out, int out_size)
{
    (void)in_sizes; (void)n_in; (void)out_size;
    const float* x     = (const float*)d_in[0];
    const float* emb   = (const float*)d_in[1];
    const float* mask  = (const float*)d_in[2];
    const float* ln_w  = (const float*)d_in[4];
    const float* ln_b  = (const float*)d_in[5];
    const float* Wq    = (const float*)d_in[6];
    const float* bq    = (const float*)d_in[7];
    const float* Wk    = (const float*)d_in[8];
    const float* bk    = (const float*)d_in[9];
    const float* Wv    = (const float*)d_in[10];
    const float* bv    = (const float*)d_in[11];
    const float* W_emb = (const float*)d_in[12];
    const float* b_emb = (const float*)d_in[13];
    const float* ln2_w = (const float*)d_in[14];
    const float* ln2_b = (const float*)d_in[15];
    const float* W_out = (const float*)d_in[16];
    const float* b_out = (const float*)d_in[17];
    float* out = (float*)d_out;

    float *p_xn, *p_act, *p_wt, *p_k, *p_y, *p_attp, *p_emba, *p_embout;
    __nv_bfloat16 *p_qh, *p_ql, *p_kTh, *p_kTl, *p_vTh, *p_vTl, *p_ath, *p_atl;
    cudaGetSymbolAddress((void**)&p_xn,     g_xn);
    cudaGetSymbolAddress((void**)&p_act,    g_act);
    cudaGetSymbolAddress((void**)&p_wt,     g_wt);
    cudaGetSymbolAddress((void**)&p_k,      g_k);
    cudaGetSymbolAddress((void**)&p_y,      g_y);
    cudaGetSymbolAddress((void**)&p_qh,     g_qhi);
    cudaGetSymbolAddress((void**)&p_ql,     g_qlo);
    cudaGetSymbolAddress((void**)&p_kTh,    g_kThi);
    cudaGetSymbolAddress((void**)&p_kTl,    g_kTlo);
    cudaGetSymbolAddress((void**)&p_vTh,    g_vThi);
    cudaGetSymbolAddress((void**)&p_vTl,    g_vTlo);
    cudaGetSymbolAddress((void**)&p_ath,    g_attThi);
    cudaGetSymbolAddress((void**)&p_atl,    g_attTlo);
    cudaGetSymbolAddress((void**)&p_attp,   g_att_part);
    cudaGetSymbolAddress((void**)&p_emba,   g_emb_act);
    cudaGetSymbolAddress((void**)&p_embout, g_embout);

    cudaFuncSetAttribute(hgemm_k, cudaFuncAttributeMaxDynamicSharedMemorySize, HG_SMEM);
    cudaFuncSetAttribute(att1_k,  cudaFuncAttributeMaxDynamicSharedMemorySize, ATT_SMEM);
    cudaFuncSetAttribute(att2_k,  cudaFuncAttributeMaxDynamicSharedMemorySize, ATT_SMEM);

    wsplit4_k<<<dim3(32,32,4), dim3(32,32)>>>(Wq, Wk, Wv, W_out, p_wt);
    ln_kernel<<<MM, 256>>>(x, ln_w, ln_b, p_xn);
    silu_emb_k<<<(BB*TEE)/256, 256>>>(emb, p_emba);

    // QKV fused: grid.z = 3 selects weight slice + epilogue
    hgemm_k<<<dim3(DD/128, MM/64, 3), 128, HG_SMEM>>>(
        p_xn, p_wt,
        bq, bk, bv, mask, nullptr, p_k, p_qh, p_ql, p_vTh, p_vTl, -1);

    ksoftmaxT_k<<<BB*32, dim3(32,8)>>>(p_k, p_kTh, p_kTl);

    att1_k<<<dim3(NCHUNK, BB*HH), 512, ATT_SMEM>>>(p_vTh, p_vTl, p_kTh, p_kTl, p_attp);
    att_reduce_k<<<(BB*HH*DHH*DHH)/256, 256>>>(p_attp, p_ath, p_atl);

    emb_gemm_k<<<dim3((2*DD)/256, BB), 256>>>(p_emba, W_emb, b_emb, p_embout);

    att2_k<<<dim3(MM/128, HH), 512, ATT_SMEM>>>(p_qh, p_ql, p_ath, p_atl, p_y);

    film_k<<<MM, 256>>>(p_y, ln2_w, ln2_b, p_embout, p_act);

    // OUT projection (+residual)
    hgemm_k<<<dim3(DD/128, MM/64, 1), 128, HG_SMEM>>>(
        p_act, p_wt + 3*(size_t)DD*DD,
        b_out, nullptr, nullptr, nullptr, x, out, nullptr, nullptr, nullptr, nullptr, 3);
}

// round 15
// speedup vs baseline: 1.5116x; 1.0194x over previous
#include <cuda_runtime.h>
#include <cuda_bf16.h>
#include <math.h>
#include <stdint.h>

#define BB 4
#define TT 2048
#define DD 1024
#define HH 8
#define DHH 128
#define TEE 2048
#define MM (BB*TT)          // 8192 rows
#define NCHUNK 8            // att1 t-chunks (256 t per block)

__device__ __forceinline__ uint32_t smem_to_u32(const void* p) {
    uint32_t a;
    asm("{ .reg .u64 t; cvta.to.shared.u64 t, %1; cvt.u32.u64 %0, t; }" : "=r"(a) : "l"(p));
    return a;
}
__device__ __forceinline__ float to_tf32(float v) {
    uint32_t u;
    asm("cvt.rna.tf32.f32 %0, %1;" : "=r"(u) : "f"(v));
    return __uint_as_float(u);
}

#define LDSM4(R, addr) \
    asm volatile("ldmatrix.sync.aligned.m8n8.x4.shared.b16 {%0,%1,%2,%3}, [%4];" \
        : "=r"((R)[0]), "=r"((R)[1]), "=r"((R)[2]), "=r"((R)[3]) : "r"(addr))

#define MMA_TF32(c, a, b0, b1) \
    asm volatile("mma.sync.aligned.m16n8k8.row.col.f32.tf32.tf32.f32 " \
        "{%0,%1,%2,%3}, {%4,%5,%6,%7}, {%8,%9}, {%0,%1,%2,%3};" \
        : "+f"((c)[0]), "+f"((c)[1]), "+f"((c)[2]), "+f"((c)[3]) \
        : "r"((a)[0]), "r"((a)[1]), "r"((a)[2]), "r"((a)[3]), "r"(b0), "r"(b1))

#define CP16(dst, src) \
    asm volatile("cp.async.cg.shared.global [%0], [%1], 16;" :: "r"(dst), "l"(src))
#define CP_COMMIT() asm volatile("cp.async.commit_group;")
#define CP_WAIT1()  asm volatile("cp.async.wait_group 1;")

// ======================= device scratch =======================
__device__ float g_xn [MM*DD];          // tf32-rounded LN output
__device__ float g_act[MM*DD];          // tf32-rounded FiLM output
__device__ float g_wt [4][DD*DD];       // tf32-rounded transposed weights
__device__ float g_k  [MM*DD];
__device__ float g_y  [MM*DD];
__device__ float g_q  [MM*DD];          // tf32 softmaxed q
__device__ float g_kT [MM*DD];          // tf32 kT [b,h,d,t]
__device__ float g_vT [MM*DD];          // tf32 vT [b,h,l,t]
__device__ float g_att_part[NCHUNK*BB*HH*DHH*DHH];
__device__ float g_attT[BB*HH*DHH*DHH]; // tf32 attT [b,h,l,d]
__device__ float g_emb_act[BB*TEE];
__device__ float g_embout[BB*2*DD];

// ======================= LayerNorm -> tf32 fp32 =======================
__global__ __launch_bounds__(256) void ln_kernel(const float* __restrict__ x,
                                                 const float* __restrict__ w,
                                                 const float* __restrict__ b,
                                                 float* __restrict__ outx)
{
    int row = blockIdx.x;
    int tid = threadIdx.x;
    const float4* xr = (const float4*)(x + (size_t)row*DD);
    float4 v = xr[tid];
    float s  = v.x+v.y+v.z+v.w;
    float ss = v.x*v.x+v.y*v.y+v.z*v.z+v.w*v.w;
    #pragma unroll
    for (int o=16;o>0;o>>=1){ s += __shfl_down_sync(0xffffffffu,s,o); ss += __shfl_down_sync(0xffffffffu,ss,o); }
    __shared__ float sm[8], sm2[8];
    int wid = tid>>5, lane = tid&31;
    if (lane==0){ sm[wid]=s; sm2[wid]=ss; }
    __syncthreads();
    if (tid==0){
        float a=0.f, c=0.f;
        #pragma unroll
        for (int i=0;i<8;i++){ a+=sm[i]; c+=sm2[i]; }
        float mean = a*(1.0f/DD);
        float var  = c*(1.0f/DD) - mean*mean;
        sm[0]=mean; sm2[0]=rsqrtf(var+1e-5f);
    }
    __syncthreads();
    float mean=sm[0], rinv=sm2[0];
    float4 wv=((const float4*)w)[tid];
    float4 bv=((const float4*)b)[tid];
    float4 o;
    o.x=to_tf32((v.x-mean)*rinv*wv.x+bv.x);
    o.y=to_tf32((v.y-mean)*rinv*wv.y+bv.y);
    o.z=to_tf32((v.z-mean)*rinv*wv.z+bv.z);
    o.w=to_tf32((v.w-mean)*rinv*wv.w+bv.w);
    ((float4*)(outx + (size_t)row*DD))[tid]=o;
}

// ======================= weight transpose -> tf32 fp32 ======================
__global__ __launch_bounds__(1024) void wsplit4_k(const float* __restrict__ W0,
                                                  const float* __restrict__ W1,
                                                  const float* __restrict__ W2,
                                                  const float* __restrict__ W3,
                                                  float* __restrict__ Wt)
{
    __shared__ float t[32][33];
    int tx = threadIdx.x, ty = threadIdx.y;
    int wsel = blockIdx.z;
    const float* W = (wsel==0)?W0:(wsel==1)?W1:(wsel==2)?W2:W3;
    t[ty][tx] = W[(size_t)(blockIdx.y*32+ty)*DD + blockIdx.x*32+tx];
    __syncthreads();
    int n = blockIdx.x*32 + ty;
    int k = blockIdx.y*32 + tx;
    Wt[(size_t)wsel*DD*DD + (size_t)n*DD + k] = to_tf32(t[tx][ty]);
}

// ======================= TF32 GEMM, BM=64 BN=128, 4 warps, 3 CTAs/SM ========
#define LDSB    144                       // smem row stride in BYTES
#define TA_B    (64*LDSB)                 // 9216 B (A tile)
#define TB_B    (128*LDSB)                // 18432 B (B tile)
#define STAGE_B (TA_B + TB_B)             // 27648 B per stage
#define HG_SMEM (2*STAGE_B)               // 55296 B

__global__ __launch_bounds__(128, 3) void hgemm_k(
        const float* __restrict__ A,
        const float* __restrict__ Wt,
        const float* __restrict__ bias0, const float* __restrict__ bias1,
        const float* __restrict__ bias2,
        const float* __restrict__ mask,
        const float* __restrict__ resid, float* __restrict__ C,
        float* __restrict__ Qf, float* __restrict__ Vt,
        int mode_ov)
{
    extern __shared__ float smbuf[];
    const int tid  = threadIdx.x;
    const int lane = tid & 31;
    const int w    = tid >> 5;      // 0..3
    const int wm   = w >> 1;        // 0..1 : 32 rows
    const int wn   = w & 1;         // 0..1 : 64 cols
    const int m0 = blockIdx.y * 64;
    const int n0 = blockIdx.x * 128;
    const int mode = (mode_ov >= 0) ? mode_ov : (int)blockIdx.z;
    const int wsel = (mode_ov >= 0) ? 0 : (int)blockIdx.z;
    const float* bias = (mode == 1) ? bias1 : (mode == 2) ? bias2 : bias0;
    const float* B = Wt + (size_t)wsel*DD*DD;

    const uint32_t smb = smem_to_u32(smbuf);
    const uint32_t dA = smb;
    const uint32_t dB = smb + TA_B;

    const int arow = wm*32 + (lane & 7) + ((lane >> 3) & 1) * 8;     // +mt*16
    const int akb  = ((lane >> 4) & 1) * 16;
    const int brow = wn*64 + ((lane >> 4) & 1) * 8 + (lane & 7);     // +nb*16
    const int bkb  = ((lane >> 3) & 1) * 16;

    float acc[2][8][4];
    #pragma unroll
    for (int i=0;i<2;i++)
        #pragma unroll
        for (int j=0;j<8;j++)
            #pragma unroll
            for (int l=0;l<4;l++) acc[i][j][l]=0.f;

    #pragma unroll
    for (int s = 0; s < 2; s++) {
        int k0 = s*32;
        uint32_t so = s*STAGE_B;
        #pragma unroll
        for (int i = 0; i < 4; i++) {
            int idx = tid + i*128;
            int r = idx >> 3, ch = idx & 7;
            CP16(dA + so + (uint32_t)(r*LDSB + ch*16), A + (size_t)(m0+r)*DD + k0 + ch*4);
        }
        #pragma unroll
        for (int i = 0; i < 8; i++) {
            int idx = tid + i*128;
            int r = idx >> 3, ch = idx & 7;
            CP16(dB + so + (uint32_t)(r*LDSB + ch*16), B + (size_t)(n0+r)*DD + k0 + ch*4);
        }
        CP_COMMIT();
    }

    for (int kc = 0; kc < 32; kc++) {
        CP_WAIT1();
        __syncthreads();

        uint32_t baseA = smb + (kc & 1)*STAGE_B;
        uint32_t baseB = baseA + TA_B;
        #pragma unroll
        for (int ks = 0; ks < 4; ks++) {
            uint32_t a[2][4];
            #pragma unroll
            for (int mt = 0; mt < 2; mt++) {
                uint32_t ra = baseA + (uint32_t)((arow + mt*16)*LDSB + akb + ks*32);
                LDSM4(a[mt], ra);
            }
            uint32_t bf[4][4];
            #pragma unroll
            for (int nb = 0; nb < 4; nb++) {
                uint32_t rb = baseB + (uint32_t)((brow + nb*16)*LDSB + bkb + ks*32);
                LDSM4(bf[nb], rb);
            }
            #pragma unroll
            for (int mt = 0; mt < 2; mt++)
                #pragma unroll
                for (int nb = 0; nb < 4; nb++) {
                    MMA_TF32(acc[mt][nb*2],   a[mt], bf[nb][0], bf[nb][1]);
                    MMA_TF32(acc[mt][nb*2+1], a[mt], bf[nb][2], bf[nb][3]);
                }
        }

        __syncthreads();
        if (kc + 2 < 32) {
            int k0 = (kc+2)*32;
            uint32_t so = (kc & 1)*STAGE_B;
            #pragma unroll
            for (int i = 0; i < 4; i++) {
                int idx = tid + i*128;
                int r = idx >> 3, ch = idx & 7;
                CP16(dA + so + (uint32_t)(r*LDSB + ch*16), A + (size_t)(m0+r)*DD + k0 + ch*4);
            }
            #pragma unroll
            for (int i = 0; i < 8; i++) {
                int idx = tid + i*128;
                int r = idx >> 3, ch = idx & 7;
                CP16(dB + so + (uint32_t)(r*LDSB + ch*16), B + (size_t)(n0+r)*DD + k0 + ch*4);
            }
        }
        CP_COMMIT();
    }

    const int t4 = lane >> 2;
    const int t2 = (lane & 3) * 2;

    #pragma unroll
    for (int mt = 0; mt < 2; mt++)
        #pragma unroll
        for (int nt = 0; nt < 8; nt++) {
            int col = n0 + wn*64 + nt*8 + t2;
            float2 bi = *(const float2*)(bias + col);
            acc[mt][nt][0] += bi.x; acc[mt][nt][1] += bi.y;
            acc[mt][nt][2] += bi.x; acc[mt][nt][3] += bi.y;
        }

    if (mode == 0) {
        // fused softmax over 128 cols (one head), 64 rows -> Qf (tf32 fp32)
        __syncthreads();
        float* red  = smbuf;
        float* red2 = smbuf + 128;
        float mrow[2][2];
        #pragma unroll
        for (int mt = 0; mt < 2; mt++) {
            float a0 = -1e30f, a1 = -1e30f;
            #pragma unroll
            for (int nt = 0; nt < 8; nt++) {
                a0 = fmaxf(a0, fmaxf(acc[mt][nt][0], acc[mt][nt][1]));
                a1 = fmaxf(a1, fmaxf(acc[mt][nt][2], acc[mt][nt][3]));
            }
            a0 = fmaxf(a0, __shfl_xor_sync(0xffffffffu, a0, 1));
            a0 = fmaxf(a0, __shfl_xor_sync(0xffffffffu, a0, 2));
            a1 = fmaxf(a1, __shfl_xor_sync(0xffffffffu, a1, 1));
            a1 = fmaxf(a1, __shfl_xor_sync(0xffffffffu, a1, 2));
            if ((lane & 3) == 0) {
                int r = wm*32 + mt*16 + t4;
                red[r*2 + wn] = a0;
                red[(r+8)*2 + wn] = a1;
            }
        }
        __syncthreads();
        #pragma unroll
        for (int mt = 0; mt < 2; mt++) {
            int r = wm*32 + mt*16 + t4;
            mrow[mt][0] = fmaxf(red[r*2+0], red[r*2+1]);
            mrow[mt][1] = fmaxf(red[(r+8)*2+0], red[(r+8)*2+1]);
        }
        float srow[2][2];
        #pragma unroll
        for (int mt = 0; mt < 2; mt++) {
            float s0 = 0.f, s1 = 0.f;
            #pragma unroll
            for (int nt = 0; nt < 8; nt++) {
                acc[mt][nt][0] = expf(acc[mt][nt][0] - mrow[mt][0]);
                acc[mt][nt][1] = expf(acc[mt][nt][1] - mrow[mt][0]);
                acc[mt][nt][2] = expf(acc[mt][nt][2] - mrow[mt][1]);
                acc[mt][nt][3] = expf(acc[mt][nt][3] - mrow[mt][1]);
                s0 += acc[mt][nt][0] + acc[mt][nt][1];
                s1 += acc[mt][nt][2] + acc[mt][nt][3];
            }
            s0 += __shfl_xor_sync(0xffffffffu, s0, 1);
            s0 += __shfl_xor_sync(0xffffffffu, s0, 2);
            s1 += __shfl_xor_sync(0xffffffffu, s1, 1);
            s1 += __shfl_xor_sync(0xffffffffu, s1, 2);
            if ((lane & 3) == 0) {
                int r = wm*32 + mt*16 + t4;
                red2[r*2 + wn] = s0;
                red2[(r+8)*2 + wn] = s1;
            }
        }
        __syncthreads();
        #pragma unroll
        for (int mt = 0; mt < 2; mt++) {
            int r = wm*32 + mt*16 + t4;
            srow[mt][0] = 1.0f / (red2[r*2+0] + red2[r*2+1]);
            srow[mt][1] = 1.0f / (red2[(r+8)*2+0] + red2[(r+8)*2+1]);
        }
        #pragma unroll
        for (int mt = 0; mt < 2; mt++) {
            int row0 = m0 + wm*32 + mt*16 + t4;
            int row1 = row0 + 8;
            #pragma unroll
            for (int nt = 0; nt < 8; nt++) {
                int col = n0 + wn*64 + nt*8 + t2;
                float v0 = to_tf32(acc[mt][nt][0] * srow[mt][0]);
                float v1 = to_tf32(acc[mt][nt][1] * srow[mt][0]);
                float v2 = to_tf32(acc[mt][nt][2] * srow[mt][1]);
                float v3 = to_tf32(acc[mt][nt][3] * srow[mt][1]);
                *(float2*)(Qf + (size_t)row0*DD + col) = make_float2(v0, v1);
                *(float2*)(Qf + (size_t)row1*DD + col) = make_float2(v2, v3);
            }
        }
        return;
    }

    if (mode == 2) {
        // V projection: (acc+bias)*mask -> transposed vT[b][h][l][t] (tf32 fp32)
        #pragma unroll
        for (int mt = 0; mt < 2; mt++) {
            int row0 = m0 + wm*32 + mt*16 + t4;
            int row1 = row0 + 8;
            float m0v = mask[row0], m1v = mask[row1];
            int b0 = row0 >> 11, tt0 = row0 & (TT-1);
            int b1 = row1 >> 11, tt1 = row1 & (TT-1);
            #pragma unroll
            for (int nt = 0; nt < 8; nt++) {
                int col = n0 + wn*64 + nt*8 + t2;
                int h = col >> 7, l = col & 127;
                size_t i00 = ((size_t)(b0*HH + h)*DHH + l)*TT + tt0;
                size_t i10 = ((size_t)(b1*HH + h)*DHH + l)*TT + tt1;
                Vt[i00]      = to_tf32(acc[mt][nt][0] * m0v);
                Vt[i00 + TT] = to_tf32(acc[mt][nt][1] * m0v);
                Vt[i10]      = to_tf32(acc[mt][nt][2] * m1v);
                Vt[i10 + TT] = to_tf32(acc[mt][nt][3] * m1v);
            }
        }
        return;
    }

    #pragma unroll
    for (int mt = 0; mt < 2; mt++) {
        int row0 = m0 + wm*32 + mt*16 + t4;
        int row1 = row0 + 8;
        float m0v = 0.f, m1v = 0.f;
        if (mode == 1) { m0v = mask[row0]; m1v = mask[row1]; }
        float add0 = (mode==1) ? (1.0f-m0v)*(-1000000.0f) : 0.f;
        float add1 = (mode==1) ? (1.0f-m1v)*(-1000000.0f) : 0.f;
        #pragma unroll
        for (int nt = 0; nt < 8; nt++) {
            int col = n0 + wn*64 + nt*8 + t2;
            float a0 = acc[mt][nt][0];
            float a1 = acc[mt][nt][1];
            float a2 = acc[mt][nt][2];
            float a3 = acc[mt][nt][3];
            if (mode == 1) { a0 += add0; a1 += add0; a2 += add1; a3 += add1; }
            else if (mode == 3) {
                float2 r0 = *(const float2*)(resid + (size_t)row0*DD + col);
                float2 r1 = *(const float2*)(resid + (size_t)row1*DD + col);
                a0 += r0.x; a1 += r0.y; a2 += r1.x; a3 += r1.y;
            }
            *(float2*)(C + (size_t)row0*DD + col) = make_float2(a0, a1);
            *(float2*)(C + (size_t)row1*DD + col) = make_float2(a2, a3);
        }
    }
}

// ======================= softmax over time -> transposed tf32 fp32 ==========
__global__ void ksoftmaxT_k(const float* __restrict__ k,
                            float* __restrict__ kT)
{
    int b = blockIdx.x >> 5;
    int g = blockIdx.x & 31;
    int tx = threadIdx.x, ty = threadIdx.y;
    int d = g*32 + tx;
    float m = -INFINITY, s = 0.f;
    for (int t=ty; t<TT; t+=8){
        float val = k[((size_t)b*TT + t)*DD + d];
        float nm = fmaxf(m, val);
        s = s*expf(m-nm) + expf(val-nm);
        m = nm;
    }
    __shared__ float smax[8][32], ssum[8][32];
    smax[ty][tx]=m; ssum[ty][tx]=s;
    __syncthreads();
    if (ty==0){
        float M=smax[0][tx], S=ssum[0][tx];
        #pragma unroll
        for (int i=1;i<8;i++){
            float m2=smax[i][tx], s2=ssum[i][tx];
            float nm=fmaxf(M,m2);
            S = S*expf(M-nm) + s2*expf(m2-nm);
            M = nm;
        }
        smax[0][tx]=M; ssum[0][tx]=1.0f/S;
    }
    __syncthreads();
    float M=smax[0][tx], R=ssum[0][tx];
    __syncthreads();

    __shared__ float sh[32][33];
    int dg0 = g*32;
    int h = dg0 >> 7;
    int dl0 = dg0 & 127;
    size_t kbase = ((size_t)(b*HH + h))*DHH + dl0;

    for (int t0 = 0; t0 < TT; t0 += 32) {
        #pragma unroll
        for (int i = 0; i < 4; i++) {
            int t = t0 + ty + i*8;
            sh[tx][ty + i*8] = to_tf32(expf(k[((size_t)b*TT + t)*DD + d] - M) * R);
        }
        __syncthreads();
        #pragma unroll
        for (int i = 0; i < 4; i++) {
            int row = ty + i*8;
            kT[(kbase + row)*TT + t0 + tx] = sh[row][tx];
        }
        __syncthreads();
    }
}

// ======================= attention core TF32 ================================
// smem row stride 272 B (68 floats): 16B-aligned, conflict-free ldmatrix
#define ALD    272
#define ATILE  (128*ALD)                  // 34816 B per tile
#define ATT_SMEM (2*ATILE)                // 69632 B

// att1: part[chunk][bh][l][d] = sum_{t in chunk} vT[l][t]*kT[d][t]
__global__ __launch_bounds__(512, 1) void att1_k(
        const float* __restrict__ vT, const float* __restrict__ kT,
        float* __restrict__ part)
{
    extern __shared__ float smf[];
    const int tid  = threadIdx.x;
    const int lane = tid & 31;
    const int w    = tid >> 5;
    const int wm   = w >> 2;        // 0..3 : 32 l-rows
    const int wn   = w & 3;         // 0..3 : 32 d-cols
    const int chunk = blockIdx.x;   // 0..7 (256 t each)
    const int bh    = blockIdx.y;

    const uint32_t smb = smem_to_u32(smf);
    const int arow = wm*32 + (lane & 7) + ((lane >> 3) & 1) * 8;   // +mt*16
    const int akb  = ((lane >> 4) & 1) * 16;
    const int brow = wn*32 + ((lane >> 4) & 1) * 8 + (lane & 7);   // +nb*16
    const int bkb  = ((lane >> 3) & 1) * 16;

    float acc[2][4][4];
    #pragma unroll
    for (int i=0;i<2;i++)
        #pragma unroll
        for (int j=0;j<4;j++)
            #pragma unroll
            for (int l=0;l<4;l++) acc[i][j][l]=0.f;

    for (int sub = 0; sub < 4; sub++) {
        int t0 = chunk*256 + sub*64;
        // load 2 tiles: vT[128][64], kT[128][64]
        #pragma unroll
        for (int i = 0; i < 4; i++) {
            int idx = tid + i*512;          // 0..2047
            int r = idx >> 4, ch = idx & 15;
            size_t gv = ((size_t)bh*DHH + r)*TT + t0 + ch*4;
            *(float4*)((char*)smf + r*ALD + ch*16)          = *(const float4*)(vT + gv);
            *(float4*)((char*)smf + ATILE + r*ALD + ch*16)  = *(const float4*)(kT + gv);
        }
        __syncthreads();

        #pragma unroll
        for (int ks = 0; ks < 8; ks++) {
            uint32_t a[2][4];
            #pragma unroll
            for (int mt = 0; mt < 2; mt++) {
                uint32_t ra = smb + (uint32_t)((arow + mt*16)*ALD + akb + ks*32);
                LDSM4(a[mt], ra);
            }
            uint32_t bf[2][4];
            #pragma unroll
            for (int nb = 0; nb < 2; nb++) {
                uint32_t rb = smb + ATILE + (uint32_t)((brow + nb*16)*ALD + bkb + ks*32);
                LDSM4(bf[nb], rb);
            }
            #pragma unroll
            for (int mt = 0; mt < 2; mt++)
                #pragma unroll
                for (int nb = 0; nb < 2; nb++) {
                    MMA_TF32(acc[mt][nb*2],   a[mt], bf[nb][0], bf[nb][1]);
                    MMA_TF32(acc[mt][nb*2+1], a[mt], bf[nb][2], bf[nb][3]);
                }
        }
        __syncthreads();
    }

    float* dst = part + ((size_t)(chunk*(BB*HH) + bh))*(DHH*DHH);
    const int t4 = lane >> 2;
    const int t2 = (lane & 3) * 2;
    #pragma unroll
    for (int mt = 0; mt < 2; mt++) {
        int row0 = wm*32 + mt*16 + t4;
        int row1 = row0 + 8;
        #pragma unroll
        for (int nt = 0; nt < 4; nt++) {
            int col = wn*32 + nt*8 + t2;
            *(float2*)(dst + row0*DHH + col) = make_float2(acc[mt][nt][0], acc[mt][nt][1]);
            *(float2*)(dst + row1*DHH + col) = make_float2(acc[mt][nt][2], acc[mt][nt][3]);
        }
    }
}

__global__ void att_reduce_k(const float* __restrict__ part,
                             float* __restrict__ attT)
{
    int i = blockIdx.x*256 + threadIdx.x;
    float s = 0.f;
    #pragma unroll
    for (int c=0;c<NCHUNK;c++) s += part[(size_t)c*(BB*HH*DHH*DHH) + i];
    attT[i] = to_tf32(s);
}

// att2: y[t][h*128+l] = sum_d q[t][h*128+d]*attT[l][d]
__global__ __launch_bounds__(512, 1) void att2_k(
        const float* __restrict__ q,
        const float* __restrict__ attT,
        float* __restrict__ y)
{
    extern __shared__ float smf[];
    const int tid  = threadIdx.x;
    const int lane = tid & 31;
    const int w    = tid >> 5;
    const int wm   = w >> 2;
    const int wn   = w & 3;
    const int m0 = blockIdx.x * 128;
    const int h  = blockIdx.y;
    const int bh = (m0 >> 11) * HH + h;

    const uint32_t smb = smem_to_u32(smf);
    const int arow = wm*32 + (lane & 7) + ((lane >> 3) & 1) * 8;
    const int akb  = ((lane >> 4) & 1) * 16;
    const int brow = wn*32 + ((lane >> 4) & 1) * 8 + (lane & 7);
    const int bkb  = ((lane >> 3) & 1) * 16;

    float acc[2][4][4];
    #pragma unroll
    for (int i=0;i<2;i++)
        #pragma unroll
        for (int j=0;j<4;j++)
            #pragma unroll
            for (int l=0;l<4;l++) acc[i][j][l]=0.f;

    for (int sub = 0; sub < 2; sub++) {
        int d0 = sub*64;
        #pragma unroll
        for (int i = 0; i < 4; i++) {
            int idx = tid + i*512;
            int r = idx >> 4, ch = idx & 15;
            size_t ga = (size_t)(m0 + r)*DD + h*DHH + d0 + ch*4;
            size_t gb = ((size_t)bh*DHH + r)*DHH + d0 + ch*4;
            *(float4*)((char*)smf + r*ALD + ch*16)          = *(const float4*)(q + ga);
            *(float4*)((char*)smf + ATILE + r*ALD + ch*16)  = *(const float4*)(attT + gb);
        }
        __syncthreads();

        #pragma unroll
        for (int ks = 0; ks < 8; ks++) {
            uint32_t a[2][4];
            #pragma unroll
            for (int mt = 0; mt < 2; mt++) {
                uint32_t ra = smb + (uint32_t)((arow + mt*16)*ALD + akb + ks*32);
                LDSM4(a[mt], ra);
            }
            uint32_t bf[2][4];
            #pragma unroll
            for (int nb = 0; nb < 2; nb++) {
                uint32_t rb = smb + ATILE + (uint32_t)((brow + nb*16)*ALD + bkb + ks*32);
                LDSM4(bf[nb], rb);
            }
            #pragma unroll
            for (int mt = 0; mt < 2; mt++)
                #pragma unroll
                for (int nb = 0; nb < 2; nb++) {
                    MMA_TF32(acc[mt][nb*2],   a[mt], bf[nb][0], bf[nb][1]);
                    MMA_TF32(acc[mt][nb*2+1], a[mt], bf[nb][2], bf[nb][3]);
                }
        }
        __syncthreads();
    }

    const int t4 = lane >> 2;
    const int t2 = (lane & 3) * 2;
    #pragma unroll
    for (int mt = 0; mt < 2; mt++) {
        int row0 = m0 + wm*32 + mt*16 + t4;
        int row1 = row0 + 8;
        #pragma unroll
        for (int nt = 0; nt < 4; nt++) {
            int col = h*DHH + wn*32 + nt*8 + t2;
            *(float2*)(y + (size_t)row0*DD + col) = make_float2(acc[mt][nt][0], acc[mt][nt][1]);
            *(float2*)(y + (size_t)row1*DD + col) = make_float2(acc[mt][nt][2], acc[mt][nt][3]);
        }
    }
}

// ======================= emb path =======================
__global__ void silu_emb_k(const float* __restrict__ emb, float* __restrict__ out)
{
    int i = blockIdx.x*256 + threadIdx.x;
    float e = emb[i];
    out[i] = e / (1.0f + expf(-e));
}

__global__ __launch_bounds__(256) void emb_gemm_k(const float* __restrict__ ea,
                                                  const float* __restrict__ W,
                                                  const float* __restrict__ bias,
                                                  float* __restrict__ out)
{
    int n = blockIdx.x*256 + threadIdx.x;
    int b = blockIdx.y;
    const float* e = ea + b*TEE;
    float acc = 0.f;
    #pragma unroll 8
    for (int t=0;t<TEE;t++)
        acc = fmaf(e[t], W[(size_t)t*(2*DD) + n], acc);
    out[b*(2*DD) + n] = acc + bias[n];
}

// ======================= LN2 + FiLM + SiLU -> tf32 fp32 =====================
__global__ __launch_bounds__(256) void film_k(const float* __restrict__ y,
                                              const float* __restrict__ w2,
                                              const float* __restrict__ b2,
                                              const float* __restrict__ embout,
                                              float* __restrict__ act)
{
    int row = blockIdx.x;
    int b = row / TT;
    int tid = threadIdx.x;
    const float4* yr = (const float4*)(y + (size_t)row*DD);
    float4 v = yr[tid];
    float s  = v.x+v.y+v.z+v.w;
    float ss = v.x*v.x+v.y*v.y+v.z*v.z+v.w*v.w;
    #pragma unroll
    for (int o=16;o>0;o>>=1){ s += __shfl_down_sync(0xffffffffu,s,o); ss += __shfl_down_sync(0xffffffffu,ss,o); }
    __shared__ float sm[8], sm2[8];
    int wid = tid>>5, lane = tid&31;
    if (lane==0){ sm[wid]=s; sm2[wid]=ss; }
    __syncthreads();
    if (tid==0){
        float a=0.f, c=0.f;
        #pragma unroll
        for (int i=0;i<8;i++){ a+=sm[i]; c+=sm2[i]; }
        float mean = a*(1.0f/DD);
        float var  = c*(1.0f/DD) - mean*mean;
        sm[0]=mean; sm2[0]=rsqrtf(var+1e-5f);
    }
    __syncthreads();
    float mean=sm[0], rinv=sm2[0];
    float4 wv=((const float4*)w2)[tid];
    float4 bv=((const float4*)b2)[tid];
    float4 sc=((const float4*)(embout + (size_t)b*(2*DD)))[tid];
    float4 sh=((const float4*)(embout + (size_t)b*(2*DD) + DD))[tid];
    float4 o;
    float h;
    h=(v.x-mean)*rinv*wv.x+bv.x; h=h*(1.0f+sc.x)+sh.x; o.x=to_tf32(h/(1.0f+expf(-h)));
    h=(v.y-mean)*rinv*wv.y+bv.y; h=h*(1.0f+sc.y)+sh.y; o.y=to_tf32(h/(1.0f+expf(-h)));
    h=(v.z-mean)*rinv*wv.z+bv.z; h=h*(1.0f+sc.z)+sh.z; o.z=to_tf32(h/(1.0f+expf(-h)));
    h=(v.w-mean)*rinv*wv.w+bv.w; h=h*(1.0f+sc.w)+sh.w; o.w=to_tf32(h/(1.0f+expf(-h)));
    ((float4*)(act + (size_t)row*DD))[tid]=o;
}

// ======================= launch =======================
extern "C" void kernel_launch(void* const* d_in, const int* in_sizes, int n_in,
                              void* d_out, int out_size)
{
    (void)in_sizes; (void)n_in; (void)out_size;
    const float* x     = (const float*)d_in[0];
    const float* emb   = (const float*)d_in[1];
    const float* mask  = (const float*)d_in[2];
    const float* ln_w  = (const float*)d_in[4];
    const float* ln_b  = (const float*)d_in[5];
    const float* Wq    = (const float*)d_in[6];
    const float* bq    = (const float*)d_in[7];
    const float* Wk    = (const float*)d_in[8];
    const float* bk    = (const float*)d_in[9];
    const float* Wv    = (const float*)d_in[10];
    const float* bv    = (const float*)d_in[11];
    const float* W_emb = (const float*)d_in[12];
    const float* b_emb = (const float*)d_in[13];
    const float* ln2_w = (const float*)d_in[14];
    const float* ln2_b = (const float*)d_in[15];
    const float* W_out = (const float*)d_in[16];
    const float* b_out = (const float*)d_in[17];
    float* out = (float*)d_out;

    float *p_xn, *p_act, *p_wt, *p_k, *p_y, *p_q, *p_kT, *p_vT, *p_attp, *p_attT, *p_emba, *p_embout;
    cudaGetSymbolAddress((void**)&p_xn,     g_xn);
    cudaGetSymbolAddress((void**)&p_act,    g_act);
    cudaGetSymbolAddress((void**)&p_wt,     g_wt);
    cudaGetSymbolAddress((void**)&p_k,      g_k);
    cudaGetSymbolAddress((void**)&p_y,      g_y);
    cudaGetSymbolAddress((void**)&p_q,      g_q);
    cudaGetSymbolAddress((void**)&p_kT,     g_kT);
    cudaGetSymbolAddress((void**)&p_vT,     g_vT);
    cudaGetSymbolAddress((void**)&p_attp,   g_att_part);
    cudaGetSymbolAddress((void**)&p_attT,   g_attT);
    cudaGetSymbolAddress((void**)&p_emba,   g_emb_act);
    cudaGetSymbolAddress((void**)&p_embout, g_embout);

    cudaFuncSetAttribute(hgemm_k, cudaFuncAttributeMaxDynamicSharedMemorySize, HG_SMEM);
    cudaFuncSetAttribute(att1_k,  cudaFuncAttributeMaxDynamicSharedMemorySize, ATT_SMEM);
    cudaFuncSetAttribute(att2_k,  cudaFuncAttributeMaxDynamicSharedMemorySize, ATT_SMEM);

    wsplit4_k<<<dim3(32,32,4), dim3(32,32)>>>(Wq, Wk, Wv, W_out, p_wt);
    ln_kernel<<<MM, 256>>>(x, ln_w, ln_b, p_xn);
    silu_emb_k<<<(BB*TEE)/256, 256>>>(emb, p_emba);

    // QKV fused: grid.z = 3 selects weight slice + epilogue
    hgemm_k<<<dim3(DD/128, MM/64, 3), 128, HG_SMEM>>>(
        p_xn, p_wt,
        bq, bk, bv, mask, nullptr, p_k, p_q, p_vT, -1);

    ksoftmaxT_k<<<BB*32, dim3(32,8)>>>(p_k, p_kT);

    att1_k<<<dim3(NCHUNK, BB*HH), 512, ATT_SMEM>>>(p_vT, p_kT, p_attp);
    att_reduce_k<<<(BB*HH*DHH*DHH)/256, 256>>>(p_attp, p_attT);

    emb_gemm_k<<<dim3((2*DD)/256, BB), 256>>>(p_emba, W_emb, b_emb, p_embout);

    att2_k<<<dim3(MM/128, HH), 512, ATT_SMEM>>>(p_q, p_attT, p_y);

    film_k<<<MM, 256>>>(p_y, ln2_w, ln2_b, p_embout, p_act);

    // OUT projection (+residual)
    hgemm_k<<<dim3(DD/128, MM/64, 1), 128, HG_SMEM>>>(
        p_act, p_wt + 3*(size_t)DD*DD,
        b_out, nullptr, nullptr, nullptr, x, out, nullptr, nullptr, 3);
}

// round 16
// speedup vs baseline: 1.6646x; 1.1013x over previous
#include <cuda_runtime.h>
#include <cuda_bf16.h>
#include <math.h>
#include <stdint.h>

#define BB 4
#define TT 2048
#define DD 1024
#define HH 8
#define DHH 128
#define TEE 2048
#define MM (BB*TT)          // 8192 rows
#define NCHUNK 8            // att1 t-chunks (256 t per block)

__device__ __forceinline__ uint32_t smem_to_u32(const void* p) {
    uint32_t a;
    asm("{ .reg .u64 t; cvta.to.shared.u64 t, %1; cvt.u32.u64 %0, t; }" : "=r"(a) : "l"(p));
    return a;
}
__device__ __forceinline__ float to_tf32(float v) {
    uint32_t u;
    asm("cvt.rna.tf32.f32 %0, %1;" : "=r"(u) : "f"(v));
    return __uint_as_float(u);
}

#define LDSM4(R, addr) \
    asm volatile("ldmatrix.sync.aligned.m8n8.x4.shared.b16 {%0,%1,%2,%3}, [%4];" \
        : "=r"((R)[0]), "=r"((R)[1]), "=r"((R)[2]), "=r"((R)[3]) : "r"(addr))

#define MMA_TF32(c, a, b0, b1) \
    asm volatile("mma.sync.aligned.m16n8k8.row.col.f32.tf32.tf32.f32 " \
        "{%0,%1,%2,%3}, {%4,%5,%6,%7}, {%8,%9}, {%0,%1,%2,%3};" \
        : "+f"((c)[0]), "+f"((c)[1]), "+f"((c)[2]), "+f"((c)[3]) \
        : "r"((a)[0]), "r"((a)[1]), "r"((a)[2]), "r"((a)[3]), "r"(b0), "r"(b1))

#define CP16(dst, src) \
    asm volatile("cp.async.cg.shared.global [%0], [%1], 16;" :: "r"(dst), "l"(src))
#define CP_COMMIT() asm volatile("cp.async.commit_group;")
#define CP_WAIT1()  asm volatile("cp.async.wait_group 1;")

// ======================= device scratch =======================
__device__ float g_xn [MM*DD];          // tf32-rounded LN output
__device__ float g_act[MM*DD];          // tf32-rounded FiLM output
__device__ float g_wt [4][DD*DD];       // tf32-rounded transposed weights
__device__ float g_y  [MM*DD];
__device__ float g_q  [MM*DD];          // tf32 softmaxed q
__device__ float g_kT [MM*DD];          // RAW k logits transposed [b,h,d,t]
__device__ float g_vT [MM*DD];          // tf32 vT [b,h,l,t]
__device__ float g_kM [BB*HH*DHH];      // per-(b,h,d) max
__device__ float g_kR [BB*HH*DHH];      // per-(b,h,d) 1/sum
__device__ float g_att_part[NCHUNK*BB*HH*DHH*DHH];
__device__ float g_attT[BB*HH*DHH*DHH]; // tf32 attT [b,h,l,d]
__device__ float g_emb_act[BB*TEE];
__device__ float g_embout[BB*2*DD];

// ======================= LayerNorm -> tf32 fp32 =======================
__global__ __launch_bounds__(256) void ln_kernel(const float* __restrict__ x,
                                                 const float* __restrict__ w,
                                                 const float* __restrict__ b,
                                                 float* __restrict__ outx)
{
    int row = blockIdx.x;
    int tid = threadIdx.x;
    const float4* xr = (const float4*)(x + (size_t)row*DD);
    float4 v = xr[tid];
    float s  = v.x+v.y+v.z+v.w;
    float ss = v.x*v.x+v.y*v.y+v.z*v.z+v.w*v.w;
    #pragma unroll
    for (int o=16;o>0;o>>=1){ s += __shfl_down_sync(0xffffffffu,s,o); ss += __shfl_down_sync(0xffffffffu,ss,o); }
    __shared__ float sm[8], sm2[8];
    int wid = tid>>5, lane = tid&31;
    if (lane==0){ sm[wid]=s; sm2[wid]=ss; }
    __syncthreads();
    if (tid==0){
        float a=0.f, c=0.f;
        #pragma unroll
        for (int i=0;i<8;i++){ a+=sm[i]; c+=sm2[i]; }
        float mean = a*(1.0f/DD);
        float var  = c*(1.0f/DD) - mean*mean;
        sm[0]=mean; sm2[0]=rsqrtf(var+1e-5f);
    }
    __syncthreads();
    float mean=sm[0], rinv=sm2[0];
    float4 wv=((const float4*)w)[tid];
    float4 bv=((const float4*)b)[tid];
    float4 o;
    o.x=to_tf32((v.x-mean)*rinv*wv.x+bv.x);
    o.y=to_tf32((v.y-mean)*rinv*wv.y+bv.y);
    o.z=to_tf32((v.z-mean)*rinv*wv.z+bv.z);
    o.w=to_tf32((v.w-mean)*rinv*wv.w+bv.w);
    ((float4*)(outx + (size_t)row*DD))[tid]=o;
}

// ======================= weight transpose -> tf32 fp32 ======================
__global__ __launch_bounds__(1024) void wsplit4_k(const float* __restrict__ W0,
                                                  const float* __restrict__ W1,
                                                  const float* __restrict__ W2,
                                                  const float* __restrict__ W3,
                                                  float* __restrict__ Wt)
{
    __shared__ float t[32][33];
    int tx = threadIdx.x, ty = threadIdx.y;
    int wsel = blockIdx.z;
    const float* W = (wsel==0)?W0:(wsel==1)?W1:(wsel==2)?W2:W3;
    t[ty][tx] = W[(size_t)(blockIdx.y*32+ty)*DD + blockIdx.x*32+tx];
    __syncthreads();
    int n = blockIdx.x*32 + ty;
    int k = blockIdx.y*32 + tx;
    Wt[(size_t)wsel*DD*DD + (size_t)n*DD + k] = to_tf32(t[tx][ty]);
}

// ======================= TF32 GEMM, BM=64 BN=128, 4 warps, 3 CTAs/SM ========
#define LDSB    144                       // smem row stride in BYTES
#define TA_B    (64*LDSB)                 // 9216 B (A tile)
#define TB_B    (128*LDSB)                // 18432 B (B tile)
#define STAGE_B (TA_B + TB_B)             // 27648 B per stage
#define HG_SMEM (2*STAGE_B)               // 55296 B

// mode 0: softmax-over-dh -> Qf
// mode 1: +bias+(1-mask)*-1e6 -> kT-raw transposed [b,h,d,t] (via C)
// mode 2: (+bias)*mask -> vT transposed [b,h,l,t] (via Vt)
// mode 3: +bias+resid -> C linear
__global__ __launch_bounds__(128, 3) void hgemm_k(
        const float* __restrict__ A,
        const float* __restrict__ Wt,
        const float* __restrict__ bias0, const float* __restrict__ bias1,
        const float* __restrict__ bias2,
        const float* __restrict__ mask,
        const float* __restrict__ resid, float* __restrict__ C,
        float* __restrict__ Qf, float* __restrict__ Vt,
        int mode_ov)
{
    extern __shared__ float smbuf[];
    const int tid  = threadIdx.x;
    const int lane = tid & 31;
    const int w    = tid >> 5;      // 0..3
    const int wm   = w >> 1;        // 0..1 : 32 rows
    const int wn   = w & 1;         // 0..1 : 64 cols
    const int m0 = blockIdx.y * 64;
    const int n0 = blockIdx.x * 128;
    const int mode = (mode_ov >= 0) ? mode_ov : (int)blockIdx.z;
    const int wsel = (mode_ov >= 0) ? 0 : (int)blockIdx.z;
    const float* bias = (mode == 1) ? bias1 : (mode == 2) ? bias2 : bias0;
    const float* B = Wt + (size_t)wsel*DD*DD;

    const uint32_t smb = smem_to_u32(smbuf);
    const uint32_t dA = smb;
    const uint32_t dB = smb + TA_B;

    const int arow = wm*32 + (lane & 7) + ((lane >> 3) & 1) * 8;     // +mt*16
    const int akb  = ((lane >> 4) & 1) * 16;
    const int brow = wn*64 + ((lane >> 4) & 1) * 8 + (lane & 7);     // +nb*16
    const int bkb  = ((lane >> 3) & 1) * 16;

    float acc[2][8][4];
    #pragma unroll
    for (int i=0;i<2;i++)
        #pragma unroll
        for (int j=0;j<8;j++)
            #pragma unroll
            for (int l=0;l<4;l++) acc[i][j][l]=0.f;

    #pragma unroll
    for (int s = 0; s < 2; s++) {
        int k0 = s*32;
        uint32_t so = s*STAGE_B;
        #pragma unroll
        for (int i = 0; i < 4; i++) {
            int idx = tid + i*128;
            int r = idx >> 3, ch = idx & 7;
            CP16(dA + so + (uint32_t)(r*LDSB + ch*16), A + (size_t)(m0+r)*DD + k0 + ch*4);
        }
        #pragma unroll
        for (int i = 0; i < 8; i++) {
            int idx = tid + i*128;
            int r = idx >> 3, ch = idx & 7;
            CP16(dB + so + (uint32_t)(r*LDSB + ch*16), B + (size_t)(n0+r)*DD + k0 + ch*4);
        }
        CP_COMMIT();
    }

    for (int kc = 0; kc < 32; kc++) {
        CP_WAIT1();
        __syncthreads();

        uint32_t baseA = smb + (kc & 1)*STAGE_B;
        uint32_t baseB = baseA + TA_B;
        #pragma unroll
        for (int ks = 0; ks < 4; ks++) {
            uint32_t a[2][4];
            #pragma unroll
            for (int mt = 0; mt < 2; mt++) {
                uint32_t ra = baseA + (uint32_t)((arow + mt*16)*LDSB + akb + ks*32);
                LDSM4(a[mt], ra);
            }
            uint32_t bf[4][4];
            #pragma unroll
            for (int nb = 0; nb < 4; nb++) {
                uint32_t rb = baseB + (uint32_t)((brow + nb*16)*LDSB + bkb + ks*32);
                LDSM4(bf[nb], rb);
            }
            #pragma unroll
            for (int mt = 0; mt < 2; mt++)
                #pragma unroll
                for (int nb = 0; nb < 4; nb++) {
                    MMA_TF32(acc[mt][nb*2],   a[mt], bf[nb][0], bf[nb][1]);
                    MMA_TF32(acc[mt][nb*2+1], a[mt], bf[nb][2], bf[nb][3]);
                }
        }

        __syncthreads();
        if (kc + 2 < 32) {
            int k0 = (kc+2)*32;
            uint32_t so = (kc & 1)*STAGE_B;
            #pragma unroll
            for (int i = 0; i < 4; i++) {
                int idx = tid + i*128;
                int r = idx >> 3, ch = idx & 7;
                CP16(dA + so + (uint32_t)(r*LDSB + ch*16), A + (size_t)(m0+r)*DD + k0 + ch*4);
            }
            #pragma unroll
            for (int i = 0; i < 8; i++) {
                int idx = tid + i*128;
                int r = idx >> 3, ch = idx & 7;
                CP16(dB + so + (uint32_t)(r*LDSB + ch*16), B + (size_t)(n0+r)*DD + k0 + ch*4);
            }
        }
        CP_COMMIT();
    }

    const int t4 = lane >> 2;
    const int t2 = (lane & 3) * 2;

    #pragma unroll
    for (int mt = 0; mt < 2; mt++)
        #pragma unroll
        for (int nt = 0; nt < 8; nt++) {
            int col = n0 + wn*64 + nt*8 + t2;
            float2 bi = *(const float2*)(bias + col);
            acc[mt][nt][0] += bi.x; acc[mt][nt][1] += bi.y;
            acc[mt][nt][2] += bi.x; acc[mt][nt][3] += bi.y;
        }

    if (mode == 0) {
        // fused softmax over 128 cols (one head), 64 rows -> Qf (tf32 fp32)
        __syncthreads();
        float* red  = smbuf;
        float* red2 = smbuf + 128;
        float mrow[2][2];
        #pragma unroll
        for (int mt = 0; mt < 2; mt++) {
            float a0 = -1e30f, a1 = -1e30f;
            #pragma unroll
            for (int nt = 0; nt < 8; nt++) {
                a0 = fmaxf(a0, fmaxf(acc[mt][nt][0], acc[mt][nt][1]));
                a1 = fmaxf(a1, fmaxf(acc[mt][nt][2], acc[mt][nt][3]));
            }
            a0 = fmaxf(a0, __shfl_xor_sync(0xffffffffu, a0, 1));
            a0 = fmaxf(a0, __shfl_xor_sync(0xffffffffu, a0, 2));
            a1 = fmaxf(a1, __shfl_xor_sync(0xffffffffu, a1, 1));
            a1 = fmaxf(a1, __shfl_xor_sync(0xffffffffu, a1, 2));
            if ((lane & 3) == 0) {
                int r = wm*32 + mt*16 + t4;
                red[r*2 + wn] = a0;
                red[(r+8)*2 + wn] = a1;
            }
        }
        __syncthreads();
        #pragma unroll
        for (int mt = 0; mt < 2; mt++) {
            int r = wm*32 + mt*16 + t4;
            mrow[mt][0] = fmaxf(red[r*2+0], red[r*2+1]);
            mrow[mt][1] = fmaxf(red[(r+8)*2+0], red[(r+8)*2+1]);
        }
        float srow[2][2];
        #pragma unroll
        for (int mt = 0; mt < 2; mt++) {
            float s0 = 0.f, s1 = 0.f;
            #pragma unroll
            for (int nt = 0; nt < 8; nt++) {
                acc[mt][nt][0] = expf(acc[mt][nt][0] - mrow[mt][0]);
                acc[mt][nt][1] = expf(acc[mt][nt][1] - mrow[mt][0]);
                acc[mt][nt][2] = expf(acc[mt][nt][2] - mrow[mt][1]);
                acc[mt][nt][3] = expf(acc[mt][nt][3] - mrow[mt][1]);
                s0 += acc[mt][nt][0] + acc[mt][nt][1];
                s1 += acc[mt][nt][2] + acc[mt][nt][3];
            }
            s0 += __shfl_xor_sync(0xffffffffu, s0, 1);
            s0 += __shfl_xor_sync(0xffffffffu, s0, 2);
            s1 += __shfl_xor_sync(0xffffffffu, s1, 1);
            s1 += __shfl_xor_sync(0xffffffffu, s1, 2);
            if ((lane & 3) == 0) {
                int r = wm*32 + mt*16 + t4;
                red2[r*2 + wn] = s0;
                red2[(r+8)*2 + wn] = s1;
            }
        }
        __syncthreads();
        #pragma unroll
        for (int mt = 0; mt < 2; mt++) {
            int r = wm*32 + mt*16 + t4;
            srow[mt][0] = 1.0f / (red2[r*2+0] + red2[r*2+1]);
            srow[mt][1] = 1.0f / (red2[(r+8)*2+0] + red2[(r+8)*2+1]);
        }
        #pragma unroll
        for (int mt = 0; mt < 2; mt++) {
            int row0 = m0 + wm*32 + mt*16 + t4;
            int row1 = row0 + 8;
            #pragma unroll
            for (int nt = 0; nt < 8; nt++) {
                int col = n0 + wn*64 + nt*8 + t2;
                float v0 = to_tf32(acc[mt][nt][0] * srow[mt][0]);
                float v1 = to_tf32(acc[mt][nt][1] * srow[mt][0]);
                float v2 = to_tf32(acc[mt][nt][2] * srow[mt][1]);
                float v3 = to_tf32(acc[mt][nt][3] * srow[mt][1]);
                *(float2*)(Qf + (size_t)row0*DD + col) = make_float2(v0, v1);
                *(float2*)(Qf + (size_t)row1*DD + col) = make_float2(v2, v3);
            }
        }
        return;
    }

    if (mode == 1) {
        // K logits: acc+bias+(1-mask)*-1e6 -> RAW transposed kT[b][h][d][t] via C
        #pragma unroll
        for (int mt = 0; mt < 2; mt++) {
            int row0 = m0 + wm*32 + mt*16 + t4;
            int row1 = row0 + 8;
            float add0 = (1.0f - mask[row0]) * (-1000000.0f);
            float add1 = (1.0f - mask[row1]) * (-1000000.0f);
            int b0 = row0 >> 11, tt0 = row0 & (TT-1);
            int b1 = row1 >> 11, tt1 = row1 & (TT-1);
            #pragma unroll
            for (int nt = 0; nt < 8; nt++) {
                int col = n0 + wn*64 + nt*8 + t2;
                int h = col >> 7, d = col & 127;
                size_t i00 = ((size_t)(b0*HH + h)*DHH + d)*TT + tt0;
                size_t i10 = ((size_t)(b1*HH + h)*DHH + d)*TT + tt1;
                C[i00]      = acc[mt][nt][0] + add0;
                C[i00 + TT] = acc[mt][nt][1] + add0;
                C[i10]      = acc[mt][nt][2] + add1;
                C[i10 + TT] = acc[mt][nt][3] + add1;
            }
        }
        return;
    }

    if (mode == 2) {
        // V projection: (acc+bias)*mask -> transposed vT[b][h][l][t] (tf32 fp32)
        #pragma unroll
        for (int mt = 0; mt < 2; mt++) {
            int row0 = m0 + wm*32 + mt*16 + t4;
            int row1 = row0 + 8;
            float m0v = mask[row0], m1v = mask[row1];
            int b0 = row0 >> 11, tt0 = row0 & (TT-1);
            int b1 = row1 >> 11, tt1 = row1 & (TT-1);
            #pragma unroll
            for (int nt = 0; nt < 8; nt++) {
                int col = n0 + wn*64 + nt*8 + t2;
                int h = col >> 7, l = col & 127;
                size_t i00 = ((size_t)(b0*HH + h)*DHH + l)*TT + tt0;
                size_t i10 = ((size_t)(b1*HH + h)*DHH + l)*TT + tt1;
                Vt[i00]      = to_tf32(acc[mt][nt][0] * m0v);
                Vt[i00 + TT] = to_tf32(acc[mt][nt][1] * m0v);
                Vt[i10]      = to_tf32(acc[mt][nt][2] * m1v);
                Vt[i10 + TT] = to_tf32(acc[mt][nt][3] * m1v);
            }
        }
        return;
    }

    // mode 3: +resid -> C linear
    #pragma unroll
    for (int mt = 0; mt < 2; mt++) {
        int row0 = m0 + wm*32 + mt*16 + t4;
        int row1 = row0 + 8;
        #pragma unroll
        for (int nt = 0; nt < 8; nt++) {
            int col = n0 + wn*64 + nt*8 + t2;
            float2 r0 = *(const float2*)(resid + (size_t)row0*DD + col);
            float2 r1 = *(const float2*)(resid + (size_t)row1*DD + col);
            *(float2*)(C + (size_t)row0*DD + col) = make_float2(acc[mt][nt][0] + r0.x, acc[mt][nt][1] + r0.y);
            *(float2*)(C + (size_t)row1*DD + col) = make_float2(acc[mt][nt][2] + r1.x, acc[mt][nt][3] + r1.y);
        }
    }
}

// ======================= k softmax stats: one warp per (b,h,d) row ==========
__global__ __launch_bounds__(256) void kstats_k(const float* __restrict__ kT,
                                                float* __restrict__ kM,
                                                float* __restrict__ kR)
{
    int row = blockIdx.x*8 + (threadIdx.x >> 5);
    int lane = threadIdx.x & 31;
    const float4* p = (const float4*)(kT + (size_t)row*TT);
    float m = -INFINITY, s = 0.f;
    #pragma unroll
    for (int i = 0; i < 16; i++) {
        float4 v = p[lane + i*32];
        float lm = fmaxf(fmaxf(v.x, v.y), fmaxf(v.z, v.w));
        float nm = fmaxf(m, lm);
        s = s*expf(m-nm) + expf(v.x-nm) + expf(v.y-nm) + expf(v.z-nm) + expf(v.w-nm);
        m = nm;
    }
    #pragma unroll
    for (int o = 16; o > 0; o >>= 1) {
        float m2 = __shfl_xor_sync(0xffffffffu, m, o);
        float s2 = __shfl_xor_sync(0xffffffffu, s, o);
        float nm = fmaxf(m, m2);
        s = s*expf(m-nm) + s2*expf(m2-nm);
        m = nm;
    }
    if (lane == 0) { kM[row] = m; kR[row] = 1.0f / s; }
}

// ======================= attention core TF32 ================================
#define ALD    272
#define ATILE  (128*ALD)                  // 34816 B per tile
#define ATT_SMEM (2*ATILE)                // 69632 B

// att1: part[chunk][bh][l][d] = sum_t vT[l][t] * softmax_k[d][t]
__global__ __launch_bounds__(512, 1) void att1_k(
        const float* __restrict__ vT, const float* __restrict__ kT,
        const float* __restrict__ kM, const float* __restrict__ kR,
        float* __restrict__ part)
{
    extern __shared__ float smf[];
    const int tid  = threadIdx.x;
    const int lane = tid & 31;
    const int w    = tid >> 5;
    const int wm   = w >> 2;
    const int wn   = w & 3;
    const int chunk = blockIdx.x;
    const int bh    = blockIdx.y;

    const uint32_t smb = smem_to_u32(smf);
    const int arow = wm*32 + (lane & 7) + ((lane >> 3) & 1) * 8;
    const int akb  = ((lane >> 4) & 1) * 16;
    const int brow = wn*32 + ((lane >> 4) & 1) * 8 + (lane & 7);
    const int bkb  = ((lane >> 3) & 1) * 16;

    float acc[2][4][4];
    #pragma unroll
    for (int i=0;i<2;i++)
        #pragma unroll
        for (int j=0;j<4;j++)
            #pragma unroll
            for (int l=0;l<4;l++) acc[i][j][l]=0.f;

    for (int sub = 0; sub < 4; sub++) {
        int t0 = chunk*256 + sub*64;
        #pragma unroll
        for (int i = 0; i < 4; i++) {
            int idx = tid + i*512;
            int r = idx >> 4, ch = idx & 15;
            size_t gv = ((size_t)bh*DHH + r)*TT + t0 + ch*4;
            *(float4*)((char*)smf + r*ALD + ch*16) = *(const float4*)(vT + gv);
            float4 kk = *(const float4*)(kT + gv);
            float mm = kM[bh*DHH + r], rr = kR[bh*DHH + r];
            kk.x = to_tf32(expf(kk.x - mm) * rr);
            kk.y = to_tf32(expf(kk.y - mm) * rr);
            kk.z = to_tf32(expf(kk.z - mm) * rr);
            kk.w = to_tf32(expf(kk.w - mm) * rr);
            *(float4*)((char*)smf + ATILE + r*ALD + ch*16) = kk;
        }
        __syncthreads();

        #pragma unroll
        for (int ks = 0; ks < 8; ks++) {
            uint32_t a[2][4];
            #pragma unroll
            for (int mt = 0; mt < 2; mt++) {
                uint32_t ra = smb + (uint32_t)((arow + mt*16)*ALD + akb + ks*32);
                LDSM4(a[mt], ra);
            }
            uint32_t bf[2][4];
            #pragma unroll
            for (int nb = 0; nb < 2; nb++) {
                uint32_t rb = smb + ATILE + (uint32_t)((brow + nb*16)*ALD + bkb + ks*32);
                LDSM4(bf[nb], rb);
            }
            #pragma unroll
            for (int mt = 0; mt < 2; mt++)
                #pragma unroll
                for (int nb = 0; nb < 2; nb++) {
                    MMA_TF32(acc[mt][nb*2],   a[mt], bf[nb][0], bf[nb][1]);
                    MMA_TF32(acc[mt][nb*2+1], a[mt], bf[nb][2], bf[nb][3]);
                }
        }
        __syncthreads();
    }

    float* dst = part + ((size_t)(chunk*(BB*HH) + bh))*(DHH*DHH);
    const int t4 = lane >> 2;
    const int t2 = (lane & 3) * 2;
    #pragma unroll
    for (int mt = 0; mt < 2; mt++) {
        int row0 = wm*32 + mt*16 + t4;
        int row1 = row0 + 8;
        #pragma unroll
        for (int nt = 0; nt < 4; nt++) {
            int col = wn*32 + nt*8 + t2;
            *(float2*)(dst + row0*DHH + col) = make_float2(acc[mt][nt][0], acc[mt][nt][1]);
            *(float2*)(dst + row1*DHH + col) = make_float2(acc[mt][nt][2], acc[mt][nt][3]);
        }
    }
}

__global__ void att_reduce_k(const float* __restrict__ part,
                             float* __restrict__ attT)
{
    int i = blockIdx.x*256 + threadIdx.x;
    float s = 0.f;
    #pragma unroll
    for (int c=0;c<NCHUNK;c++) s += part[(size_t)c*(BB*HH*DHH*DHH) + i];
    attT[i] = to_tf32(s);
}

// att2: y[t][h*128+l] = sum_d q[t][h*128+d]*attT[l][d]
__global__ __launch_bounds__(512, 1) void att2_k(
        const float* __restrict__ q,
        const float* __restrict__ attT,
        float* __restrict__ y)
{
    extern __shared__ float smf[];
    const int tid  = threadIdx.x;
    const int lane = tid & 31;
    const int w    = tid >> 5;
    const int wm   = w >> 2;
    const int wn   = w & 3;
    const int m0 = blockIdx.x * 128;
    const int h  = blockIdx.y;
    const int bh = (m0 >> 11) * HH + h;

    const uint32_t smb = smem_to_u32(smf);
    const int arow = wm*32 + (lane & 7) + ((lane >> 3) & 1) * 8;
    const int akb  = ((lane >> 4) & 1) * 16;
    const int brow = wn*32 + ((lane >> 4) & 1) * 8 + (lane & 7);
    const int bkb  = ((lane >> 3) & 1) * 16;

    float acc[2][4][4];
    #pragma unroll
    for (int i=0;i<2;i++)
        #pragma unroll
        for (int j=0;j<4;j++)
            #pragma unroll
            for (int l=0;l<4;l++) acc[i][j][l]=0.f;

    for (int sub = 0; sub < 2; sub++) {
        int d0 = sub*64;
        #pragma unroll
        for (int i = 0; i < 4; i++) {
            int idx = tid + i*512;
            int r = idx >> 4, ch = idx & 15;
            size_t ga = (size_t)(m0 + r)*DD + h*DHH + d0 + ch*4;
            size_t gb = ((size_t)bh*DHH + r)*DHH + d0 + ch*4;
            *(float4*)((char*)smf + r*ALD + ch*16)          = *(const float4*)(q + ga);
            *(float4*)((char*)smf + ATILE + r*ALD + ch*16)  = *(const float4*)(attT + gb);
        }
        __syncthreads();

        #pragma unroll
        for (int ks = 0; ks < 8; ks++) {
            uint32_t a[2][4];
            #pragma unroll
            for (int mt = 0; mt < 2; mt++) {
                uint32_t ra = smb + (uint32_t)((arow + mt*16)*ALD + akb + ks*32);
                LDSM4(a[mt], ra);
            }
            uint32_t bf[2][4];
            #pragma unroll
            for (int nb = 0; nb < 2; nb++) {
                uint32_t rb = smb + ATILE + (uint32_t)((brow + nb*16)*ALD + bkb + ks*32);
                LDSM4(bf[nb], rb);
            }
            #pragma unroll
            for (int mt = 0; mt < 2; mt++)
                #pragma unroll
                for (int nb = 0; nb < 2; nb++) {
                    MMA_TF32(acc[mt][nb*2],   a[mt], bf[nb][0], bf[nb][1]);
                    MMA_TF32(acc[mt][nb*2+1], a[mt], bf[nb][2], bf[nb][3]);
                }
        }
        __syncthreads();
    }

    const int t4 = lane >> 2;
    const int t2 = (lane & 3) * 2;
    #pragma unroll
    for (int mt = 0; mt < 2; mt++) {
        int row0 = m0 + wm*32 + mt*16 + t4;
        int row1 = row0 + 8;
        #pragma unroll
        for (int nt = 0; nt < 4; nt++) {
            int col = h*DHH + wn*32 + nt*8 + t2;
            *(float2*)(y + (size_t)row0*DD + col) = make_float2(acc[mt][nt][0], acc[mt][nt][1]);
            *(float2*)(y + (size_t)row1*DD + col) = make_float2(acc[mt][nt][2], acc[mt][nt][3]);
        }
    }
}

// ======================= emb path =======================
__global__ void silu_emb_k(const float* __restrict__ emb, float* __restrict__ out)
{
    int i = blockIdx.x*256 + threadIdx.x;
    float e = emb[i];
    out[i] = e / (1.0f + expf(-e));
}

__global__ __launch_bounds__(256) void emb_gemm_k(const float* __restrict__ ea,
                                                  const float* __restrict__ W,
                                                  const float* __restrict__ bias,
                                                  float* __restrict__ out)
{
    int n = blockIdx.x*256 + threadIdx.x;
    int b = blockIdx.y;
    const float* e = ea + b*TEE;
    float acc = 0.f;
    #pragma unroll 8
    for (int t=0;t<TEE;t++)
        acc = fmaf(e[t], W[(size_t)t*(2*DD) + n], acc);
    out[b*(2*DD) + n] = acc + bias[n];
}

// ======================= LN2 + FiLM + SiLU -> tf32 fp32 =====================
__global__ __launch_bounds__(256) void film_k(const float* __restrict__ y,
                                              const float* __restrict__ w2,
                                              const float* __restrict__ b2,
                                              const float* __restrict__ embout,
                                              float* __restrict__ act)
{
    int row = blockIdx.x;
    int b = row / TT;
    int tid = threadIdx.x;
    const float4* yr = (const float4*)(y + (size_t)row*DD);
    float4 v = yr[tid];
    float s  = v.x+v.y+v.z+v.w;
    float ss = v.x*v.x+v.y*v.y+v.z*v.z+v.w*v.w;
    #pragma unroll
    for (int o=16;o>0;o>>=1){ s += __shfl_down_sync(0xffffffffu,s,o); ss += __shfl_down_sync(0xffffffffu,ss,o); }
    __shared__ float sm[8], sm2[8];
    int wid = tid>>5, lane = tid&31;
    if (lane==0){ sm[wid]=s; sm2[wid]=ss; }
    __syncthreads();
    if (tid==0){
        float a=0.f, c=0.f;
        #pragma unroll
        for (int i=0;i<8;i++){ a+=sm[i]; c+=sm2[i]; }
        float mean = a*(1.0f/DD);
        float var  = c*(1.0f/DD) - mean*mean;
        sm[0]=mean; sm2[0]=rsqrtf(var+1e-5f);
    }
    __syncthreads();
    float mean=sm[0], rinv=sm2[0];
    float4 wv=((const float4*)w2)[tid];
    float4 bv=((const float4*)b2)[tid];
    float4 sc=((const float4*)(embout + (size_t)b*(2*DD)))[tid];
    float4 sh=((const float4*)(embout + (size_t)b*(2*DD) + DD))[tid];
    float4 o;
    float h;
    h=(v.x-mean)*rinv*wv.x+bv.x; h=h*(1.0f+sc.x)+sh.x; o.x=to_tf32(h/(1.0f+expf(-h)));
    h=(v.y-mean)*rinv*wv.y+bv.y; h=h*(1.0f+sc.y)+sh.y; o.y=to_tf32(h/(1.0f+expf(-h)));
    h=(v.z-mean)*rinv*wv.z+bv.z; h=h*(1.0f+sc.z)+sh.z; o.z=to_tf32(h/(1.0f+expf(-h)));
    h=(v.w-mean)*rinv*wv.w+bv.w; h=h*(1.0f+sc.w)+sh.w; o.w=to_tf32(h/(1.0f+expf(-h)));
    ((float4*)(act + (size_t)row*DD))[tid]=o;
}

// ======================= launch =======================
extern "C" void kernel_launch(void* const* d_in, const int* in_sizes, int n_in,
                              void* d_out, int out_size)
{
    (void)in_sizes; (void)n_in; (void)out_size;
    const float* x     = (const float*)d_in[0];
    const float* emb   = (const float*)d_in[1];
    const float* mask  = (const float*)d_in[2];
    const float* ln_w  = (const float*)d_in[4];
    const float* ln_b  = (const float*)d_in[5];
    const float* Wq    = (const float*)d_in[6];
    const float* bq    = (const float*)d_in[7];
    const float* Wk    = (const float*)d_in[8];
    const float* bk    = (const float*)d_in[9];
    const float* Wv    = (const float*)d_in[10];
    const float* bv    = (const float*)d_in[11];
    const float* W_emb = (const float*)d_in[12];
    const float* b_emb = (const float*)d_in[13];
    const float* ln2_w = (const float*)d_in[14];
    const float* ln2_b = (const float*)d_in[15];
    const float* W_out = (const float*)d_in[16];
    const float* b_out = (const float*)d_in[17];
    float* out = (float*)d_out;

    float *p_xn, *p_act, *p_wt, *p_y, *p_q, *p_kT, *p_vT, *p_kM, *p_kR, *p_attp, *p_attT, *p_emba, *p_embout;
    cudaGetSymbolAddress((void**)&p_xn,     g_xn);
    cudaGetSymbolAddress((void**)&p_act,    g_act);
    cudaGetSymbolAddress((void**)&p_wt,     g_wt);
    cudaGetSymbolAddress((void**)&p_y,      g_y);
    cudaGetSymbolAddress((void**)&p_q,      g_q);
    cudaGetSymbolAddress((void**)&p_kT,     g_kT);
    cudaGetSymbolAddress((void**)&p_vT,     g_vT);
    cudaGetSymbolAddress((void**)&p_kM,     g_kM);
    cudaGetSymbolAddress((void**)&p_kR,     g_kR);
    cudaGetSymbolAddress((void**)&p_attp,   g_att_part);
    cudaGetSymbolAddress((void**)&p_attT,   g_attT);
    cudaGetSymbolAddress((void**)&p_emba,   g_emb_act);
    cudaGetSymbolAddress((void**)&p_embout, g_embout);

    cudaFuncSetAttribute(hgemm_k, cudaFuncAttributeMaxDynamicSharedMemorySize, HG_SMEM);
    cudaFuncSetAttribute(att1_k,  cudaFuncAttributeMaxDynamicSharedMemorySize, ATT_SMEM);
    cudaFuncSetAttribute(att2_k,  cudaFuncAttributeMaxDynamicSharedMemorySize, ATT_SMEM);

    wsplit4_k<<<dim3(32,32,4), dim3(32,32)>>>(Wq, Wk, Wv, W_out, p_wt);
    ln_kernel<<<MM, 256>>>(x, ln_w, ln_b, p_xn);
    silu_emb_k<<<(BB*TEE)/256, 256>>>(emb, p_emba);

    // QKV fused: grid.z selects weight slice + epilogue.
    // mode 1 (K) writes raw transposed logits into p_kT (C param).
    hgemm_k<<<dim3(DD/128, MM/64, 3), 128, HG_SMEM>>>(
        p_xn, p_wt,
        bq, bk, bv, mask, nullptr, p_kT, p_q, p_vT, -1);

    kstats_k<<<(BB*HH*DHH)/8, 256>>>(p_kT, p_kM, p_kR);

    att1_k<<<dim3(NCHUNK, BB*HH), 512, ATT_SMEM>>>(p_vT, p_kT, p_kM, p_kR, p_attp);
    att_reduce_k<<<(BB*HH*DHH*DHH)/256, 256>>>(p_attp, p_attT);

    emb_gemm_k<<<dim3((2*DD)/256, BB), 256>>>(p_emba, W_emb, b_emb, p_embout);

    att2_k<<<dim3(MM/128, HH), 512, ATT_SMEM>>>(p_q, p_attT, p_y);

    film_k<<<MM, 256>>>(p_y, ln2_w, ln2_b, p_embout, p_act);

    // OUT projection (+residual)
    hgemm_k<<<dim3(DD/128, MM/64, 1), 128, HG_SMEM>>>(
        p_act, p_wt + 3*(size_t)DD*DD,
        b_out, nullptr, nullptr, nullptr, x, out, nullptr, nullptr, 3);
}

// round 17
// speedup vs baseline: 2.0112x; 1.2082x over previous
#include <cuda_runtime.h>
#include <cuda_bf16.h>
#include <math.h>
#include <stdint.h>

#define BB 4
#define TT 2048
#define DD 1024
#define HH 8
#define DHH 128
#define TEE 2048
#define MM (BB*TT)          // 8192 rows
#define NCHUNK 4            // att1 t-chunks (512 t per block)

__device__ __forceinline__ uint32_t smem_to_u32(const void* p) {
    uint32_t a;
    asm("{ .reg .u64 t; cvta.to.shared.u64 t, %1; cvt.u32.u64 %0, t; }" : "=r"(a) : "l"(p));
    return a;
}
__device__ __forceinline__ float to_tf32(float v) {
    uint32_t u;
    asm("cvt.rna.tf32.f32 %0, %1;" : "=r"(u) : "f"(v));
    return __uint_as_float(u);
}

#define LDSM4(R, addr) \
    asm volatile("ldmatrix.sync.aligned.m8n8.x4.shared.b16 {%0,%1,%2,%3}, [%4];" \
        : "=r"((R)[0]), "=r"((R)[1]), "=r"((R)[2]), "=r"((R)[3]) : "r"(addr))

#define MMA_TF32(c, a, b0, b1) \
    asm volatile("mma.sync.aligned.m16n8k8.row.col.f32.tf32.tf32.f32 " \
        "{%0,%1,%2,%3}, {%4,%5,%6,%7}, {%8,%9}, {%0,%1,%2,%3};" \
        : "+f"((c)[0]), "+f"((c)[1]), "+f"((c)[2]), "+f"((c)[3]) \
        : "r"((a)[0]), "r"((a)[1]), "r"((a)[2]), "r"((a)[3]), "r"(b0), "r"(b1))

#define CP16(dst, src) \
    asm volatile("cp.async.cg.shared.global [%0], [%1], 16;" :: "r"(dst), "l"(src))
#define CP_COMMIT() asm volatile("cp.async.commit_group;")
#define CP_WAIT1()  asm volatile("cp.async.wait_group 1;")

// ======================= device scratch =======================
__device__ float g_xn [MM*DD];          // tf32-rounded LN output
__device__ float g_act[MM*DD];          // tf32-rounded FiLM output
__device__ float g_wt [4][DD*DD];       // tf32-rounded transposed weights
__device__ float g_y  [MM*DD];
__device__ float g_q  [MM*DD];          // tf32 softmaxed q
__device__ float g_kT [MM*DD];          // RAW k logits transposed [b,h,d,t]
__device__ float g_vT [MM*DD];          // tf32 vT [b,h,l,t]
__device__ float g_kM [BB*HH*DHH];      // per-(b,h,d) max
__device__ float g_kR [BB*HH*DHH];      // per-(b,h,d) 1/sum
__device__ float g_att_part[NCHUNK*BB*HH*DHH*DHH];
__device__ float g_attT[BB*HH*DHH*DHH]; // tf32 attT [b,h,l,d]
__device__ float g_emb_act[BB*TEE];
__device__ float g_emb_part[16*BB*2*DD];
__device__ float g_embout[BB*2*DD];

// ======================= LayerNorm -> tf32 fp32 =======================
__global__ __launch_bounds__(256) void ln_kernel(const float* __restrict__ x,
                                                 const float* __restrict__ w,
                                                 const float* __restrict__ b,
                                                 float* __restrict__ outx)
{
    int row = blockIdx.x;
    int tid = threadIdx.x;
    const float4* xr = (const float4*)(x + (size_t)row*DD);
    float4 v = xr[tid];
    float s  = v.x+v.y+v.z+v.w;
    float ss = v.x*v.x+v.y*v.y+v.z*v.z+v.w*v.w;
    #pragma unroll
    for (int o=16;o>0;o>>=1){ s += __shfl_down_sync(0xffffffffu,s,o); ss += __shfl_down_sync(0xffffffffu,ss,o); }
    __shared__ float sm[8], sm2[8];
    int wid = tid>>5, lane = tid&31;
    if (lane==0){ sm[wid]=s; sm2[wid]=ss; }
    __syncthreads();
    if (tid==0){
        float a=0.f, c=0.f;
        #pragma unroll
        for (int i=0;i<8;i++){ a+=sm[i]; c+=sm2[i]; }
        float mean = a*(1.0f/DD);
        float var  = c*(1.0f/DD) - mean*mean;
        sm[0]=mean; sm2[0]=rsqrtf(var+1e-5f);
    }
    __syncthreads();
    float mean=sm[0], rinv=sm2[0];
    float4 wv=((const float4*)w)[tid];
    float4 bv=((const float4*)b)[tid];
    float4 o;
    o.x=to_tf32((v.x-mean)*rinv*wv.x+bv.x);
    o.y=to_tf32((v.y-mean)*rinv*wv.y+bv.y);
    o.z=to_tf32((v.z-mean)*rinv*wv.z+bv.z);
    o.w=to_tf32((v.w-mean)*rinv*wv.w+bv.w);
    ((float4*)(outx + (size_t)row*DD))[tid]=o;
}

// ======================= weight transpose -> tf32 fp32 ======================
__global__ __launch_bounds__(1024) void wsplit4_k(const float* __restrict__ W0,
                                                  const float* __restrict__ W1,
                                                  const float* __restrict__ W2,
                                                  const float* __restrict__ W3,
                                                  float* __restrict__ Wt)
{
    __shared__ float t[32][33];
    int tx = threadIdx.x, ty = threadIdx.y;
    int wsel = blockIdx.z;
    const float* W = (wsel==0)?W0:(wsel==1)?W1:(wsel==2)?W2:W3;
    t[ty][tx] = W[(size_t)(blockIdx.y*32+ty)*DD + blockIdx.x*32+tx];
    __syncthreads();
    int n = blockIdx.x*32 + ty;
    int k = blockIdx.y*32 + tx;
    Wt[(size_t)wsel*DD*DD + (size_t)n*DD + k] = to_tf32(t[tx][ty]);
}

// ======================= TF32 GEMM, BM=64 BN=128, 4 warps, 3 CTAs/SM ========
#define LDSB    144                       // smem row stride in BYTES
#define TA_B    (64*LDSB)                 // 9216 B (A tile)
#define TB_B    (128*LDSB)                // 18432 B (B tile)
#define STAGE_B (TA_B + TB_B)             // 27648 B per stage
#define HG_SMEM (2*STAGE_B)               // 55296 B

// mode 0: softmax-over-dh -> Qf
// mode 1: +bias+(1-mask)*-1e6 -> kT-raw transposed [b,h,d,t] (via C)
// mode 2: (+bias)*mask -> vT transposed [b,h,l,t] (via Vt)
// mode 3: +bias+resid -> C linear
__global__ __launch_bounds__(128, 3) void hgemm_k(
        const float* __restrict__ A,
        const float* __restrict__ Wt,
        const float* __restrict__ bias0, const float* __restrict__ bias1,
        const float* __restrict__ bias2,
        const float* __restrict__ mask,
        const float* __restrict__ resid, float* __restrict__ C,
        float* __restrict__ Qf, float* __restrict__ Vt,
        int mode_ov)
{
    extern __shared__ float smbuf[];
    const int tid  = threadIdx.x;
    const int lane = tid & 31;
    const int w    = tid >> 5;      // 0..3
    const int wm   = w >> 1;        // 0..1 : 32 rows
    const int wn   = w & 1;         // 0..1 : 64 cols
    const int m0 = blockIdx.y * 64;
    const int n0 = blockIdx.x * 128;
    const int mode = (mode_ov >= 0) ? mode_ov : (int)blockIdx.z;
    const int wsel = (mode_ov >= 0) ? 0 : (int)blockIdx.z;
    const float* bias = (mode == 1) ? bias1 : (mode == 2) ? bias2 : bias0;
    const float* B = Wt + (size_t)wsel*DD*DD;

    const uint32_t smb = smem_to_u32(smbuf);
    const uint32_t dA = smb;
    const uint32_t dB = smb + TA_B;

    const int arow = wm*32 + (lane & 7) + ((lane >> 3) & 1) * 8;     // +mt*16
    const int akb  = ((lane >> 4) & 1) * 16;
    const int brow = wn*64 + ((lane >> 4) & 1) * 8 + (lane & 7);     // +nb*16
    const int bkb  = ((lane >> 3) & 1) * 16;

    float acc[2][8][4];
    #pragma unroll
    for (int i=0;i<2;i++)
        #pragma unroll
        for (int j=0;j<8;j++)
            #pragma unroll
            for (int l=0;l<4;l++) acc[i][j][l]=0.f;

    #pragma unroll
    for (int s = 0; s < 2; s++) {
        int k0 = s*32;
        uint32_t so = s*STAGE_B;
        #pragma unroll
        for (int i = 0; i < 4; i++) {
            int idx = tid + i*128;
            int r = idx >> 3, ch = idx & 7;
            CP16(dA + so + (uint32_t)(r*LDSB + ch*16), A + (size_t)(m0+r)*DD + k0 + ch*4);
        }
        #pragma unroll
        for (int i = 0; i < 8; i++) {
            int idx = tid + i*128;
            int r = idx >> 3, ch = idx & 7;
            CP16(dB + so + (uint32_t)(r*LDSB + ch*16), B + (size_t)(n0+r)*DD + k0 + ch*4);
        }
        CP_COMMIT();
    }

    for (int kc = 0; kc < 32; kc++) {
        CP_WAIT1();
        __syncthreads();

        uint32_t baseA = smb + (kc & 1)*STAGE_B;
        uint32_t baseB = baseA + TA_B;
        #pragma unroll
        for (int ks = 0; ks < 4; ks++) {
            uint32_t a[2][4];
            #pragma unroll
            for (int mt = 0; mt < 2; mt++) {
                uint32_t ra = baseA + (uint32_t)((arow + mt*16)*LDSB + akb + ks*32);
                LDSM4(a[mt], ra);
            }
            uint32_t bf[4][4];
            #pragma unroll
            for (int nb = 0; nb < 4; nb++) {
                uint32_t rb = baseB + (uint32_t)((brow + nb*16)*LDSB + bkb + ks*32);
                LDSM4(bf[nb], rb);
            }
            #pragma unroll
            for (int mt = 0; mt < 2; mt++)
                #pragma unroll
                for (int nb = 0; nb < 4; nb++) {
                    MMA_TF32(acc[mt][nb*2],   a[mt], bf[nb][0], bf[nb][1]);
                    MMA_TF32(acc[mt][nb*2+1], a[mt], bf[nb][2], bf[nb][3]);
                }
        }

        __syncthreads();
        if (kc + 2 < 32) {
            int k0 = (kc+2)*32;
            uint32_t so = (kc & 1)*STAGE_B;
            #pragma unroll
            for (int i = 0; i < 4; i++) {
                int idx = tid + i*128;
                int r = idx >> 3, ch = idx & 7;
                CP16(dA + so + (uint32_t)(r*LDSB + ch*16), A + (size_t)(m0+r)*DD + k0 + ch*4);
            }
            #pragma unroll
            for (int i = 0; i < 8; i++) {
                int idx = tid + i*128;
                int r = idx >> 3, ch = idx & 7;
                CP16(dB + so + (uint32_t)(r*LDSB + ch*16), B + (size_t)(n0+r)*DD + k0 + ch*4);
            }
        }
        CP_COMMIT();
    }

    const int t4 = lane >> 2;
    const int t2 = (lane & 3) * 2;

    #pragma unroll
    for (int mt = 0; mt < 2; mt++)
        #pragma unroll
        for (int nt = 0; nt < 8; nt++) {
            int col = n0 + wn*64 + nt*8 + t2;
            float2 bi = *(const float2*)(bias + col);
            acc[mt][nt][0] += bi.x; acc[mt][nt][1] += bi.y;
            acc[mt][nt][2] += bi.x; acc[mt][nt][3] += bi.y;
        }

    if (mode == 0) {
        // fused softmax over 128 cols (one head), 64 rows -> Qf (tf32 fp32)
        __syncthreads();
        float* red  = smbuf;
        float* red2 = smbuf + 128;
        float mrow[2][2];
        #pragma unroll
        for (int mt = 0; mt < 2; mt++) {
            float a0 = -1e30f, a1 = -1e30f;
            #pragma unroll
            for (int nt = 0; nt < 8; nt++) {
                a0 = fmaxf(a0, fmaxf(acc[mt][nt][0], acc[mt][nt][1]));
                a1 = fmaxf(a1, fmaxf(acc[mt][nt][2], acc[mt][nt][3]));
            }
            a0 = fmaxf(a0, __shfl_xor_sync(0xffffffffu, a0, 1));
            a0 = fmaxf(a0, __shfl_xor_sync(0xffffffffu, a0, 2));
            a1 = fmaxf(a1, __shfl_xor_sync(0xffffffffu, a1, 1));
            a1 = fmaxf(a1, __shfl_xor_sync(0xffffffffu, a1, 2));
            if ((lane & 3) == 0) {
                int r = wm*32 + mt*16 + t4;
                red[r*2 + wn] = a0;
                red[(r+8)*2 + wn] = a1;
            }
        }
        __syncthreads();
        #pragma unroll
        for (int mt = 0; mt < 2; mt++) {
            int r = wm*32 + mt*16 + t4;
            mrow[mt][0] = fmaxf(red[r*2+0], red[r*2+1]);
            mrow[mt][1] = fmaxf(red[(r+8)*2+0], red[(r+8)*2+1]);
        }
        float srow[2][2];
        #pragma unroll
        for (int mt = 0; mt < 2; mt++) {
            float s0 = 0.f, s1 = 0.f;
            #pragma unroll
            for (int nt = 0; nt < 8; nt++) {
                acc[mt][nt][0] = expf(acc[mt][nt][0] - mrow[mt][0]);
                acc[mt][nt][1] = expf(acc[mt][nt][1] - mrow[mt][0]);
                acc[mt][nt][2] = expf(acc[mt][nt][2] - mrow[mt][1]);
                acc[mt][nt][3] = expf(acc[mt][nt][3] - mrow[mt][1]);
                s0 += acc[mt][nt][0] + acc[mt][nt][1];
                s1 += acc[mt][nt][2] + acc[mt][nt][3];
            }
            s0 += __shfl_xor_sync(0xffffffffu, s0, 1);
            s0 += __shfl_xor_sync(0xffffffffu, s0, 2);
            s1 += __shfl_xor_sync(0xffffffffu, s1, 1);
            s1 += __shfl_xor_sync(0xffffffffu, s1, 2);
            if ((lane & 3) == 0) {
                int r = wm*32 + mt*16 + t4;
                red2[r*2 + wn] = s0;
                red2[(r+8)*2 + wn] = s1;
            }
        }
        __syncthreads();
        #pragma unroll
        for (int mt = 0; mt < 2; mt++) {
            int r = wm*32 + mt*16 + t4;
            srow[mt][0] = 1.0f / (red2[r*2+0] + red2[r*2+1]);
            srow[mt][1] = 1.0f / (red2[(r+8)*2+0] + red2[(r+8)*2+1]);
        }
        #pragma unroll
        for (int mt = 0; mt < 2; mt++) {
            int row0 = m0 + wm*32 + mt*16 + t4;
            int row1 = row0 + 8;
            #pragma unroll
            for (int nt = 0; nt < 8; nt++) {
                int col = n0 + wn*64 + nt*8 + t2;
                float v0 = to_tf32(acc[mt][nt][0] * srow[mt][0]);
                float v1 = to_tf32(acc[mt][nt][1] * srow[mt][0]);
                float v2 = to_tf32(acc[mt][nt][2] * srow[mt][1]);
                float v3 = to_tf32(acc[mt][nt][3] * srow[mt][1]);
                *(float2*)(Qf + (size_t)row0*DD + col) = make_float2(v0, v1);
                *(float2*)(Qf + (size_t)row1*DD + col) = make_float2(v2, v3);
            }
        }
        return;
    }

    if (mode == 1) {
        // K logits: acc+bias+(1-mask)*-1e6 -> RAW transposed kT[b][h][d][t] via C
        #pragma unroll
        for (int mt = 0; mt < 2; mt++) {
            int row0 = m0 + wm*32 + mt*16 + t4;
            int row1 = row0 + 8;
            float add0 = (1.0f - mask[row0]) * (-1000000.0f);
            float add1 = (1.0f - mask[row1]) * (-1000000.0f);
            int b0 = row0 >> 11, tt0 = row0 & (TT-1);
            int b1 = row1 >> 11, tt1 = row1 & (TT-1);
            #pragma unroll
            for (int nt = 0; nt < 8; nt++) {
                int col = n0 + wn*64 + nt*8 + t2;
                int h = col >> 7, d = col & 127;
                size_t i00 = ((size_t)(b0*HH + h)*DHH + d)*TT + tt0;
                size_t i10 = ((size_t)(b1*HH + h)*DHH + d)*TT + tt1;
                C[i00]      = acc[mt][nt][0] + add0;
                C[i00 + TT] = acc[mt][nt][1] + add0;
                C[i10]      = acc[mt][nt][2] + add1;
                C[i10 + TT] = acc[mt][nt][3] + add1;
            }
        }
        return;
    }

    if (mode == 2) {
        // V projection: (acc+bias)*mask -> transposed vT[b][h][l][t] (tf32 fp32)
        #pragma unroll
        for (int mt = 0; mt < 2; mt++) {
            int row0 = m0 + wm*32 + mt*16 + t4;
            int row1 = row0 + 8;
            float m0v = mask[row0], m1v = mask[row1];
            int b0 = row0 >> 11, tt0 = row0 & (TT-1);
            int b1 = row1 >> 11, tt1 = row1 & (TT-1);
            #pragma unroll
            for (int nt = 0; nt < 8; nt++) {
                int col = n0 + wn*64 + nt*8 + t2;
                int h = col >> 7, l = col & 127;
                size_t i00 = ((size_t)(b0*HH + h)*DHH + l)*TT + tt0;
                size_t i10 = ((size_t)(b1*HH + h)*DHH + l)*TT + tt1;
                Vt[i00]      = to_tf32(acc[mt][nt][0] * m0v);
                Vt[i00 + TT] = to_tf32(acc[mt][nt][1] * m0v);
                Vt[i10]      = to_tf32(acc[mt][nt][2] * m1v);
                Vt[i10 + TT] = to_tf32(acc[mt][nt][3] * m1v);
            }
        }
        return;
    }

    // mode 3: +resid -> C linear
    #pragma unroll
    for (int mt = 0; mt < 2; mt++) {
        int row0 = m0 + wm*32 + mt*16 + t4;
        int row1 = row0 + 8;
        #pragma unroll
        for (int nt = 0; nt < 8; nt++) {
            int col = n0 + wn*64 + nt*8 + t2;
            float2 r0 = *(const float2*)(resid + (size_t)row0*DD + col);
            float2 r1 = *(const float2*)(resid + (size_t)row1*DD + col);
            *(float2*)(C + (size_t)row0*DD + col) = make_float2(acc[mt][nt][0] + r0.x, acc[mt][nt][1] + r0.y);
            *(float2*)(C + (size_t)row1*DD + col) = make_float2(acc[mt][nt][2] + r1.x, acc[mt][nt][3] + r1.y);
        }
    }
}

// ======================= k softmax stats: one warp per (b,h,d) row ==========
__global__ __launch_bounds__(256) void kstats_k(const float* __restrict__ kT,
                                                float* __restrict__ kM,
                                                float* __restrict__ kR)
{
    int row = blockIdx.x*8 + (threadIdx.x >> 5);
    int lane = threadIdx.x & 31;
    const float4* p = (const float4*)(kT + (size_t)row*TT);
    float m = -INFINITY, s = 0.f;
    #pragma unroll
    for (int i = 0; i < 16; i++) {
        float4 v = p[lane + i*32];
        float lm = fmaxf(fmaxf(v.x, v.y), fmaxf(v.z, v.w));
        float nm = fmaxf(m, lm);
        s = s*expf(m-nm) + expf(v.x-nm) + expf(v.y-nm) + expf(v.z-nm) + expf(v.w-nm);
        m = nm;
    }
    #pragma unroll
    for (int o = 16; o > 0; o >>= 1) {
        float m2 = __shfl_xor_sync(0xffffffffu, m, o);
        float s2 = __shfl_xor_sync(0xffffffffu, s, o);
        float nm = fmaxf(m, m2);
        s = s*expf(m-nm) + s2*expf(m2-nm);
        m = nm;
    }
    if (lane == 0) { kM[row] = m; kR[row] = 1.0f / s; }
}

// ======================= attention core TF32 ================================
#define ALD    272
#define ATILE  (128*ALD)                  // 34816 B per tile
#define ATT_SMEM (2*ATILE)                // 69632 B

// att1: part[chunk][bh][l][d] = sum_t vT[l][t] * softmax_k[d][t]
__global__ __launch_bounds__(512, 1) void att1_k(
        const float* __restrict__ vT, const float* __restrict__ kT,
        const float* __restrict__ kM, const float* __restrict__ kR,
        float* __restrict__ part)
{
    extern __shared__ float smf[];
    const int tid  = threadIdx.x;
    const int lane = tid & 31;
    const int w    = tid >> 5;
    const int wm   = w >> 2;
    const int wn   = w & 3;
    const int chunk = blockIdx.x;   // 0..3 (512 t each)
    const int bh    = blockIdx.y;

    const uint32_t smb = smem_to_u32(smf);
    const int arow = wm*32 + (lane & 7) + ((lane >> 3) & 1) * 8;
    const int akb  = ((lane >> 4) & 1) * 16;
    const int brow = wn*32 + ((lane >> 4) & 1) * 8 + (lane & 7);
    const int bkb  = ((lane >> 3) & 1) * 16;

    float acc[2][4][4];
    #pragma unroll
    for (int i=0;i<2;i++)
        #pragma unroll
        for (int j=0;j<4;j++)
            #pragma unroll
            for (int l=0;l<4;l++) acc[i][j][l]=0.f;

    for (int sub = 0; sub < 8; sub++) {
        int t0 = chunk*512 + sub*64;
        #pragma unroll
        for (int i = 0; i < 4; i++) {
            int idx = tid + i*512;
            int r = idx >> 4, ch = idx & 15;
            size_t gv = ((size_t)bh*DHH + r)*TT + t0 + ch*4;
            *(float4*)((char*)smf + r*ALD + ch*16) = *(const float4*)(vT + gv);
            float4 kk = *(const float4*)(kT + gv);
            float mm = kM[bh*DHH + r], rr = kR[bh*DHH + r];
            kk.x = to_tf32(expf(kk.x - mm) * rr);
            kk.y = to_tf32(expf(kk.y - mm) * rr);
            kk.z = to_tf32(expf(kk.z - mm) * rr);
            kk.w = to_tf32(expf(kk.w - mm) * rr);
            *(float4*)((char*)smf + ATILE + r*ALD + ch*16) = kk;
        }
        __syncthreads();

        #pragma unroll
        for (int ks = 0; ks < 8; ks++) {
            uint32_t a[2][4];
            #pragma unroll
            for (int mt = 0; mt < 2; mt++) {
                uint32_t ra = smb + (uint32_t)((arow + mt*16)*ALD + akb + ks*32);
                LDSM4(a[mt], ra);
            }
            uint32_t bf[2][4];
            #pragma unroll
            for (int nb = 0; nb < 2; nb++) {
                uint32_t rb = smb + ATILE + (uint32_t)((brow + nb*16)*ALD + bkb + ks*32);
                LDSM4(bf[nb], rb);
            }
            #pragma unroll
            for (int mt = 0; mt < 2; mt++)
                #pragma unroll
                for (int nb = 0; nb < 2; nb++) {
                    MMA_TF32(acc[mt][nb*2],   a[mt], bf[nb][0], bf[nb][1]);
                    MMA_TF32(acc[mt][nb*2+1], a[mt], bf[nb][2], bf[nb][3]);
                }
        }
        __syncthreads();
    }

    float* dst = part + ((size_t)(chunk*(BB*HH) + bh))*(DHH*DHH);
    const int t4 = lane >> 2;
    const int t2 = (lane & 3) * 2;
    #pragma unroll
    for (int mt = 0; mt < 2; mt++) {
        int row0 = wm*32 + mt*16 + t4;
        int row1 = row0 + 8;
        #pragma unroll
        for (int nt = 0; nt < 4; nt++) {
            int col = wn*32 + nt*8 + t2;
            *(float2*)(dst + row0*DHH + col) = make_float2(acc[mt][nt][0], acc[mt][nt][1]);
            *(float2*)(dst + row1*DHH + col) = make_float2(acc[mt][nt][2], acc[mt][nt][3]);
        }
    }
}

__global__ void att_reduce_k(const float* __restrict__ part,
                             float* __restrict__ attT)
{
    int i = blockIdx.x*256 + threadIdx.x;
    float s = 0.f;
    #pragma unroll
    for (int c=0;c<NCHUNK;c++) s += part[(size_t)c*(BB*HH*DHH*DHH) + i];
    attT[i] = to_tf32(s);
}

// att2: y[t][h*128+l] = sum_d q[t][h*128+d]*attT[l][d]
__global__ __launch_bounds__(512, 1) void att2_k(
        const float* __restrict__ q,
        const float* __restrict__ attT,
        float* __restrict__ y)
{
    extern __shared__ float smf[];
    const int tid  = threadIdx.x;
    const int lane = tid & 31;
    const int w    = tid >> 5;
    const int wm   = w >> 2;
    const int wn   = w & 3;
    const int m0 = blockIdx.x * 128;
    const int h  = blockIdx.y;
    const int bh = (m0 >> 11) * HH + h;

    const uint32_t smb = smem_to_u32(smf);
    const int arow = wm*32 + (lane & 7) + ((lane >> 3) & 1) * 8;
    const int akb  = ((lane >> 4) & 1) * 16;
    const int brow = wn*32 + ((lane >> 4) & 1) * 8 + (lane & 7);
    const int bkb  = ((lane >> 3) & 1) * 16;

    float acc[2][4][4];
    #pragma unroll
    for (int i=0;i<2;i++)
        #pragma unroll
        for (int j=0;j<4;j++)
            #pragma unroll
            for (int l=0;l<4;l++) acc[i][j][l]=0.f;

    for (int sub = 0; sub < 2; sub++) {
        int d0 = sub*64;
        #pragma unroll
        for (int i = 0; i < 4; i++) {
            int idx = tid + i*512;
            int r = idx >> 4, ch = idx & 15;
            size_t ga = (size_t)(m0 + r)*DD + h*DHH + d0 + ch*4;
            size_t gb = ((size_t)bh*DHH + r)*DHH + d0 + ch*4;
            *(float4*)((char*)smf + r*ALD + ch*16)          = *(const float4*)(q + ga);
            *(float4*)((char*)smf + ATILE + r*ALD + ch*16)  = *(const float4*)(attT + gb);
        }
        __syncthreads();

        #pragma unroll
        for (int ks = 0; ks < 8; ks++) {
            uint32_t a[2][4];
            #pragma unroll
            for (int mt = 0; mt < 2; mt++) {
                uint32_t ra = smb + (uint32_t)((arow + mt*16)*ALD + akb + ks*32);
                LDSM4(a[mt], ra);
            }
            uint32_t bf[2][4];
            #pragma unroll
            for (int nb = 0; nb < 2; nb++) {
                uint32_t rb = smb + ATILE + (uint32_t)((brow + nb*16)*ALD + bkb + ks*32);
                LDSM4(bf[nb], rb);
            }
            #pragma unroll
            for (int mt = 0; mt < 2; mt++)
                #pragma unroll
                for (int nb = 0; nb < 2; nb++) {
                    MMA_TF32(acc[mt][nb*2],   a[mt], bf[nb][0], bf[nb][1]);
                    MMA_TF32(acc[mt][nb*2+1], a[mt], bf[nb][2], bf[nb][3]);
                }
        }
        __syncthreads();
    }

    const int t4 = lane >> 2;
    const int t2 = (lane & 3) * 2;
    #pragma unroll
    for (int mt = 0; mt < 2; mt++) {
        int row0 = m0 + wm*32 + mt*16 + t4;
        int row1 = row0 + 8;
        #pragma unroll
        for (int nt = 0; nt < 4; nt++) {
            int col = h*DHH + wn*32 + nt*8 + t2;
            *(float2*)(y + (size_t)row0*DD + col) = make_float2(acc[mt][nt][0], acc[mt][nt][1]);
            *(float2*)(y + (size_t)row1*DD + col) = make_float2(acc[mt][nt][2], acc[mt][nt][3]);
        }
    }
}

// ======================= emb path =======================
__global__ void silu_emb_k(const float* __restrict__ emb, float* __restrict__ out)
{
    int i = blockIdx.x*256 + threadIdx.x;
    float e = emb[i];
    out[i] = e / (1.0f + expf(-e));
}

// split-k emb GEMM: grid (2DD/256, 16 t-chunks); each block reads its W chunk
// once and accumulates all 4 batches from smem-staged e.
__global__ __launch_bounds__(256) void emb_gemm_k(const float* __restrict__ ea,
                                                  const float* __restrict__ W,
                                                  float* __restrict__ part)
{
    int n  = blockIdx.x*256 + threadIdx.x;  // 0..2047
    int tc = blockIdx.y;                    // 0..15
    int t0 = tc*128;
    __shared__ float es[4][128];
    if (threadIdx.x < 128) {
        #pragma unroll
        for (int b = 0; b < 4; b++)
            es[b][threadIdx.x] = ea[b*TEE + t0 + threadIdx.x];
    }
    __syncthreads();
    float acc[4] = {0.f, 0.f, 0.f, 0.f};
    #pragma unroll 4
    for (int t = 0; t < 128; t++) {
        float wv = W[(size_t)(t0 + t)*(2*DD) + n];
        #pragma unroll
        for (int b = 0; b < 4; b++)
            acc[b] = fmaf(es[b][t], wv, acc[b]);
    }
    #pragma unroll
    for (int b = 0; b < 4; b++)
        part[(size_t)tc*(BB*2*DD) + b*(2*DD) + n] = acc[b];
}

__global__ void emb_red_k(const float* __restrict__ part,
                          const float* __restrict__ bias,
                          float* __restrict__ out)
{
    int i = blockIdx.x*256 + threadIdx.x;   // < BB*2DD
    int n = i & (2*DD - 1);
    float s = bias[n];
    #pragma unroll
    for (int c = 0; c < 16; c++)
        s += part[(size_t)c*(BB*2*DD) + i];
    out[i] = s;
}

// ======================= LN2 + FiLM + SiLU -> tf32 fp32 =====================
__global__ __launch_bounds__(256) void film_k(const float* __restrict__ y,
                                              const float* __restrict__ w2,
                                              const float* __restrict__ b2,
                                              const float* __restrict__ embout,
                                              float* __restrict__ act)
{
    int row = blockIdx.x;
    int b = row / TT;
    int tid = threadIdx.x;
    const float4* yr = (const float4*)(y + (size_t)row*DD);
    float4 v = yr[tid];
    float s  = v.x+v.y+v.z+v.w;
    float ss = v.x*v.x+v.y*v.y+v.z*v.z+v.w*v.w;
    #pragma unroll
    for (int o=16;o>0;o>>=1){ s += __shfl_down_sync(0xffffffffu,s,o); ss += __shfl_down_sync(0xffffffffu,ss,o); }
    __shared__ float sm[8], sm2[8];
    int wid = tid>>5, lane = tid&31;
    if (lane==0){ sm[wid]=s; sm2[wid]=ss; }
    __syncthreads();
    if (tid==0){
        float a=0.f, c=0.f;
        #pragma unroll
        for (int i=0;i<8;i++){ a+=sm[i]; c+=sm2[i]; }
        float mean = a*(1.0f/DD);
        float var  = c*(1.0f/DD) - mean*mean;
        sm[0]=mean; sm2[0]=rsqrtf(var+1e-5f);
    }
    __syncthreads();
    float mean=sm[0], rinv=sm2[0];
    float4 wv=((const float4*)w2)[tid];
    float4 bv=((const float4*)b2)[tid];
    float4 sc=((const float4*)(embout + (size_t)b*(2*DD)))[tid];
    float4 sh=((const float4*)(embout + (size_t)b*(2*DD) + DD))[tid];
    float4 o;
    float h;
    h=(v.x-mean)*rinv*wv.x+bv.x; h=h*(1.0f+sc.x)+sh.x; o.x=to_tf32(h/(1.0f+expf(-h)));
    h=(v.y-mean)*rinv*wv.y+bv.y; h=h*(1.0f+sc.y)+sh.y; o.y=to_tf32(h/(1.0f+expf(-h)));
    h=(v.z-mean)*rinv*wv.z+bv.z; h=h*(1.0f+sc.z)+sh.z; o.z=to_tf32(h/(1.0f+expf(-h)));
    h=(v.w-mean)*rinv*wv.w+bv.w; h=h*(1.0f+sc.w)+sh.w; o.w=to_tf32(h/(1.0f+expf(-h)));
    ((float4*)(act + (size_t)row*DD))[tid]=o;
}

// ======================= launch =======================
extern "C" void kernel_launch(void* const* d_in, const int* in_sizes, int n_in,
                              void* d_out, int out_size)
{
    (void)in_sizes; (void)n_in; (void)out_size;
    const float* x     = (const float*)d_in[0];
    const float* emb   = (const float*)d_in[1];
    const float* mask  = (const float*)d_in[2];
    const float* ln_w  = (const float*)d_in[4];
    const float* ln_b  = (const float*)d_in[5];
    const float* Wq    = (const float*)d_in[6];
    const float* bq    = (const float*)d_in[7];
    const float* Wk    = (const float*)d_in[8];
    const float* bk    = (const float*)d_in[9];
    const float* Wv    = (const float*)d_in[10];
    const float* bv    = (const float*)d_in[11];
    const float* W_emb = (const float*)d_in[12];
    const float* b_emb = (const float*)d_in[13];
    const float* ln2_w = (const float*)d_in[14];
    const float* ln2_b = (const float*)d_in[15];
    const float* W_out = (const float*)d_in[16];
    const float* b_out = (const float*)d_in[17];
    float* out = (float*)d_out;

    float *p_xn, *p_act, *p_wt, *p_y, *p_q, *p_kT, *p_vT, *p_kM, *p_kR;
    float *p_attp, *p_attT, *p_emba, *p_embp, *p_embout;
    cudaGetSymbolAddress((void**)&p_xn,     g_xn);
    cudaGetSymbolAddress((void**)&p_act,    g_act);
    cudaGetSymbolAddress((void**)&p_wt,     g_wt);
    cudaGetSymbolAddress((void**)&p_y,      g_y);
    cudaGetSymbolAddress((void**)&p_q,      g_q);
    cudaGetSymbolAddress((void**)&p_kT,     g_kT);
    cudaGetSymbolAddress((void**)&p_vT,     g_vT);
    cudaGetSymbolAddress((void**)&p_kM,     g_kM);
    cudaGetSymbolAddress((void**)&p_kR,     g_kR);
    cudaGetSymbolAddress((void**)&p_attp,   g_att_part);
    cudaGetSymbolAddress((void**)&p_attT,   g_attT);
    cudaGetSymbolAddress((void**)&p_emba,   g_emb_act);
    cudaGetSymbolAddress((void**)&p_embp,   g_emb_part);
    cudaGetSymbolAddress((void**)&p_embout, g_embout);

    cudaFuncSetAttribute(hgemm_k, cudaFuncAttributeMaxDynamicSharedMemorySize, HG_SMEM);
    cudaFuncSetAttribute(att1_k,  cudaFuncAttributeMaxDynamicSharedMemorySize, ATT_SMEM);
    cudaFuncSetAttribute(att2_k,  cudaFuncAttributeMaxDynamicSharedMemorySize, ATT_SMEM);

    wsplit4_k<<<dim3(32,32,4), dim3(32,32)>>>(Wq, Wk, Wv, W_out, p_wt);
    ln_kernel<<<MM, 256>>>(x, ln_w, ln_b, p_xn);
    silu_emb_k<<<(BB*TEE)/256, 256>>>(emb, p_emba);
    emb_gemm_k<<<dim3((2*DD)/256, 16), 256>>>(p_emba, W_emb, p_embp);
    emb_red_k<<<(BB*2*DD)/256, 256>>>(p_embp, b_emb, p_embout);

    // QKV fused: grid.z selects weight slice + epilogue.
    hgemm_k<<<dim3(DD/128, MM/64, 3), 128, HG_SMEM>>>(
        p_xn, p_wt,
        bq, bk, bv, mask, nullptr, p_kT, p_q, p_vT, -1);

    kstats_k<<<(BB*HH*DHH)/8, 256>>>(p_kT, p_kM, p_kR);

    att1_k<<<dim3(NCHUNK, BB*HH), 512, ATT_SMEM>>>(p_vT, p_kT, p_kM, p_kR, p_attp);
    att_reduce_k<<<(BB*HH*DHH*DHH)/256, 256>>>(p_attp, p_attT);

    att2_k<<<dim3(MM/128, HH), 512, ATT_SMEM>>>(p_q, p_attT, p_y);

    film_k<<<MM, 256>>>(p_y, ln2_w, ln2_b, p_embout, p_act);

    // OUT projection (+residual)
    hgemm_k<<<dim3(DD/128, MM/64, 1), 128, HG_SMEM>>>(
        p_act, p_wt + 3*(size_t)DD*DD,
        b_out, nullptr, nullptr, nullptr, x, out, nullptr, nullptr, 3);
}